// round 3
// baseline (speedup 1.0000x reference)
#include <cuda_runtime.h>
#include <math.h>

#define NPIX 16384
#define QSCALE 0.35355339059327373f

__device__ __align__(16) float g_y[NPIX * 256];   // per pixel: q*s | k | v | raw x
__device__ __align__(16) float g_osum[NPIX * 64];
__device__ __align__(16) float g_const[192];      // qkv row for masked/OOB slots
__device__ float g_qwT[64 * 192];
__device__ float g_w1T[64 * 256];
__device__ float g_w2T[256 * 64];
__device__ float g_projT[64 * 64];
__device__ float g_bias[8 * 25 * 25];

__device__ __forceinline__ float wsum(float v) {
#pragma unroll
    for (int o = 16; o; o >>= 1) v += __shfl_xor_sync(0xffffffffu, v, o);
    return v;
}

// ---- prep: transposed weights + rel-pos bias table ----
__global__ void prep(const float* __restrict__ qw, const float* __restrict__ w1,
                     const float* __restrict__ w2, const float* __restrict__ pw,
                     const float* __restrict__ rpb) {
    for (int i = blockIdx.x * blockDim.x + threadIdx.x; i < 54152; i += gridDim.x * blockDim.x) {
        if (i < 12288) { int c = i / 192, o = i % 192; g_qwT[i] = qw[o * 64 + c]; }
        else if (i < 28672) { int j = i - 12288; int c = j / 256, u = j % 256; g_w1T[j] = w1[u * 64 + c]; }
        else if (i < 45056) { int j = i - 28672; int u = j / 64, c = j % 64; g_w2T[j] = w2[c * 256 + u]; }
        else if (i < 49152) { int j = i - 45056; int c = j / 64, o = j % 64; g_projT[j] = pw[o * 64 + c]; }
        else {
            int j = i - 49152; int h = j / 625, r = j % 625; int qi = r / 25, kj = r % 25;
            int idx = (qi / 5 - kj / 5 + 4) * 9 + (qi % 5 - kj % 5 + 4);
            g_bias[j] = rpb[idx * 8 + h];
        }
    }
}

// ---- prep: constant qkv row (LN(0) = norm1_b) ----
__global__ void prep_const(const float* __restrict__ n1b, const float* __restrict__ qw,
                           const float* __restrict__ qb) {
    int o = threadIdx.x; if (o >= 192) return;
    float a = qb[o];
    for (int c = 0; c < 64; c++) a += n1b[c] * qw[o * 64 + c];
    if (o < 64) a *= QSCALE;
    g_const[o] = a;
}

// ---- k1: per-pixel LN1 + QKV (warp per pixel) ----
__global__ __launch_bounds__(256) void k1(const float* __restrict__ x,
                                          const float* __restrict__ n1w,
                                          const float* __restrict__ n1b,
                                          const float* __restrict__ qb) {
    int wid = (blockIdx.x * 256 + threadIdx.x) >> 5;
    int lane = threadIdx.x & 31;
    if (wid >= NPIX) return;
    int b = wid >> 12, hw = wid & 4095;
    const float* xb = x + (size_t)b * 64 * 4096 + hw;
    float x0 = __ldg(xb + (size_t)lane * 4096);
    float x1 = __ldg(xb + (size_t)(lane + 32) * 4096);
    float m  = wsum(x0 + x1) * (1.f / 64.f);
    float vv = wsum(x0 * x0 + x1 * x1) * (1.f / 64.f) - m * m;
    float rs = rsqrtf(vv + 1e-5f);
    float ln0 = (x0 - m) * rs * n1w[lane] + n1b[lane];
    float ln1 = (x1 - m) * rs * n1w[lane + 32] + n1b[lane + 32];
    float* yp = g_y + (size_t)wid * 256;
    yp[192 + lane] = x0; yp[224 + lane] = x1;
    float acc[6];
#pragma unroll
    for (int k = 0; k < 6; k++) acc[k] = 0.f;
    for (int c = 0; c < 64; c++) {
        float a  = __shfl_sync(0xffffffffu, ln0, c & 31);
        float bb = __shfl_sync(0xffffffffu, ln1, c & 31);
        float lc = (c < 32) ? a : bb;
        const float* wr = g_qwT + c * 192 + lane;
#pragma unroll
        for (int k = 0; k < 6; k++) acc[k] += lc * wr[32 * k];
    }
#pragma unroll
    for (int k = 0; k < 6; k++) {
        int o = lane + 32 * k;
        float v = acc[k] + qb[o];
        if (o < 64) v *= QSCALE;
        yp[o] = v;
    }
}

// ---- k2: window attention + residual row-sum (warp per pixel) ----
__global__ __launch_bounds__(256) void k2() {
    __shared__ float sb[5000];
    __shared__ int snbr[8][25];
    int tid = threadIdx.x;
    for (int i = tid; i < 5000; i += 256) sb[i] = g_bias[i];
    int wwarp = tid >> 5, lane = tid & 31;
    int p = blockIdx.x * 8 + wwarp;
    int b = p >> 12, hw = p & 4095, h0 = hw >> 6, w0 = hw & 63;
    if (lane < 25) {
        int ri = lane / 5 - 2, ci = lane % 5 - 2;
        int nh = h0 + ri, nw = w0 + ci;
        int ok = (lane < 12) && nh >= 0 && nh < 64 && nw >= 0 && nw < 64;
        snbr[wwarp][lane] = ok ? ((b << 12) + (nh << 6) + nw) * 256 : -1;
    }
    __syncthreads();
    int h = lane & 7;
    float osum[8];
#pragma unroll
    for (int d = 0; d < 8; d++) osum[d] = 0.f;
    const int* nbr = snbr[wwarp];
    for (int it = 0; it < 7; it++) {
        int r = (lane >> 3) + it * 4;
        if (r < 25) {
            int qo = nbr[r];
            const float* qp = (qo < 0) ? g_const : g_y + qo;
            float4 qa = *(const float4*)(qp + h * 8);
            float4 qd = *(const float4*)(qp + h * 8 + 4);
            float l[25]; float mx = -1e30f;
            const float* brow = sb + h * 625 + r * 25;
#pragma unroll
            for (int col = 0; col < 25; col++) {
                int ko = nbr[col];
                const float* kb = (ko < 0) ? g_const + 64 : g_y + ko + 64;
                float4 ka = *(const float4*)(kb + h * 8);
                float4 kd = *(const float4*)(kb + h * 8 + 4);
                float dot = qa.x * ka.x + qa.y * ka.y + qa.z * ka.z + qa.w * ka.w
                          + qd.x * kd.x + qd.y * kd.y + qd.z * kd.z + qd.w * kd.w;
                l[col] = dot + brow[col];
                mx = fmaxf(mx, l[col]);
            }
            float den = 0.f; float ac[8];
#pragma unroll
            for (int d = 0; d < 8; d++) ac[d] = 0.f;
#pragma unroll
            for (int col = 0; col < 25; col++) {
                float e = __expf(l[col] - mx);
                den += e;
                int vo = nbr[col];
                const float* vb = (vo < 0) ? g_const + 128 : g_y + vo + 128;
                float4 va = *(const float4*)(vb + h * 8);
                float4 vd = *(const float4*)(vb + h * 8 + 4);
                ac[0] += e * va.x; ac[1] += e * va.y; ac[2] += e * va.z; ac[3] += e * va.w;
                ac[4] += e * vd.x; ac[5] += e * vd.y; ac[6] += e * vd.z; ac[7] += e * vd.w;
            }
            float inv = 1.f / den;
#pragma unroll
            for (int d = 0; d < 8; d++) osum[d] += ac[d] * inv;
        }
    }
#pragma unroll
    for (int d = 0; d < 8; d++) {
        osum[d] += __shfl_xor_sync(0xffffffffu, osum[d], 8);
        osum[d] += __shfl_xor_sync(0xffffffffu, osum[d], 16);
    }
    if (lane < 8) {
        for (int s = 0; s < 12; s++) {
            int off = nbr[s];
            if (off >= 0) {
                const float* xr = g_y + off + 192 + h * 8;
#pragma unroll
                for (int d = 0; d < 8; d++) osum[d] += xr[d];
            }
        }
        float* op = g_osum + (size_t)p * 64 + h * 8;
#pragma unroll
        for (int d = 0; d < 8; d++) op[d] = osum[d];
    }
}

// ---- k3: LN2 + MLP(gelu exact) + residual + proj (warp per pixel) ----
__global__ __launch_bounds__(256) void k3(const float* __restrict__ n2w, const float* __restrict__ n2b,
                                          const float* __restrict__ b1, const float* __restrict__ b2,
                                          const float* __restrict__ pb, float* __restrict__ out) {
    int wid = (blockIdx.x * 256 + threadIdx.x) >> 5;
    int lane = threadIdx.x & 31;
    if (wid >= NPIX) return;
    const float* os = g_osum + (size_t)wid * 64;
    float x0 = os[lane], x1 = os[lane + 32];
    float m  = wsum(x0 + x1) * (1.f / 64.f);
    float vv = wsum(x0 * x0 + x1 * x1) * (1.f / 64.f) - m * m;
    float rs = rsqrtf(vv + 1e-5f);
    float ln0 = (x0 - m) * rs * n2w[lane] + n2b[lane];
    float ln1 = (x1 - m) * rs * n2w[lane + 32] + n2b[lane + 32];
    float hh[8];
#pragma unroll
    for (int k = 0; k < 8; k++) hh[k] = 0.f;
    for (int c = 0; c < 64; c++) {
        float a  = __shfl_sync(0xffffffffu, ln0, c & 31);
        float bb = __shfl_sync(0xffffffffu, ln1, c & 31);
        float lc = (c < 32) ? a : bb;
        const float* wr = g_w1T + c * 256 + lane;
#pragma unroll
        for (int k = 0; k < 8; k++) hh[k] += lc * wr[32 * k];
    }
#pragma unroll
    for (int k = 0; k < 8; k++) {
        float v = hh[k] + b1[lane + 32 * k];
        hh[k] = 0.5f * v * (1.f + erff(v * 0.70710678118f));
    }
    float o0 = 0.f, o1 = 0.f;
#pragma unroll
    for (int k = 0; k < 8; k++) {
        for (int s = 0; s < 32; s++) {
            float hv = __shfl_sync(0xffffffffu, hh[k], s);
            const float* wr = g_w2T + (s + 32 * k) * 64;
            o0 += hv * wr[lane]; o1 += hv * wr[lane + 32];
        }
    }
    float y0 = o0 + b2[lane] + x0;
    float y1 = o1 + b2[lane + 32] + x1;
    float p0 = 0.f, p1 = 0.f;
    for (int c = 0; c < 64; c++) {
        float a  = __shfl_sync(0xffffffffu, y0, c & 31);
        float bb = __shfl_sync(0xffffffffu, y1, c & 31);
        float yv = (c < 32) ? a : bb;
        const float* wr = g_projT + c * 64;
        p0 += yv * wr[lane]; p1 += yv * wr[lane + 32];
    }
    int b = wid >> 12, hw = wid & 4095;
    float* ob = out + (size_t)b * 64 * 4096 + hw;
    ob[(size_t)lane * 4096] = p0 + pb[lane];
    ob[(size_t)(lane + 32) * 4096] = p1 + pb[lane + 32];
}

extern "C" void kernel_launch(void* const* d_in, const int* in_sizes, int n_in,
                              void* d_out, int out_size) {
    const float* x    = (const float*)d_in[0];
    const float* n1w  = (const float*)d_in[1];
    const float* n1b  = (const float*)d_in[2];
    const float* qw   = (const float*)d_in[3];
    const float* qb   = (const float*)d_in[4];
    const float* rpb  = (const float*)d_in[5];
    const float* n2w  = (const float*)d_in[6];
    const float* n2b  = (const float*)d_in[7];
    const float* w1   = (const float*)d_in[8];
    const float* b1   = (const float*)d_in[9];
    const float* w2   = (const float*)d_in[10];
    const float* b2   = (const float*)d_in[11];
    const float* pw   = (const float*)d_in[12];
    const float* pb   = (const float*)d_in[13];
    float* out = (float*)d_out;

    prep<<<64, 256>>>(qw, w1, w2, pw, rpb);
    prep_const<<<1, 192>>>(n1b, qw, qb);
    k1<<<2048, 256>>>(x, n1w, n1b, qb);
    k2<<<2048, 256>>>();
    k3<<<2048, 256>>>(n2w, n2b, b1, b2, pb, out);
}

// round 4
// speedup vs baseline: 1.5203x; 1.5203x over previous
#include <cuda_runtime.h>
#include <math.h>

#define NPIX 16384
#define QSCALE 0.35355339059327373f
#define SLOT_STRIDE 260

__device__ __align__(16) float g_y[NPIX * 256];   // per pixel: q*s | k | v | raw x
__device__ __align__(16) float g_osum[NPIX * 64];
__device__ __align__(16) float g_const[192];      // qkv row for masked/OOB slots
__device__ float g_qwT[64 * 192];
__device__ float g_w1T[64 * 256];
__device__ float g_w2T[256 * 64];
__device__ float g_projT[64 * 64];
__device__ float g_ebias[8 * 25 * 25];            // exp(bias)

__device__ __forceinline__ float wsum(float v) {
#pragma unroll
    for (int o = 16; o; o >>= 1) v += __shfl_xor_sync(0xffffffffu, v, o);
    return v;
}

// ---- prep: transposed weights + exp(rel-pos bias) table ----
__global__ void prep(const float* __restrict__ qw, const float* __restrict__ w1,
                     const float* __restrict__ w2, const float* __restrict__ pw,
                     const float* __restrict__ rpb) {
    for (int i = blockIdx.x * blockDim.x + threadIdx.x; i < 54152; i += gridDim.x * blockDim.x) {
        if (i < 12288) { int c = i / 192, o = i % 192; g_qwT[i] = qw[o * 64 + c]; }
        else if (i < 28672) { int j = i - 12288; int c = j / 256, u = j % 256; g_w1T[j] = w1[u * 64 + c]; }
        else if (i < 45056) { int j = i - 28672; int u = j / 64, c = j % 64; g_w2T[j] = w2[c * 256 + u]; }
        else if (i < 49152) { int j = i - 45056; int c = j / 64, o = j % 64; g_projT[j] = pw[o * 64 + c]; }
        else {
            int j = i - 49152; int h = j / 625, r = j % 625; int qi = r / 25, kj = r % 25;
            int idx = (qi / 5 - kj / 5 + 4) * 9 + (qi % 5 - kj % 5 + 4);
            g_ebias[j] = __expf(rpb[idx * 8 + h]);
        }
    }
}

__global__ void prep_const(const float* __restrict__ n1b, const float* __restrict__ qw,
                           const float* __restrict__ qb) {
    int o = threadIdx.x; if (o >= 192) return;
    float a = qb[o];
    for (int c = 0; c < 64; c++) a += n1b[c] * qw[o * 64 + c];
    if (o < 64) a *= QSCALE;
    g_const[o] = a;
}

// ---- k1: per-pixel LN1 + QKV (warp per pixel) ----
__global__ __launch_bounds__(256) void k1(const float* __restrict__ x,
                                          const float* __restrict__ n1w,
                                          const float* __restrict__ n1b,
                                          const float* __restrict__ qb) {
    int wid = (blockIdx.x * 256 + threadIdx.x) >> 5;
    int lane = threadIdx.x & 31;
    if (wid >= NPIX) return;
    int b = wid >> 12, hw = wid & 4095;
    const float* xb = x + (size_t)b * 64 * 4096 + hw;
    float x0 = __ldg(xb + (size_t)lane * 4096);
    float x1 = __ldg(xb + (size_t)(lane + 32) * 4096);
    float m  = wsum(x0 + x1) * (1.f / 64.f);
    float vv = wsum(x0 * x0 + x1 * x1) * (1.f / 64.f) - m * m;
    float rs = rsqrtf(vv + 1e-5f);
    float ln0 = (x0 - m) * rs * n1w[lane] + n1b[lane];
    float ln1 = (x1 - m) * rs * n1w[lane + 32] + n1b[lane + 32];
    float* yp = g_y + (size_t)wid * 256;
    yp[192 + lane] = x0; yp[224 + lane] = x1;
    float acc[6];
#pragma unroll
    for (int k = 0; k < 6; k++) acc[k] = 0.f;
    for (int c = 0; c < 64; c++) {
        float a  = __shfl_sync(0xffffffffu, ln0, c & 31);
        float bb = __shfl_sync(0xffffffffu, ln1, c & 31);
        float lc = (c < 32) ? a : bb;
        const float* wr = g_qwT + c * 192 + lane;
#pragma unroll
        for (int k = 0; k < 6; k++) acc[k] += lc * wr[32 * k];
    }
#pragma unroll
    for (int k = 0; k < 6; k++) {
        int o = lane + 32 * k;
        float v = acc[k] + qb[o];
        if (o < 64) v *= QSCALE;
        yp[o] = v;
    }
}

// ---- k2: window attention via factored softmax + aggregated col weights ----
// block = 1 pixel, 256 threads
__global__ __launch_bounds__(256) void k2() {
    __shared__ float sQ[13 * SLOT_STRIDE];   // per slot: q|k|v|x (x=0 for const/OOB)
    __shared__ float sEB[5000];              // exp(bias)[8][25][25]
    __shared__ float sED[8 * 169];           // exp(q_i . k_j) [8][13][13]
    __shared__ float sInv[200], sCB[200];    // 1/den, const-group EB sum  [8][25]
    __shared__ float sW[104];                // aggregated col weights [8][13]
    __shared__ int   sMap[25];               // col/row -> distinct slot (12 = const)
    __shared__ int   sOff[13];               // gmem offset per slot (-1 = const)

    int tid = threadIdx.x;
    int p = blockIdx.x;
    int b = p >> 12, hw = p & 4095, h0 = hw >> 6, w0 = hw & 63;

    for (int i = tid; i < 5000; i += 256) sEB[i] = g_ebias[i];
    if (tid < 25) {
        int ri = tid / 5 - 2, ci = tid % 5 - 2;
        int nh = h0 + ri, nw = w0 + ci;
        int ok = (tid < 12) && nh >= 0 && nh < 64 && nw >= 0 && nw < 64;
        sMap[tid] = ok ? tid : 12;
        if (tid < 13) sOff[tid] = -1;
        if (ok) sOff[tid] = ((b << 12) + (nh << 6) + nw) * 256;
    }
    __syncthreads();

    // stage 13 slots x 64 float4 (q|k|v|x); const slot: g_const then zeros
    for (int i = tid; i < 13 * 64; i += 256) {
        int slot = i >> 6, j = i & 63;
        int off = sOff[slot];
        float4 v;
        if (off >= 0)       v = *(const float4*)(g_y + off + j * 4);
        else if (j < 48)    v = *(const float4*)(g_const + j * 4);
        else                v = make_float4(0.f, 0.f, 0.f, 0.f);
        *(float4*)(sQ + slot * SLOT_STRIDE + j * 4) = v;
    }
    __syncthreads();

    // dots: (h, qi) -> 13 exp(dot) entries
    if (tid < 104) {
        int h = tid / 13, qi = tid % 13;
        float4 qa = *(const float4*)(sQ + qi * SLOT_STRIDE + h * 8);
        float4 qd = *(const float4*)(sQ + qi * SLOT_STRIDE + h * 8 + 4);
        float* ed = sED + h * 169 + qi * 13;
#pragma unroll
        for (int ki = 0; ki < 13; ki++) {
            const float* kb = sQ + ki * SLOT_STRIDE + 64 + h * 8;
            float4 ka = *(const float4*)kb;
            float4 kd = *(const float4*)(kb + 4);
            float dot = qa.x * ka.x + qa.y * ka.y + qa.z * ka.z + qa.w * ka.w
                      + qd.x * kd.x + qd.y * kd.y + qd.z * kd.z + qd.w * kd.w;
            ed[ki] = __expf(dot);
        }
    }
    __syncthreads();

    // pass1: (h, r) -> 1/den and const-group EB sum
    if (tid < 200) {
        int h = tid / 25, r = tid % 25;
        int qi = sMap[r];
        const float* eb = sEB + h * 625 + r * 25;
        const float* ed = sED + h * 169 + qi * 13;
        float den = 0.f, cb = 0.f;
#pragma unroll
        for (int col = 0; col < 25; col++) {
            int ki = sMap[col];
            float e = eb[col];
            den += e * ed[ki];
            if (ki == 12) cb += e;
        }
        sInv[tid] = 1.f / den;
        sCB[tid] = cb;
    }
    __syncthreads();

    // pass2: (h, c) -> aggregated softmax weight for distinct col c
    if (tid < 104) {
        int h = tid / 13, c = tid % 13;
        const float* ed = sED + h * 169;
        const float* iv = sInv + h * 25;
        float w = 0.f;
        if (c == 12) {
            const float* cb = sCB + h * 25;
#pragma unroll
            for (int r = 0; r < 25; r++) w += iv[r] * ed[sMap[r] * 13 + 12] * cb[r];
        } else if (sMap[c] == c) {
            const float* eb = sEB + h * 625 + c;
#pragma unroll
            for (int r = 0; r < 25; r++) w += iv[r] * ed[sMap[r] * 13 + c] * eb[r * 25];
        }
        sW[tid] = w;
    }
    __syncthreads();

    // pass3: output channel ch = weighted v + residual x sum
    if (tid < 64) {
        int h = tid >> 3;
        const float* w = sW + h * 13;
        float acc = 0.f;
#pragma unroll
        for (int c = 0; c < 13; c++) acc += w[c] * sQ[c * SLOT_STRIDE + 128 + tid];
#pragma unroll
        for (int s = 0; s < 12; s++) acc += sQ[s * SLOT_STRIDE + 192 + tid];
        g_osum[(size_t)p * 64 + tid] = acc;
    }
}

// ---- k3: LN2 + MLP(gelu exact) + residual + proj (warp per pixel) ----
__global__ __launch_bounds__(256) void k3(const float* __restrict__ n2w, const float* __restrict__ n2b,
                                          const float* __restrict__ b1, const float* __restrict__ b2,
                                          const float* __restrict__ pb, float* __restrict__ out) {
    int wid = (blockIdx.x * 256 + threadIdx.x) >> 5;
    int lane = threadIdx.x & 31;
    if (wid >= NPIX) return;
    const float* os = g_osum + (size_t)wid * 64;
    float x0 = os[lane], x1 = os[lane + 32];
    float m  = wsum(x0 + x1) * (1.f / 64.f);
    float vv = wsum(x0 * x0 + x1 * x1) * (1.f / 64.f) - m * m;
    float rs = rsqrtf(vv + 1e-5f);
    float ln0 = (x0 - m) * rs * n2w[lane] + n2b[lane];
    float ln1 = (x1 - m) * rs * n2w[lane + 32] + n2b[lane + 32];
    float hh[8];
#pragma unroll
    for (int k = 0; k < 8; k++) hh[k] = 0.f;
    for (int c = 0; c < 64; c++) {
        float a  = __shfl_sync(0xffffffffu, ln0, c & 31);
        float bb = __shfl_sync(0xffffffffu, ln1, c & 31);
        float lc = (c < 32) ? a : bb;
        const float* wr = g_w1T + c * 256 + lane;
#pragma unroll
        for (int k = 0; k < 8; k++) hh[k] += lc * wr[32 * k];
    }
#pragma unroll
    for (int k = 0; k < 8; k++) {
        float v = hh[k] + b1[lane + 32 * k];
        hh[k] = 0.5f * v * (1.f + erff(v * 0.70710678118f));
    }
    float o0 = 0.f, o1 = 0.f;
#pragma unroll
    for (int k = 0; k < 8; k++) {
        for (int s = 0; s < 32; s++) {
            float hv = __shfl_sync(0xffffffffu, hh[k], s);
            const float* wr = g_w2T + (s + 32 * k) * 64;
            o0 += hv * wr[lane]; o1 += hv * wr[lane + 32];
        }
    }
    float y0 = o0 + b2[lane] + x0;
    float y1 = o1 + b2[lane + 32] + x1;
    float p0 = 0.f, p1 = 0.f;
    for (int c = 0; c < 64; c++) {
        float a  = __shfl_sync(0xffffffffu, y0, c & 31);
        float bb = __shfl_sync(0xffffffffu, y1, c & 31);
        float yv = (c < 32) ? a : bb;
        const float* wr = g_projT + c * 64;
        p0 += yv * wr[lane]; p1 += yv * wr[lane + 32];
    }
    int b = wid >> 12, hw = wid & 4095;
    float* ob = out + (size_t)b * 64 * 4096 + hw;
    ob[(size_t)lane * 4096] = p0 + pb[lane];
    ob[(size_t)(lane + 32) * 4096] = p1 + pb[lane + 32];
}

extern "C" void kernel_launch(void* const* d_in, const int* in_sizes, int n_in,
                              void* d_out, int out_size) {
    const float* x    = (const float*)d_in[0];
    const float* n1w  = (const float*)d_in[1];
    const float* n1b  = (const float*)d_in[2];
    const float* qw   = (const float*)d_in[3];
    const float* qb   = (const float*)d_in[4];
    const float* rpb  = (const float*)d_in[5];
    const float* n2w  = (const float*)d_in[6];
    const float* n2b  = (const float*)d_in[7];
    const float* w1   = (const float*)d_in[8];
    const float* b1   = (const float*)d_in[9];
    const float* w2   = (const float*)d_in[10];
    const float* b2   = (const float*)d_in[11];
    const float* pw   = (const float*)d_in[12];
    const float* pb   = (const float*)d_in[13];
    float* out = (float*)d_out;

    prep<<<64, 256>>>(qw, w1, w2, pw, rpb);
    prep_const<<<1, 192>>>(n1b, qw, qb);
    k1<<<2048, 256>>>(x, n1w, n1b, qb);
    k2<<<16384, 256>>>();
    k3<<<2048, 256>>>(n2w, n2b, b1, b2, pb, out);
}

// round 5
// speedup vs baseline: 1.8919x; 1.2444x over previous
#include <cuda_runtime.h>
#include <math.h>

#define NPIX 16384
#define QSCALE 0.35355339059327373f
#define SLOT_STRIDE 260

__device__ __align__(16) float g_y[NPIX * 256];   // per pixel: q*s | k | v | raw x
__device__ __align__(16) float g_osum[NPIX * 64];
__device__ __align__(16) float g_const[192];      // qkv row for masked/OOB slots
__device__ float g_qwT[64 * 192];
__device__ float g_w1T[64 * 256];
__device__ float g_w2T[256 * 64];
__device__ float g_projT[64 * 64];
__device__ float g_ebias[8 * 25 * 25];            // exp(bias) full (boundary path)
__device__ float g_eb12[8 * 25 * 12];             // exp(bias)[h][r][c<12] (interior)
__device__ float g_cb[8 * 25];                    // sum_{c>=12} exp(bias) (interior)

__device__ __forceinline__ float wsum(float v) {
#pragma unroll
    for (int o = 16; o; o >>= 1) v += __shfl_xor_sync(0xffffffffu, v, o);
    return v;
}

// ---- prep: transposed weights + exp(bias) tables ----
__global__ void prep(const float* __restrict__ qw, const float* __restrict__ w1,
                     const float* __restrict__ w2, const float* __restrict__ pw,
                     const float* __restrict__ rpb) {
    for (int i = blockIdx.x * blockDim.x + threadIdx.x; i < 56752; i += gridDim.x * blockDim.x) {
        if (i < 12288) { int c = i / 192, o = i % 192; g_qwT[i] = qw[o * 64 + c]; }
        else if (i < 28672) { int j = i - 12288; int c = j / 256, u = j % 256; g_w1T[j] = w1[u * 64 + c]; }
        else if (i < 45056) { int j = i - 28672; int u = j / 64, c = j % 64; g_w2T[j] = w2[c * 256 + u]; }
        else if (i < 49152) { int j = i - 45056; int c = j / 64, o = j % 64; g_projT[j] = pw[o * 64 + c]; }
        else if (i < 54152) {
            int j = i - 49152; int h = j / 625, r = j % 625; int qi = r / 25, kj = r % 25;
            int idx = (qi / 5 - kj / 5 + 4) * 9 + (qi % 5 - kj % 5 + 4);
            g_ebias[j] = __expf(rpb[idx * 8 + h]);
        } else if (i < 56552) {
            int j = i - 54152; int h = j / 300, rem = j % 300; int r = rem / 12, c = rem % 12;
            int idx = (r / 5 - c / 5 + 4) * 9 + (r % 5 - c % 5 + 4);
            g_eb12[j] = __expf(rpb[idx * 8 + h]);
        } else {
            int j = i - 56552; int h = j / 25, r = j % 25;
            float s = 0.f;
            for (int c = 12; c < 25; c++) {
                int idx = (r / 5 - c / 5 + 4) * 9 + (r % 5 - c % 5 + 4);
                s += __expf(rpb[idx * 8 + h]);
            }
            g_cb[j] = s;
        }
    }
}

__global__ void prep_const(const float* __restrict__ n1b, const float* __restrict__ qw,
                           const float* __restrict__ qb) {
    int o = threadIdx.x; if (o >= 192) return;
    float a = qb[o];
    for (int c = 0; c < 64; c++) a += n1b[c] * qw[o * 64 + c];
    if (o < 64) a *= QSCALE;
    g_const[o] = a;
}

// ---- k1: per-pixel LN1 + QKV (warp per pixel) ----
__global__ __launch_bounds__(256) void k1(const float* __restrict__ x,
                                          const float* __restrict__ n1w,
                                          const float* __restrict__ n1b,
                                          const float* __restrict__ qb) {
    int wid = (blockIdx.x * 256 + threadIdx.x) >> 5;
    int lane = threadIdx.x & 31;
    if (wid >= NPIX) return;
    int b = wid >> 12, hw = wid & 4095;
    const float* xb = x + (size_t)b * 64 * 4096 + hw;
    float x0 = __ldg(xb + (size_t)lane * 4096);
    float x1 = __ldg(xb + (size_t)(lane + 32) * 4096);
    float m  = wsum(x0 + x1) * (1.f / 64.f);
    float vv = wsum(x0 * x0 + x1 * x1) * (1.f / 64.f) - m * m;
    float rs = rsqrtf(vv + 1e-5f);
    float ln0 = (x0 - m) * rs * n1w[lane] + n1b[lane];
    float ln1 = (x1 - m) * rs * n1w[lane + 32] + n1b[lane + 32];
    float* yp = g_y + (size_t)wid * 256;
    yp[192 + lane] = x0; yp[224 + lane] = x1;
    float acc[6];
#pragma unroll
    for (int k = 0; k < 6; k++) acc[k] = 0.f;
    for (int c = 0; c < 64; c++) {
        float a  = __shfl_sync(0xffffffffu, ln0, c & 31);
        float bb = __shfl_sync(0xffffffffu, ln1, c & 31);
        float lc = (c < 32) ? a : bb;
        const float* wr = g_qwT + c * 192 + lane;
#pragma unroll
        for (int k = 0; k < 6; k++) acc[k] += lc * wr[32 * k];
    }
#pragma unroll
    for (int k = 0; k < 6; k++) {
        int o = lane + 32 * k;
        float v = acc[k] + qb[o];
        if (o < 64) v *= QSCALE;
        yp[o] = v;
    }
}

// ---- k2i: interior pixels (all 12 slots valid, sMap = identity) ----
__global__ __launch_bounds__(256) void k2i() {
    __shared__ float sQ[13 * SLOT_STRIDE];
    __shared__ float sEB12[2400];
    __shared__ float sCB[200];
    __shared__ float sED[8 * 169];
    __shared__ float sInv[200];
    __shared__ float sW[104];

    int tid = threadIdx.x;
    int idx = blockIdx.x;
    int b = idx / 3600, rem = idx - b * 3600;
    int h0 = 2 + rem / 60, w0 = 2 + rem % 60;
    int base = (b << 12) + (h0 << 6) + w0;

    for (int i = tid; i < 2400; i += 256) sEB12[i] = g_eb12[i];
    if (tid < 200) sCB[tid] = g_cb[tid];

    for (int i = tid; i < 13 * 64; i += 256) {
        int slot = i >> 6, j = i & 63;
        float4 v;
        if (slot < 12) {
            int off = (base + (slot / 5 - 2) * 64 + (slot % 5 - 2)) * 256;
            v = *(const float4*)(g_y + off + j * 4);
        } else {
            v = (j < 48) ? *(const float4*)(g_const + j * 4) : make_float4(0.f, 0.f, 0.f, 0.f);
        }
        *(float4*)(sQ + slot * SLOT_STRIDE + j * 4) = v;
    }
    __syncthreads();

    if (tid < 104) {
        int h = tid / 13, qi = tid - h * 13;
        float4 qa = *(const float4*)(sQ + qi * SLOT_STRIDE + h * 8);
        float4 qd = *(const float4*)(sQ + qi * SLOT_STRIDE + h * 8 + 4);
        float* ed = sED + h * 169 + qi * 13;
#pragma unroll
        for (int ki = 0; ki < 13; ki++) {
            const float* kb = sQ + ki * SLOT_STRIDE + 64 + h * 8;
            float4 ka = *(const float4*)kb;
            float4 kd = *(const float4*)(kb + 4);
            float dot = qa.x * ka.x + qa.y * ka.y + qa.z * ka.z + qa.w * ka.w
                      + qd.x * kd.x + qd.y * kd.y + qd.z * kd.z + qd.w * kd.w;
            ed[ki] = __expf(dot);
        }
    }
    __syncthreads();

    if (tid < 200) {
        int h = tid / 25, r = tid - h * 25;
        int qi = (r < 12) ? r : 12;
        const float* ed = sED + h * 169 + qi * 13;
        const float* eb = sEB12 + h * 300 + r * 12;
        float den = sCB[tid] * ed[12];
#pragma unroll
        for (int c = 0; c < 12; c++) den += eb[c] * ed[c];
        sInv[tid] = 1.f / den;
    }
    __syncthreads();

    if (tid < 104) {
        int h = tid / 13, c = tid - h * 13;
        const float* ed = sED + h * 169;
        const float* iv = sInv + h * 25;
        float w = 0.f, t = 0.f;
        if (c < 12) {
            const float* eb = sEB12 + h * 300 + c;
#pragma unroll
            for (int r = 0; r < 12; r++) w += iv[r] * ed[r * 13 + c] * eb[r * 12];
#pragma unroll
            for (int r = 12; r < 25; r++) t += iv[r] * eb[r * 12];
            w += ed[156 + c] * t;
        } else {
            const float* cb = sCB + h * 25;
#pragma unroll
            for (int r = 0; r < 12; r++) w += iv[r] * ed[r * 13 + 12] * cb[r];
#pragma unroll
            for (int r = 12; r < 25; r++) t += iv[r] * cb[r];
            w += ed[168] * t;
        }
        sW[tid] = w;
    }
    __syncthreads();

    if (tid < 64) {
        int h = tid >> 3;
        const float* w = sW + h * 13;
        float acc = 0.f;
#pragma unroll
        for (int c = 0; c < 13; c++) acc += w[c] * sQ[c * SLOT_STRIDE + 128 + tid];
#pragma unroll
        for (int s = 0; s < 12; s++) acc += sQ[s * SLOT_STRIDE + 192 + tid];
        g_osum[(size_t)base * 64 + tid] = acc;
    }
}

// ---- k2b: boundary pixels (generic masked path) ----
__global__ __launch_bounds__(256) void k2b() {
    __shared__ float sQ[13 * SLOT_STRIDE];
    __shared__ float sEB[5000];
    __shared__ float sED[8 * 169];
    __shared__ float sInv[200], sCB[200];
    __shared__ float sW[104];
    __shared__ int   sMap[25];
    __shared__ int   sOff[13];

    int tid = threadIdx.x;
    int t = blockIdx.x;
    int b = t / 496, u = t - b * 496;
    int h0, w0;
    if (u < 128)      { h0 = u >> 6; w0 = u & 63; }
    else if (u < 256) { int v = u - 128; h0 = 62 + (v >> 6); w0 = v & 63; }
    else              { int v = u - 256; h0 = 2 + v / 4; int c = v & 3; w0 = (c < 2) ? c : (60 + c); }
    int p = (b << 12) + (h0 << 6) + w0;

    for (int i = tid; i < 5000; i += 256) sEB[i] = g_ebias[i];
    if (tid < 25) {
        int ri = tid / 5 - 2, ci = tid % 5 - 2;
        int nh = h0 + ri, nw = w0 + ci;
        int ok = (tid < 12) && nh >= 0 && nh < 64 && nw >= 0 && nw < 64;
        sMap[tid] = ok ? tid : 12;
        if (tid < 13) sOff[tid] = -1;
        if (ok) sOff[tid] = ((b << 12) + (nh << 6) + nw) * 256;
    }
    __syncthreads();

    for (int i = tid; i < 13 * 64; i += 256) {
        int slot = i >> 6, j = i & 63;
        int off = sOff[slot];
        float4 v;
        if (off >= 0)    v = *(const float4*)(g_y + off + j * 4);
        else if (j < 48) v = *(const float4*)(g_const + j * 4);
        else             v = make_float4(0.f, 0.f, 0.f, 0.f);
        *(float4*)(sQ + slot * SLOT_STRIDE + j * 4) = v;
    }
    __syncthreads();

    if (tid < 104) {
        int h = tid / 13, qi = tid % 13;
        float4 qa = *(const float4*)(sQ + qi * SLOT_STRIDE + h * 8);
        float4 qd = *(const float4*)(sQ + qi * SLOT_STRIDE + h * 8 + 4);
        float* ed = sED + h * 169 + qi * 13;
#pragma unroll
        for (int ki = 0; ki < 13; ki++) {
            const float* kb = sQ + ki * SLOT_STRIDE + 64 + h * 8;
            float4 ka = *(const float4*)kb;
            float4 kd = *(const float4*)(kb + 4);
            float dot = qa.x * ka.x + qa.y * ka.y + qa.z * ka.z + qa.w * ka.w
                      + qd.x * kd.x + qd.y * kd.y + qd.z * kd.z + qd.w * kd.w;
            ed[ki] = __expf(dot);
        }
    }
    __syncthreads();

    if (tid < 200) {
        int h = tid / 25, r = tid % 25;
        int qi = sMap[r];
        const float* eb = sEB + h * 625 + r * 25;
        const float* ed = sED + h * 169 + qi * 13;
        float den = 0.f, cb = 0.f;
#pragma unroll
        for (int col = 0; col < 25; col++) {
            int ki = sMap[col];
            float e = eb[col];
            den += e * ed[ki];
            if (ki == 12) cb += e;
        }
        sInv[tid] = 1.f / den;
        sCB[tid] = cb;
    }
    __syncthreads();

    if (tid < 104) {
        int h = tid / 13, c = tid % 13;
        const float* ed = sED + h * 169;
        const float* iv = sInv + h * 25;
        float w = 0.f;
        if (c == 12) {
            const float* cb = sCB + h * 25;
#pragma unroll
            for (int r = 0; r < 25; r++) w += iv[r] * ed[sMap[r] * 13 + 12] * cb[r];
        } else if (sMap[c] == c) {
            const float* eb = sEB + h * 625 + c;
#pragma unroll
            for (int r = 0; r < 25; r++) w += iv[r] * ed[sMap[r] * 13 + c] * eb[r * 25];
        }
        sW[tid] = w;
    }
    __syncthreads();

    if (tid < 64) {
        int h = tid >> 3;
        const float* w = sW + h * 13;
        float acc = 0.f;
#pragma unroll
        for (int c = 0; c < 13; c++) acc += w[c] * sQ[c * SLOT_STRIDE + 128 + tid];
#pragma unroll
        for (int s = 0; s < 12; s++) acc += sQ[s * SLOT_STRIDE + 192 + tid];
        g_osum[(size_t)p * 64 + tid] = acc;
    }
}

// ---- k3: LN2 + MLP(gelu exact) + residual + proj (warp per pixel) ----
__global__ __launch_bounds__(256) void k3(const float* __restrict__ n2w, const float* __restrict__ n2b,
                                          const float* __restrict__ b1, const float* __restrict__ b2,
                                          const float* __restrict__ pb, float* __restrict__ out) {
    int wid = (blockIdx.x * 256 + threadIdx.x) >> 5;
    int lane = threadIdx.x & 31;
    if (wid >= NPIX) return;
    const float* os = g_osum + (size_t)wid * 64;
    float x0 = os[lane], x1 = os[lane + 32];
    float m  = wsum(x0 + x1) * (1.f / 64.f);
    float vv = wsum(x0 * x0 + x1 * x1) * (1.f / 64.f) - m * m;
    float rs = rsqrtf(vv + 1e-5f);
    float ln0 = (x0 - m) * rs * n2w[lane] + n2b[lane];
    float ln1 = (x1 - m) * rs * n2w[lane + 32] + n2b[lane + 32];
    float hh[8];
#pragma unroll
    for (int k = 0; k < 8; k++) hh[k] = 0.f;
    for (int c = 0; c < 64; c++) {
        float a  = __shfl_sync(0xffffffffu, ln0, c & 31);
        float bb = __shfl_sync(0xffffffffu, ln1, c & 31);
        float lc = (c < 32) ? a : bb;
        const float* wr = g_w1T + c * 256 + lane;
#pragma unroll
        for (int k = 0; k < 8; k++) hh[k] += lc * wr[32 * k];
    }
#pragma unroll
    for (int k = 0; k < 8; k++) {
        float v = hh[k] + b1[lane + 32 * k];
        hh[k] = 0.5f * v * (1.f + erff(v * 0.70710678118f));
    }
    float o0 = 0.f, o1 = 0.f;
#pragma unroll
    for (int k = 0; k < 8; k++) {
        for (int s = 0; s < 32; s++) {
            float hv = __shfl_sync(0xffffffffu, hh[k], s);
            const float* wr = g_w2T + (s + 32 * k) * 64;
            o0 += hv * wr[lane]; o1 += hv * wr[lane + 32];
        }
    }
    float y0 = o0 + b2[lane] + x0;
    float y1 = o1 + b2[lane + 32] + x1;
    float p0 = 0.f, p1 = 0.f;
    for (int c = 0; c < 64; c++) {
        float a  = __shfl_sync(0xffffffffu, y0, c & 31);
        float bb = __shfl_sync(0xffffffffu, y1, c & 31);
        float yv = (c < 32) ? a : bb;
        const float* wr = g_projT + c * 64;
        p0 += yv * wr[lane]; p1 += yv * wr[lane + 32];
    }
    int b = wid >> 12, hw = wid & 4095;
    float* ob = out + (size_t)b * 64 * 4096 + hw;
    ob[(size_t)lane * 4096] = p0 + pb[lane];
    ob[(size_t)(lane + 32) * 4096] = p1 + pb[lane + 32];
}

extern "C" void kernel_launch(void* const* d_in, const int* in_sizes, int n_in,
                              void* d_out, int out_size) {
    const float* x    = (const float*)d_in[0];
    const float* n1w  = (const float*)d_in[1];
    const float* n1b  = (const float*)d_in[2];
    const float* qw   = (const float*)d_in[3];
    const float* qb   = (const float*)d_in[4];
    const float* rpb  = (const float*)d_in[5];
    const float* n2w  = (const float*)d_in[6];
    const float* n2b  = (const float*)d_in[7];
    const float* w1   = (const float*)d_in[8];
    const float* b1   = (const float*)d_in[9];
    const float* w2   = (const float*)d_in[10];
    const float* b2   = (const float*)d_in[11];
    const float* pw   = (const float*)d_in[12];
    const float* pb   = (const float*)d_in[13];
    float* out = (float*)d_out;

    prep<<<64, 256>>>(qw, w1, w2, pw, rpb);
    prep_const<<<1, 192>>>(n1b, qw, qb);
    k1<<<2048, 256>>>(x, n1w, n1b, qb);
    k2i<<<14400, 256>>>();
    k2b<<<1984, 256>>>();
    k3<<<2048, 256>>>(n2w, n2b, b1, b2, pb, out);
}

// round 6
// speedup vs baseline: 2.2631x; 1.1962x over previous
#include <cuda_runtime.h>
#include <math.h>

#define NPIX 16384
#define QSCALE 0.35355339059327373f
#define SLOT_STRIDE 260

__device__ __align__(16) float g_y[NPIX * 256];   // per pixel: q*s | k | v | raw x
__device__ __align__(16) float g_osum[NPIX * 64];
__device__ __align__(16) float g_const[192];      // qkv row for masked/OOB slots
__device__ float g_qwT[64 * 192];                 // [c][o]
__device__ float g_w1T[64 * 256];                 // [c][u]
__device__ float g_w2T[256 * 64];                 // [u][o]
__device__ float g_projT[64 * 64];                // [c][o]
__device__ float g_ebias[8 * 25 * 25];            // exp(bias) full (boundary path)
__device__ float g_eb12[8 * 25 * 12];             // exp(bias)[h][r][c<12] (interior)
__device__ float g_cb[8 * 25];                    // sum_{c>=12} exp(bias) (interior)

__device__ __forceinline__ float wsum(float v) {
#pragma unroll
    for (int o = 16; o; o >>= 1) v += __shfl_xor_sync(0xffffffffu, v, o);
    return v;
}

// ---- prep: transposed weights + exp(bias) tables ----
__global__ void prep(const float* __restrict__ qw, const float* __restrict__ w1,
                     const float* __restrict__ w2, const float* __restrict__ pw,
                     const float* __restrict__ rpb) {
    for (int i = blockIdx.x * blockDim.x + threadIdx.x; i < 56752; i += gridDim.x * blockDim.x) {
        if (i < 12288) { int c = i / 192, o = i % 192; g_qwT[i] = qw[o * 64 + c]; }
        else if (i < 28672) { int j = i - 12288; int c = j / 256, u = j % 256; g_w1T[j] = w1[u * 64 + c]; }
        else if (i < 45056) { int j = i - 28672; int u = j / 64, c = j % 64; g_w2T[j] = w2[c * 256 + u]; }
        else if (i < 49152) { int j = i - 45056; int c = j / 64, o = j % 64; g_projT[j] = pw[o * 64 + c]; }
        else if (i < 54152) {
            int j = i - 49152; int h = j / 625, r = j % 625; int qi = r / 25, kj = r % 25;
            int idx = (qi / 5 - kj / 5 + 4) * 9 + (qi % 5 - kj % 5 + 4);
            g_ebias[j] = __expf(rpb[idx * 8 + h]);
        } else if (i < 56552) {
            int j = i - 54152; int h = j / 300, rem = j % 300; int r = rem / 12, c = rem % 12;
            int idx = (r / 5 - c / 5 + 4) * 9 + (r % 5 - c % 5 + 4);
            g_eb12[j] = __expf(rpb[idx * 8 + h]);
        } else {
            int j = i - 56552; int h = j / 25, r = j % 25;
            float s = 0.f;
            for (int c = 12; c < 25; c++) {
                int idx = (r / 5 - c / 5 + 4) * 9 + (r % 5 - c % 5 + 4);
                s += __expf(rpb[idx * 8 + h]);
            }
            g_cb[j] = s;
        }
    }
}

__global__ void prep_const(const float* __restrict__ n1b, const float* __restrict__ qw,
                           const float* __restrict__ qb) {
    int o = threadIdx.x; if (o >= 192) return;
    float a = qb[o];
    for (int c = 0; c < 64; c++) a += n1b[c] * qw[o * 64 + c];
    if (o < 64) a *= QSCALE;
    g_const[o] = a;
}

// ---- k1: LN1 + QKV, register-tiled: block=64 pixels, warp=8 pixels ----
__global__ __launch_bounds__(256) void k1(const float* __restrict__ x,
                                          const float* __restrict__ n1w,
                                          const float* __restrict__ n1b,
                                          const float* __restrict__ qb) {
    __shared__ float sLn[64][65];
    int tid = threadIdx.x, lane = tid & 31, w = tid >> 5;
    int p0 = blockIdx.x * 64;
    float nw0 = n1w[lane], nw1 = n1w[lane + 32];
    float nb0 = n1b[lane], nb1 = n1b[lane + 32];
#pragma unroll
    for (int t = 0; t < 8; t++) {
        int wid = p0 + w * 8 + t;
        int b = wid >> 12, hw = wid & 4095;
        const float* xb = x + (size_t)b * 262144 + hw;
        float x0 = __ldg(xb + (size_t)lane * 4096);
        float x1 = __ldg(xb + (size_t)(lane + 32) * 4096);
        float m  = wsum(x0 + x1) * (1.f / 64.f);
        float vv = wsum(x0 * x0 + x1 * x1) * (1.f / 64.f) - m * m;
        float rs = rsqrtf(vv + 1e-5f);
        sLn[w * 8 + t][lane]      = (x0 - m) * rs * nw0 + nb0;
        sLn[w * 8 + t][lane + 32] = (x1 - m) * rs * nw1 + nb1;
        float* yp = g_y + (size_t)wid * 256;
        yp[192 + lane] = x0; yp[224 + lane] = x1;
    }
    __syncwarp();
    float acc[6][8];
#pragma unroll
    for (int k = 0; k < 6; k++)
#pragma unroll
        for (int j = 0; j < 8; j++) acc[k][j] = 0.f;
    for (int c = 0; c < 64; c++) {
        float wv[6];
        const float* wr = g_qwT + c * 192 + lane;
#pragma unroll
        for (int k = 0; k < 6; k++) wv[k] = wr[32 * k];
#pragma unroll
        for (int j = 0; j < 8; j++) {
            float l = sLn[w * 8 + j][c];
#pragma unroll
            for (int k = 0; k < 6; k++) acc[k][j] += wv[k] * l;
        }
    }
#pragma unroll
    for (int k = 0; k < 6; k++) {
        int o = lane + 32 * k;
        float bias = qb[o];
        float sc = (o < 64) ? QSCALE : 1.f;
#pragma unroll
        for (int j = 0; j < 8; j++)
            g_y[(size_t)(p0 + w * 8 + j) * 256 + o] = (acc[k][j] + bias) * sc;
    }
}

// ---- k2i: interior, 4-pixel horizontal strip per block ----
__global__ __launch_bounds__(256) void k2i() {
    __shared__ float sQ[22 * SLOT_STRIDE];
    __shared__ float sEB12[2400];
    __shared__ float sCB[200];
    __shared__ float sED[4 * 1352];
    __shared__ float sInv[4 * 200];
    __shared__ float sW[4 * 104];
    __shared__ int   sSlot[4][13];

    int tid = threadIdx.x;
    int idx = blockIdx.x;
    int b = idx / 900, rem = idx - b * 900;
    int h0 = 2 + rem / 15, w0 = 2 + (rem % 15) * 4;
    int base = (b << 12) + (h0 << 6) + w0;

    for (int i = tid; i < 2400; i += 256) sEB12[i] = g_eb12[i];
    if (tid < 200) sCB[tid] = g_cb[tid];
    if (tid < 52) {
        int j = tid / 13, ls = tid - j * 13;
        int g = (ls < 5) ? ls + j : (ls < 10) ? 8 + (ls - 5) + j : (ls < 12) ? 16 + (ls - 10) + j : 21;
        sSlot[j][ls] = g;
    }
    for (int i = tid; i < 22 * 64; i += 256) {
        int slot = i >> 6, jj = i & 63;
        float4 v;
        if (slot < 21) {
            int row, col;
            if (slot < 16) { row = slot >> 3; col = slot & 7; }
            else { row = 2; col = slot - 16; }
            int pp = base + (row - 2) * 64 + (col - 2);
            v = *(const float4*)(g_y + (size_t)pp * 256 + jj * 4);
        } else {
            v = (jj < 48) ? *(const float4*)(g_const + jj * 4) : make_float4(0.f, 0.f, 0.f, 0.f);
        }
        *(float4*)(sQ + slot * SLOT_STRIDE + jj * 4) = v;
    }
    __syncthreads();

    // dots: 416 tasks (pix, h, qi)
    for (int i = tid; i < 416; i += 256) {
        int pix = i / 104, t = i - pix * 104;
        int h = t / 13, qi = t - h * 13;
        int gq = sSlot[pix][qi];
        float4 qa = *(const float4*)(sQ + gq * SLOT_STRIDE + h * 8);
        float4 qd = *(const float4*)(sQ + gq * SLOT_STRIDE + h * 8 + 4);
        float* ed = sED + pix * 1352 + h * 169 + qi * 13;
#pragma unroll
        for (int ki = 0; ki < 13; ki++) {
            const float* kb = sQ + sSlot[pix][ki] * SLOT_STRIDE + 64 + h * 8;
            float4 ka = *(const float4*)kb;
            float4 kd = *(const float4*)(kb + 4);
            float dot = qa.x * ka.x + qa.y * ka.y + qa.z * ka.z + qa.w * ka.w
                      + qd.x * kd.x + qd.y * kd.y + qd.z * kd.z + qd.w * kd.w;
            ed[ki] = __expf(dot);
        }
    }
    __syncthreads();

    // pass1: 800 tasks (pix, h, r)
    for (int i = tid; i < 800; i += 256) {
        int pix = i / 200, t = i - pix * 200;
        int h = t / 25, r = t - h * 25;
        int qi = (r < 12) ? r : 12;
        const float* ed = sED + pix * 1352 + h * 169 + qi * 13;
        const float* eb = sEB12 + h * 300 + r * 12;
        float den = sCB[h * 25 + r] * ed[12];
#pragma unroll
        for (int c = 0; c < 12; c++) den += eb[c] * ed[c];
        sInv[pix * 200 + t] = 1.f / den;
    }
    __syncthreads();

    // pass2: 416 tasks (pix, h, c)
    for (int i = tid; i < 416; i += 256) {
        int pix = i / 104, t = i - pix * 104;
        int h = t / 13, c = t - h * 13;
        const float* ed = sED + pix * 1352 + h * 169;
        const float* iv = sInv + pix * 200 + h * 25;
        float w = 0.f, tt = 0.f;
        if (c < 12) {
            const float* eb = sEB12 + h * 300 + c;
#pragma unroll
            for (int r = 0; r < 12; r++) w += iv[r] * ed[r * 13 + c] * eb[r * 12];
#pragma unroll
            for (int r = 12; r < 25; r++) tt += iv[r] * eb[r * 12];
            w += ed[156 + c] * tt;
        } else {
            const float* cb = sCB + h * 25;
#pragma unroll
            for (int r = 0; r < 12; r++) w += iv[r] * ed[r * 13 + 12] * cb[r];
#pragma unroll
            for (int r = 12; r < 25; r++) tt += iv[r] * cb[r];
            w += ed[168] * tt;
        }
        sW[pix * 104 + t] = w;
    }
    __syncthreads();

    // pass3: 256 tasks (pix, ch)
    {
        int pix = tid >> 6, ch = tid & 63, h = ch >> 3;
        const float* w = sW + pix * 104 + h * 13;
        const int* sm = sSlot[pix];
        float acc = 0.f;
#pragma unroll
        for (int c = 0; c < 13; c++) acc += w[c] * sQ[sm[c] * SLOT_STRIDE + 128 + ch];
#pragma unroll
        for (int s = 0; s < 12; s++) acc += sQ[sm[s] * SLOT_STRIDE + 192 + ch];
        g_osum[(size_t)(base + pix) * 64 + ch] = acc;
    }
}

// ---- k2b: boundary pixels (generic masked path) ----
__global__ __launch_bounds__(256) void k2b() {
    __shared__ float sQ[13 * SLOT_STRIDE];
    __shared__ float sEB[5000];
    __shared__ float sED[8 * 169];
    __shared__ float sInv[200], sCB[200];
    __shared__ float sW[104];
    __shared__ int   sMap[25];
    __shared__ int   sOff[13];

    int tid = threadIdx.x;
    int t = blockIdx.x;
    int b = t / 496, u = t - b * 496;
    int h0, w0;
    if (u < 128)      { h0 = u >> 6; w0 = u & 63; }
    else if (u < 256) { int v = u - 128; h0 = 62 + (v >> 6); w0 = v & 63; }
    else              { int v = u - 256; h0 = 2 + v / 4; int c = v & 3; w0 = (c < 2) ? c : (60 + c); }
    int p = (b << 12) + (h0 << 6) + w0;

    for (int i = tid; i < 5000; i += 256) sEB[i] = g_ebias[i];
    if (tid < 25) {
        int ri = tid / 5 - 2, ci = tid % 5 - 2;
        int nh = h0 + ri, nw = w0 + ci;
        int ok = (tid < 12) && nh >= 0 && nh < 64 && nw >= 0 && nw < 64;
        sMap[tid] = ok ? tid : 12;
        if (tid < 13) sOff[tid] = -1;
        if (ok) sOff[tid] = ((b << 12) + (nh << 6) + nw) * 256;
    }
    __syncthreads();

    for (int i = tid; i < 13 * 64; i += 256) {
        int slot = i >> 6, j = i & 63;
        int off = sOff[slot];
        float4 v;
        if (off >= 0)    v = *(const float4*)(g_y + off + j * 4);
        else if (j < 48) v = *(const float4*)(g_const + j * 4);
        else             v = make_float4(0.f, 0.f, 0.f, 0.f);
        *(float4*)(sQ + slot * SLOT_STRIDE + j * 4) = v;
    }
    __syncthreads();

    if (tid < 104) {
        int h = tid / 13, qi = tid % 13;
        float4 qa = *(const float4*)(sQ + qi * SLOT_STRIDE + h * 8);
        float4 qd = *(const float4*)(sQ + qi * SLOT_STRIDE + h * 8 + 4);
        float* ed = sED + h * 169 + qi * 13;
#pragma unroll
        for (int ki = 0; ki < 13; ki++) {
            const float* kb = sQ + ki * SLOT_STRIDE + 64 + h * 8;
            float4 ka = *(const float4*)kb;
            float4 kd = *(const float4*)(kb + 4);
            float dot = qa.x * ka.x + qa.y * ka.y + qa.z * ka.z + qa.w * ka.w
                      + qd.x * kd.x + qd.y * kd.y + qd.z * kd.z + qd.w * kd.w;
            ed[ki] = __expf(dot);
        }
    }
    __syncthreads();

    if (tid < 200) {
        int h = tid / 25, r = tid % 25;
        int qi = sMap[r];
        const float* eb = sEB + h * 625 + r * 25;
        const float* ed = sED + h * 169 + qi * 13;
        float den = 0.f, cb = 0.f;
#pragma unroll
        for (int col = 0; col < 25; col++) {
            int ki = sMap[col];
            float e = eb[col];
            den += e * ed[ki];
            if (ki == 12) cb += e;
        }
        sInv[tid] = 1.f / den;
        sCB[tid] = cb;
    }
    __syncthreads();

    if (tid < 104) {
        int h = tid / 13, c = tid % 13;
        const float* ed = sED + h * 169;
        const float* iv = sInv + h * 25;
        float w = 0.f;
        if (c == 12) {
            const float* cb = sCB + h * 25;
#pragma unroll
            for (int r = 0; r < 25; r++) w += iv[r] * ed[sMap[r] * 13 + 12] * cb[r];
        } else if (sMap[c] == c) {
            const float* eb = sEB + h * 625 + c;
#pragma unroll
            for (int r = 0; r < 25; r++) w += iv[r] * ed[sMap[r] * 13 + c] * eb[r * 25];
        }
        sW[tid] = w;
    }
    __syncthreads();

    if (tid < 64) {
        int h = tid >> 3;
        const float* w = sW + h * 13;
        float acc = 0.f;
#pragma unroll
        for (int c = 0; c < 13; c++) acc += w[c] * sQ[c * SLOT_STRIDE + 128 + tid];
#pragma unroll
        for (int s = 0; s < 12; s++) acc += sQ[s * SLOT_STRIDE + 192 + tid];
        g_osum[(size_t)p * 64 + tid] = acc;
    }
}

// ---- k3: LN2 + MLP + proj, register-tiled: block=32 pixels, warp=4 pixels ----
__global__ __launch_bounds__(256) void k3(const float* __restrict__ n2w, const float* __restrict__ n2b,
                                          const float* __restrict__ b1, const float* __restrict__ b2,
                                          const float* __restrict__ pb, float* __restrict__ out) {
    __shared__ float sLn[32][68];     // reused as sY
    __shared__ float sH[32][260];
    int tid = threadIdx.x, lane = tid & 31, w = tid >> 5;
    int p0 = blockIdx.x * 32;

    float nw0 = n2w[lane], nw1 = n2w[lane + 32];
    float nb0 = n2b[lane], nb1 = n2b[lane + 32];
#pragma unroll
    for (int t = 0; t < 4; t++) {
        const float* os = g_osum + (size_t)(p0 + w * 4 + t) * 64;
        float x0 = os[lane], x1 = os[lane + 32];
        float m  = wsum(x0 + x1) * (1.f / 64.f);
        float vv = wsum(x0 * x0 + x1 * x1) * (1.f / 64.f) - m * m;
        float rs = rsqrtf(vv + 1e-5f);
        sLn[w * 4 + t][lane]      = (x0 - m) * rs * nw0 + nb0;
        sLn[w * 4 + t][lane + 32] = (x1 - m) * rs * nw1 + nb1;
    }
    __syncwarp();

    // fc1: thread = 8 outputs x 4 pixels
    float acc[8][4];
#pragma unroll
    for (int k = 0; k < 8; k++)
#pragma unroll
        for (int j = 0; j < 4; j++) acc[k][j] = 0.f;
    for (int c = 0; c < 64; c++) {
        float wv[8];
        const float* wr = g_w1T + c * 256 + lane;
#pragma unroll
        for (int k = 0; k < 8; k++) wv[k] = wr[32 * k];
#pragma unroll
        for (int j = 0; j < 4; j++) {
            float l = sLn[w * 4 + j][c];
#pragma unroll
            for (int k = 0; k < 8; k++) acc[k][j] += wv[k] * l;
        }
    }
#pragma unroll
    for (int k = 0; k < 8; k++) {
        float bb = b1[lane + 32 * k];
#pragma unroll
        for (int j = 0; j < 4; j++) {
            float v = acc[k][j] + bb;
            sH[w * 4 + j][lane + 32 * k] = 0.5f * v * (1.f + erff(v * 0.70710678118f));
        }
    }
    __syncwarp();

    // fc2 + residual: thread = 2 outputs x 4 pixels
    float a2[2][4];
#pragma unroll
    for (int k = 0; k < 2; k++)
#pragma unroll
        for (int j = 0; j < 4; j++) a2[k][j] = 0.f;
    for (int c0 = 0; c0 < 256; c0 += 4) {
        float4 h4[4];
#pragma unroll
        for (int j = 0; j < 4; j++) h4[j] = *(const float4*)&sH[w * 4 + j][c0];
#pragma unroll
        for (int d = 0; d < 4; d++) {
            const float* wr = g_w2T + (c0 + d) * 64;
            float w0v = wr[lane], w1v = wr[lane + 32];
#pragma unroll
            for (int j = 0; j < 4; j++) {
                float hv = (d == 0) ? h4[j].x : (d == 1) ? h4[j].y : (d == 2) ? h4[j].z : h4[j].w;
                a2[0][j] += w0v * hv; a2[1][j] += w1v * hv;
            }
        }
    }
    float bb0 = b2[lane], bb1 = b2[lane + 32];
#pragma unroll
    for (int j = 0; j < 4; j++) {
        const float* os = g_osum + (size_t)(p0 + w * 4 + j) * 64;
        sLn[w * 4 + j][lane]      = a2[0][j] + bb0 + os[lane];
        sLn[w * 4 + j][lane + 32] = a2[1][j] + bb1 + os[lane + 32];
    }
    __syncwarp();

    // proj: thread = 2 outputs x 4 pixels
    float a3[2][4];
#pragma unroll
    for (int k = 0; k < 2; k++)
#pragma unroll
        for (int j = 0; j < 4; j++) a3[k][j] = 0.f;
    for (int c0 = 0; c0 < 64; c0 += 4) {
        float4 y4[4];
#pragma unroll
        for (int j = 0; j < 4; j++) y4[j] = *(const float4*)&sLn[w * 4 + j][c0];
#pragma unroll
        for (int d = 0; d < 4; d++) {
            const float* wr = g_projT + (c0 + d) * 64;
            float w0v = wr[lane], w1v = wr[lane + 32];
#pragma unroll
            for (int j = 0; j < 4; j++) {
                float yv = (d == 0) ? y4[j].x : (d == 1) ? y4[j].y : (d == 2) ? y4[j].z : y4[j].w;
                a3[0][j] += w0v * yv; a3[1][j] += w1v * yv;
            }
        }
    }
    float pb0 = pb[lane], pb1 = pb[lane + 32];
#pragma unroll
    for (int j = 0; j < 4; j++) {
        int wid = p0 + w * 4 + j;
        int b = wid >> 12, hw = wid & 4095;
        float* ob = out + (size_t)b * 262144 + hw;
        ob[(size_t)lane * 4096]        = a3[0][j] + pb0;
        ob[(size_t)(lane + 32) * 4096] = a3[1][j] + pb1;
    }
}

extern "C" void kernel_launch(void* const* d_in, const int* in_sizes, int n_in,
                              void* d_out, int out_size) {
    const float* x    = (const float*)d_in[0];
    const float* n1w  = (const float*)d_in[1];
    const float* n1b  = (const float*)d_in[2];
    const float* qw   = (const float*)d_in[3];
    const float* qb   = (const float*)d_in[4];
    const float* rpb  = (const float*)d_in[5];
    const float* n2w  = (const float*)d_in[6];
    const float* n2b  = (const float*)d_in[7];
    const float* w1   = (const float*)d_in[8];
    const float* b1   = (const float*)d_in[9];
    const float* w2   = (const float*)d_in[10];
    const float* b2   = (const float*)d_in[11];
    const float* pw   = (const float*)d_in[12];
    const float* pb   = (const float*)d_in[13];
    float* out = (float*)d_out;

    prep<<<64, 256>>>(qw, w1, w2, pw, rpb);
    prep_const<<<1, 192>>>(n1b, qw, qb);
    k1<<<256, 256>>>(x, n1w, n1b, qb);
    k2i<<<3600, 256>>>();
    k2b<<<1984, 256>>>();
    k3<<<512, 256>>>(n2w, n2b, b1, b2, pb, out);
}

// round 7
// speedup vs baseline: 2.3408x; 1.0344x over previous
#include <cuda_runtime.h>
#include <math.h>

#define NPIX 16384
#define QSCALE 0.35355339059327373f
#define SLOT_STRIDE 260

__device__ __align__(16) float g_y[NPIX * 256];   // per pixel: q*s | k | v | raw x
__device__ __align__(16) float g_osum[NPIX * 64];
__device__ __align__(16) float g_const[192];      // qkv row for masked/OOB slots
__device__ float g_qwT[64 * 192];                 // [c][o]
__device__ float g_w1T[64 * 256];                 // [c][u]
__device__ float g_w2T[256 * 64];                 // [u][o]
__device__ float g_projT[64 * 64];                // [c][o]
__device__ float g_ebias[8 * 25 * 25];            // exp(bias) full (boundary path)
__device__ __align__(16) float g_eb12[8 * 25 * 12]; // exp(bias)[h][r][c<12] (interior)
__device__ float g_cb[8 * 25];                    // sum_{c>=12} exp(bias) (interior)

__device__ __forceinline__ float wsum(float v) {
#pragma unroll
    for (int o = 16; o; o >>= 1) v += __shfl_xor_sync(0xffffffffu, v, o);
    return v;
}

// ---- prep: transposed weights + exp(bias) tables ----
__global__ void prep(const float* __restrict__ qw, const float* __restrict__ w1,
                     const float* __restrict__ w2, const float* __restrict__ pw,
                     const float* __restrict__ rpb) {
    for (int i = blockIdx.x * blockDim.x + threadIdx.x; i < 56752; i += gridDim.x * blockDim.x) {
        if (i < 12288) { int c = i / 192, o = i % 192; g_qwT[i] = qw[o * 64 + c]; }
        else if (i < 28672) { int j = i - 12288; int c = j / 256, u = j % 256; g_w1T[j] = w1[u * 64 + c]; }
        else if (i < 45056) { int j = i - 28672; int u = j / 64, c = j % 64; g_w2T[j] = w2[c * 256 + u]; }
        else if (i < 49152) { int j = i - 45056; int c = j / 64, o = j % 64; g_projT[j] = pw[o * 64 + c]; }
        else if (i < 54152) {
            int j = i - 49152; int h = j / 625, r = j % 625; int qi = r / 25, kj = r % 25;
            int idx = (qi / 5 - kj / 5 + 4) * 9 + (qi % 5 - kj % 5 + 4);
            g_ebias[j] = __expf(rpb[idx * 8 + h]);
        } else if (i < 56552) {
            int j = i - 54152; int h = j / 300, rem = j % 300; int r = rem / 12, c = rem % 12;
            int idx = (r / 5 - c / 5 + 4) * 9 + (r % 5 - c % 5 + 4);
            g_eb12[j] = __expf(rpb[idx * 8 + h]);
        } else {
            int j = i - 56552; int h = j / 25, r = j % 25;
            float s = 0.f;
            for (int c = 12; c < 25; c++) {
                int idx = (r / 5 - c / 5 + 4) * 9 + (r % 5 - c % 5 + 4);
                s += __expf(rpb[idx * 8 + h]);
            }
            g_cb[j] = s;
        }
    }
}

__global__ void prep_const(const float* __restrict__ n1b, const float* __restrict__ qw,
                           const float* __restrict__ qb) {
    int o = threadIdx.x; if (o >= 192) return;
    float a = qb[o];
    for (int c = 0; c < 64; c++) a += n1b[c] * qw[o * 64 + c];
    if (o < 64) a *= QSCALE;
    g_const[o] = a;
}

// ---- k1: LN1 + QKV, register-tiled: block=64 pixels, warp=8 pixels ----
__global__ __launch_bounds__(256) void k1(const float* __restrict__ x,
                                          const float* __restrict__ n1w,
                                          const float* __restrict__ n1b,
                                          const float* __restrict__ qb) {
    __shared__ float sLn[64][65];
    int tid = threadIdx.x, lane = tid & 31, w = tid >> 5;
    int p0 = blockIdx.x * 64;
    float nw0 = n1w[lane], nw1 = n1w[lane + 32];
    float nb0 = n1b[lane], nb1 = n1b[lane + 32];
#pragma unroll
    for (int t = 0; t < 8; t++) {
        int wid = p0 + w * 8 + t;
        int b = wid >> 12, hw = wid & 4095;
        const float* xb = x + (size_t)b * 262144 + hw;
        float x0 = __ldg(xb + (size_t)lane * 4096);
        float x1 = __ldg(xb + (size_t)(lane + 32) * 4096);
        float m  = wsum(x0 + x1) * (1.f / 64.f);
        float vv = wsum(x0 * x0 + x1 * x1) * (1.f / 64.f) - m * m;
        float rs = rsqrtf(vv + 1e-5f);
        sLn[w * 8 + t][lane]      = (x0 - m) * rs * nw0 + nb0;
        sLn[w * 8 + t][lane + 32] = (x1 - m) * rs * nw1 + nb1;
        float* yp = g_y + (size_t)wid * 256;
        yp[192 + lane] = x0; yp[224 + lane] = x1;
    }
    __syncwarp();
    float acc[6][8];
#pragma unroll
    for (int k = 0; k < 6; k++)
#pragma unroll
        for (int j = 0; j < 8; j++) acc[k][j] = 0.f;
    for (int c = 0; c < 64; c++) {
        float wv[6];
        const float* wr = g_qwT + c * 192 + lane;
#pragma unroll
        for (int k = 0; k < 6; k++) wv[k] = wr[32 * k];
#pragma unroll
        for (int j = 0; j < 8; j++) {
            float l = sLn[w * 8 + j][c];
#pragma unroll
            for (int k = 0; k < 6; k++) acc[k][j] += wv[k] * l;
        }
    }
#pragma unroll
    for (int k = 0; k < 6; k++) {
        int o = lane + 32 * k;
        float bias = qb[o];
        float sc = (o < 64) ? QSCALE : 1.f;
#pragma unroll
        for (int j = 0; j < 8; j++)
            g_y[(size_t)(p0 + w * 8 + j) * 256 + o] = (acc[k][j] + bias) * sc;
    }
}

// ---- k2i: interior, 4-pixel horizontal strip per block ----
__global__ __launch_bounds__(256, 4) void k2i() {
    __shared__ float sQ[22 * SLOT_STRIDE];
    __shared__ float sED[4 * 1352];
    __shared__ float sInv[4 * 200];
    __shared__ float sW[4 * 104];
    __shared__ int   sSlot[4][13];

    int tid = threadIdx.x;
    int idx = blockIdx.x;
    int b = idx / 900, rem = idx - b * 900;
    int h0 = 2 + rem / 15, w0 = 2 + (rem % 15) * 4;
    int base = (b << 12) + (h0 << 6) + w0;

    if (tid < 52) {
        int j = tid / 13, ls = tid - j * 13;
        int g = (ls < 5) ? ls + j : (ls < 10) ? 8 + (ls - 5) + j : (ls < 12) ? 16 + (ls - 10) + j : 21;
        sSlot[j][ls] = g;
    }
    for (int i = tid; i < 22 * 64; i += 256) {
        int slot = i >> 6, jj = i & 63;
        float4 v;
        if (slot < 21) {
            int row, col;
            if (slot < 16) { row = slot >> 3; col = slot & 7; }
            else { row = 2; col = slot - 16; }
            int pp = base + (row - 2) * 64 + (col - 2);
            v = *(const float4*)(g_y + (size_t)pp * 256 + jj * 4);
        } else {
            v = (jj < 48) ? *(const float4*)(g_const + jj * 4) : make_float4(0.f, 0.f, 0.f, 0.f);
        }
        *(float4*)(sQ + slot * SLOT_STRIDE + jj * 4) = v;
    }
    __syncthreads();

    // dots: 416 tasks (pix, h, qi)
    for (int i = tid; i < 416; i += 256) {
        int pix = i / 104, t = i - pix * 104;
        int h = t / 13, qi = t - h * 13;
        int gq = sSlot[pix][qi];
        float4 qa = *(const float4*)(sQ + gq * SLOT_STRIDE + h * 8);
        float4 qd = *(const float4*)(sQ + gq * SLOT_STRIDE + h * 8 + 4);
        float* ed = sED + pix * 1352 + h * 169 + qi * 13;
#pragma unroll
        for (int ki = 0; ki < 13; ki++) {
            const float* kb = sQ + sSlot[pix][ki] * SLOT_STRIDE + 64 + h * 8;
            float4 ka = *(const float4*)kb;
            float4 kd = *(const float4*)(kb + 4);
            float dot = qa.x * ka.x + qa.y * ka.y + qa.z * ka.z + qa.w * ka.w
                      + qd.x * kd.x + qd.y * kd.y + qd.z * kd.z + qd.w * kd.w;
            ed[ki] = __expf(dot);
        }
    }
    __syncthreads();

    // pass1: 800 tasks (pix, h, r) — bias rows via vectorized __ldg (L1-resident)
    for (int i = tid; i < 800; i += 256) {
        int pix = i / 200, t = i - pix * 200;
        int h = t / 25, r = t - h * 25;
        int qi = (r < 12) ? r : 12;
        const float* ed = sED + pix * 1352 + h * 169 + qi * 13;
        const float* eb = g_eb12 + h * 300 + r * 12;
        float4 e0 = __ldg((const float4*)eb);
        float4 e1 = __ldg((const float4*)(eb + 4));
        float4 e2 = __ldg((const float4*)(eb + 8));
        float den = __ldg(g_cb + h * 25 + r) * ed[12];
        den += e0.x * ed[0] + e0.y * ed[1] + e0.z * ed[2] + e0.w * ed[3];
        den += e1.x * ed[4] + e1.y * ed[5] + e1.z * ed[6] + e1.w * ed[7];
        den += e2.x * ed[8] + e2.y * ed[9] + e2.z * ed[10] + e2.w * ed[11];
        sInv[pix * 200 + t] = 1.f / den;
    }
    __syncthreads();

    // pass2: 416 tasks (pix, h, c) — strided bias reads via __ldg (coalesce across lanes)
    for (int i = tid; i < 416; i += 256) {
        int pix = i / 104, t = i - pix * 104;
        int h = t / 13, c = t - h * 13;
        const float* ed = sED + pix * 1352 + h * 169;
        const float* iv = sInv + pix * 200 + h * 25;
        float w = 0.f, tt = 0.f;
        if (c < 12) {
            const float* eb = g_eb12 + h * 300 + c;
#pragma unroll
            for (int r = 0; r < 12; r++) w += iv[r] * ed[r * 13 + c] * __ldg(eb + r * 12);
#pragma unroll
            for (int r = 12; r < 25; r++) tt += iv[r] * __ldg(eb + r * 12);
            w += ed[156 + c] * tt;
        } else {
            const float* cb = g_cb + h * 25;
#pragma unroll
            for (int r = 0; r < 12; r++) w += iv[r] * ed[r * 13 + 12] * __ldg(cb + r);
#pragma unroll
            for (int r = 12; r < 25; r++) tt += iv[r] * __ldg(cb + r);
            w += ed[168] * tt;
        }
        sW[pix * 104 + t] = w;
    }
    __syncthreads();

    // pass3: 256 tasks (pix, ch)
    {
        int pix = tid >> 6, ch = tid & 63, h = ch >> 3;
        const float* w = sW + pix * 104 + h * 13;
        const int* sm = sSlot[pix];
        float acc = 0.f;
#pragma unroll
        for (int c = 0; c < 13; c++) acc += w[c] * sQ[sm[c] * SLOT_STRIDE + 128 + ch];
#pragma unroll
        for (int s = 0; s < 12; s++) acc += sQ[sm[s] * SLOT_STRIDE + 192 + ch];
        g_osum[(size_t)(base + pix) * 64 + ch] = acc;
    }
}

// ---- k2b: boundary pixels (generic masked path) ----
__global__ __launch_bounds__(256) void k2b() {
    __shared__ float sQ[13 * SLOT_STRIDE];
    __shared__ float sEB[5000];
    __shared__ float sED[8 * 169];
    __shared__ float sInv[200], sCB[200];
    __shared__ float sW[104];
    __shared__ int   sMap[25];
    __shared__ int   sOff[13];

    int tid = threadIdx.x;
    int t = blockIdx.x;
    int b = t / 496, u = t - b * 496;
    int h0, w0;
    if (u < 128)      { h0 = u >> 6; w0 = u & 63; }
    else if (u < 256) { int v = u - 128; h0 = 62 + (v >> 6); w0 = v & 63; }
    else              { int v = u - 256; h0 = 2 + v / 4; int c = v & 3; w0 = (c < 2) ? c : (60 + c); }
    int p = (b << 12) + (h0 << 6) + w0;

    for (int i = tid; i < 5000; i += 256) sEB[i] = g_ebias[i];
    if (tid < 25) {
        int ri = tid / 5 - 2, ci = tid % 5 - 2;
        int nh = h0 + ri, nw = w0 + ci;
        int ok = (tid < 12) && nh >= 0 && nh < 64 && nw >= 0 && nw < 64;
        sMap[tid] = ok ? tid : 12;
        if (tid < 13) sOff[tid] = -1;
        if (ok) sOff[tid] = ((b << 12) + (nh << 6) + nw) * 256;
    }
    __syncthreads();

    for (int i = tid; i < 13 * 64; i += 256) {
        int slot = i >> 6, j = i & 63;
        int off = sOff[slot];
        float4 v;
        if (off >= 0)    v = *(const float4*)(g_y + off + j * 4);
        else if (j < 48) v = *(const float4*)(g_const + j * 4);
        else             v = make_float4(0.f, 0.f, 0.f, 0.f);
        *(float4*)(sQ + slot * SLOT_STRIDE + j * 4) = v;
    }
    __syncthreads();

    if (tid < 104) {
        int h = tid / 13, qi = tid % 13;
        float4 qa = *(const float4*)(sQ + qi * SLOT_STRIDE + h * 8);
        float4 qd = *(const float4*)(sQ + qi * SLOT_STRIDE + h * 8 + 4);
        float* ed = sED + h * 169 + qi * 13;
#pragma unroll
        for (int ki = 0; ki < 13; ki++) {
            const float* kb = sQ + ki * SLOT_STRIDE + 64 + h * 8;
            float4 ka = *(const float4*)kb;
            float4 kd = *(const float4*)(kb + 4);
            float dot = qa.x * ka.x + qa.y * ka.y + qa.z * ka.z + qa.w * ka.w
                      + qd.x * kd.x + qd.y * kd.y + qd.z * kd.z + qd.w * kd.w;
            ed[ki] = __expf(dot);
        }
    }
    __syncthreads();

    if (tid < 200) {
        int h = tid / 25, r = tid % 25;
        int qi = sMap[r];
        const float* eb = sEB + h * 625 + r * 25;
        const float* ed = sED + h * 169 + qi * 13;
        float den = 0.f, cb = 0.f;
#pragma unroll
        for (int col = 0; col < 25; col++) {
            int ki = sMap[col];
            float e = eb[col];
            den += e * ed[ki];
            if (ki == 12) cb += e;
        }
        sInv[tid] = 1.f / den;
        sCB[tid] = cb;
    }
    __syncthreads();

    if (tid < 104) {
        int h = tid / 13, c = tid % 13;
        const float* ed = sED + h * 169;
        const float* iv = sInv + h * 25;
        float w = 0.f;
        if (c == 12) {
            const float* cb = sCB + h * 25;
#pragma unroll
            for (int r = 0; r < 25; r++) w += iv[r] * ed[sMap[r] * 13 + 12] * cb[r];
        } else if (sMap[c] == c) {
            const float* eb = sEB + h * 625 + c;
#pragma unroll
            for (int r = 0; r < 25; r++) w += iv[r] * ed[sMap[r] * 13 + c] * eb[r * 25];
        }
        sW[tid] = w;
    }
    __syncthreads();

    if (tid < 64) {
        int h = tid >> 3;
        const float* w = sW + h * 13;
        float acc = 0.f;
#pragma unroll
        for (int c = 0; c < 13; c++) acc += w[c] * sQ[c * SLOT_STRIDE + 128 + tid];
#pragma unroll
        for (int s = 0; s < 12; s++) acc += sQ[s * SLOT_STRIDE + 192 + tid];
        g_osum[(size_t)p * 64 + tid] = acc;
    }
}

// ---- k3: LN2 + MLP + proj, register-tiled: block=32 pixels, warp=4 pixels ----
__global__ __launch_bounds__(256) void k3(const float* __restrict__ n2w, const float* __restrict__ n2b,
                                          const float* __restrict__ b1, const float* __restrict__ b2,
                                          const float* __restrict__ pb, float* __restrict__ out) {
    __shared__ float sLn[32][68];     // reused as sY
    __shared__ float sH[32][260];
    int tid = threadIdx.x, lane = tid & 31, w = tid >> 5;
    int p0 = blockIdx.x * 32;

    float nw0 = n2w[lane], nw1 = n2w[lane + 32];
    float nb0 = n2b[lane], nb1 = n2b[lane + 32];
#pragma unroll
    for (int t = 0; t < 4; t++) {
        const float* os = g_osum + (size_t)(p0 + w * 4 + t) * 64;
        float x0 = os[lane], x1 = os[lane + 32];
        float m  = wsum(x0 + x1) * (1.f / 64.f);
        float vv = wsum(x0 * x0 + x1 * x1) * (1.f / 64.f) - m * m;
        float rs = rsqrtf(vv + 1e-5f);
        sLn[w * 4 + t][lane]      = (x0 - m) * rs * nw0 + nb0;
        sLn[w * 4 + t][lane + 32] = (x1 - m) * rs * nw1 + nb1;
    }
    __syncwarp();

    // fc1: thread = 8 outputs x 4 pixels
    float acc[8][4];
#pragma unroll
    for (int k = 0; k < 8; k++)
#pragma unroll
        for (int j = 0; j < 4; j++) acc[k][j] = 0.f;
    for (int c = 0; c < 64; c++) {
        float wv[8];
        const float* wr = g_w1T + c * 256 + lane;
#pragma unroll
        for (int k = 0; k < 8; k++) wv[k] = wr[32 * k];
#pragma unroll
        for (int j = 0; j < 4; j++) {
            float l = sLn[w * 4 + j][c];
#pragma unroll
            for (int k = 0; k < 8; k++) acc[k][j] += wv[k] * l;
        }
    }
#pragma unroll
    for (int k = 0; k < 8; k++) {
        float bb = b1[lane + 32 * k];
#pragma unroll
        for (int j = 0; j < 4; j++) {
            float v = acc[k][j] + bb;
            sH[w * 4 + j][lane + 32 * k] = 0.5f * v * (1.f + erff(v * 0.70710678118f));
        }
    }
    __syncwarp();

    // fc2 + residual: thread = 2 outputs x 4 pixels
    float a2[2][4];
#pragma unroll
    for (int k = 0; k < 2; k++)
#pragma unroll
        for (int j = 0; j < 4; j++) a2[k][j] = 0.f;
    for (int c0 = 0; c0 < 256; c0 += 4) {
        float4 h4[4];
#pragma unroll
        for (int j = 0; j < 4; j++) h4[j] = *(const float4*)&sH[w * 4 + j][c0];
#pragma unroll
        for (int d = 0; d < 4; d++) {
            const float* wr = g_w2T + (c0 + d) * 64;
            float w0v = wr[lane], w1v = wr[lane + 32];
#pragma unroll
            for (int j = 0; j < 4; j++) {
                float hv = (d == 0) ? h4[j].x : (d == 1) ? h4[j].y : (d == 2) ? h4[j].z : h4[j].w;
                a2[0][j] += w0v * hv; a2[1][j] += w1v * hv;
            }
        }
    }
    float bb0 = b2[lane], bb1 = b2[lane + 32];
#pragma unroll
    for (int j = 0; j < 4; j++) {
        const float* os = g_osum + (size_t)(p0 + w * 4 + j) * 64;
        sLn[w * 4 + j][lane]      = a2[0][j] + bb0 + os[lane];
        sLn[w * 4 + j][lane + 32] = a2[1][j] + bb1 + os[lane + 32];
    }
    __syncwarp();

    // proj: thread = 2 outputs x 4 pixels
    float a3[2][4];
#pragma unroll
    for (int k = 0; k < 2; k++)
#pragma unroll
        for (int j = 0; j < 4; j++) a3[k][j] = 0.f;
    for (int c0 = 0; c0 < 64; c0 += 4) {
        float4 y4[4];
#pragma unroll
        for (int j = 0; j < 4; j++) y4[j] = *(const float4*)&sLn[w * 4 + j][c0];
#pragma unroll
        for (int d = 0; d < 4; d++) {
            const float* wr = g_projT + (c0 + d) * 64;
            float w0v = wr[lane], w1v = wr[lane + 32];
#pragma unroll
            for (int j = 0; j < 4; j++) {
                float yv = (d == 0) ? y4[j].x : (d == 1) ? y4[j].y : (d == 2) ? y4[j].z : y4[j].w;
                a3[0][j] += w0v * yv; a3[1][j] += w1v * yv;
            }
        }
    }
    float pb0 = pb[lane], pb1 = pb[lane + 32];
#pragma unroll
    for (int j = 0; j < 4; j++) {
        int wid = p0 + w * 4 + j;
        int b = wid >> 12, hw = wid & 4095;
        float* ob = out + (size_t)b * 262144 + hw;
        ob[(size_t)lane * 4096]        = a3[0][j] + pb0;
        ob[(size_t)(lane + 32) * 4096] = a3[1][j] + pb1;
    }
}

extern "C" void kernel_launch(void* const* d_in, const int* in_sizes, int n_in,
                              void* d_out, int out_size) {
    const float* x    = (const float*)d_in[0];
    const float* n1w  = (const float*)d_in[1];
    const float* n1b  = (const float*)d_in[2];
    const float* qw   = (const float*)d_in[3];
    const float* qb   = (const float*)d_in[4];
    const float* rpb  = (const float*)d_in[5];
    const float* n2w  = (const float*)d_in[6];
    const float* n2b  = (const float*)d_in[7];
    const float* w1   = (const float*)d_in[8];
    const float* b1   = (const float*)d_in[9];
    const float* w2   = (const float*)d_in[10];
    const float* b2   = (const float*)d_in[11];
    const float* pw   = (const float*)d_in[12];
    const float* pb   = (const float*)d_in[13];
    float* out = (float*)d_out;

    prep<<<64, 256>>>(qw, w1, w2, pw, rpb);
    prep_const<<<1, 192>>>(n1b, qw, qb);
    k1<<<256, 256>>>(x, n1w, n1b, qb);
    k2i<<<3600, 256>>>();
    k2b<<<1984, 256>>>();
    k3<<<512, 256>>>(n2w, n2b, b1, b2, pb, out);
}

// round 8
// speedup vs baseline: 2.3583x; 1.0075x over previous
#include <cuda_runtime.h>
#include <math.h>

#define NPIX 16384
#define QSCALE 0.35355339059327373f
#define SLOT_STRIDE 260

__device__ __align__(16) float g_y[NPIX * 256];   // per pixel: q*s | k | v | raw x
__device__ __align__(16) float g_osum[NPIX * 64];
__device__ __align__(16) float g_const[192];      // qkv row for masked/OOB slots
__device__ float g_qwT[64 * 192];                 // [c][o]
__device__ float g_w1T[64 * 256];                 // [c][u]
__device__ float g_w2T[256 * 64];                 // [u][o]
__device__ float g_projT[64 * 64];                // [c][o]
__device__ float g_ebias[8 * 25 * 25];            // exp(bias) full (boundary path)
__device__ __align__(16) float g_eb12[8 * 25 * 12]; // exp(bias)[h][r][c<12] (interior)
__device__ float g_cb[8 * 25];                    // sum_{c>=12} exp(bias) (interior)

__device__ __forceinline__ float wsum(float v) {
#pragma unroll
    for (int o = 16; o; o >>= 1) v += __shfl_xor_sync(0xffffffffu, v, o);
    return v;
}

// ---- prep: transposed weights + exp(bias) tables ----
__global__ void prep(const float* __restrict__ qw, const float* __restrict__ w1,
                     const float* __restrict__ w2, const float* __restrict__ pw,
                     const float* __restrict__ rpb) {
    for (int i = blockIdx.x * blockDim.x + threadIdx.x; i < 56752; i += gridDim.x * blockDim.x) {
        if (i < 12288) { int c = i / 192, o = i % 192; g_qwT[i] = qw[o * 64 + c]; }
        else if (i < 28672) { int j = i - 12288; int c = j / 256, u = j % 256; g_w1T[j] = w1[u * 64 + c]; }
        else if (i < 45056) { int j = i - 28672; int u = j / 64, c = j % 64; g_w2T[j] = w2[c * 256 + u]; }
        else if (i < 49152) { int j = i - 45056; int c = j / 64, o = j % 64; g_projT[j] = pw[o * 64 + c]; }
        else if (i < 54152) {
            int j = i - 49152; int h = j / 625, r = j % 625; int qi = r / 25, kj = r % 25;
            int idx = (qi / 5 - kj / 5 + 4) * 9 + (qi % 5 - kj % 5 + 4);
            g_ebias[j] = __expf(rpb[idx * 8 + h]);
        } else if (i < 56552) {
            int j = i - 54152; int h = j / 300, rem = j % 300; int r = rem / 12, c = rem % 12;
            int idx = (r / 5 - c / 5 + 4) * 9 + (r % 5 - c % 5 + 4);
            g_eb12[j] = __expf(rpb[idx * 8 + h]);
        } else {
            int j = i - 56552; int h = j / 25, r = j % 25;
            float s = 0.f;
            for (int c = 12; c < 25; c++) {
                int idx = (r / 5 - c / 5 + 4) * 9 + (r % 5 - c % 5 + 4);
                s += __expf(rpb[idx * 8 + h]);
            }
            g_cb[j] = s;
        }
    }
}

__global__ void prep_const(const float* __restrict__ n1b, const float* __restrict__ qw,
                           const float* __restrict__ qb) {
    int o = threadIdx.x; if (o >= 192) return;
    float a = qb[o];
    for (int c = 0; c < 64; c++) a += n1b[c] * qw[o * 64 + c];
    if (o < 64) a *= QSCALE;
    g_const[o] = a;
}

// ---- k1: LN1 + QKV, register-tiled: block=64 pixels, warp=8 pixels ----
__global__ __launch_bounds__(256) void k1(const float* __restrict__ x,
                                          const float* __restrict__ n1w,
                                          const float* __restrict__ n1b,
                                          const float* __restrict__ qb) {
    __shared__ float sLn[64][65];
    int tid = threadIdx.x, lane = tid & 31, w = tid >> 5;
    int p0 = blockIdx.x * 64;
    float nw0 = n1w[lane], nw1 = n1w[lane + 32];
    float nb0 = n1b[lane], nb1 = n1b[lane + 32];
#pragma unroll
    for (int t = 0; t < 8; t++) {
        int wid = p0 + w * 8 + t;
        int b = wid >> 12, hw = wid & 4095;
        const float* xb = x + (size_t)b * 262144 + hw;
        float x0 = __ldg(xb + (size_t)lane * 4096);
        float x1 = __ldg(xb + (size_t)(lane + 32) * 4096);
        float m  = wsum(x0 + x1) * (1.f / 64.f);
        float vv = wsum(x0 * x0 + x1 * x1) * (1.f / 64.f) - m * m;
        float rs = rsqrtf(vv + 1e-5f);
        sLn[w * 8 + t][lane]      = (x0 - m) * rs * nw0 + nb0;
        sLn[w * 8 + t][lane + 32] = (x1 - m) * rs * nw1 + nb1;
        float* yp = g_y + (size_t)wid * 256;
        yp[192 + lane] = x0; yp[224 + lane] = x1;
    }
    __syncwarp();
    float acc[6][8];
#pragma unroll
    for (int k = 0; k < 6; k++)
#pragma unroll
        for (int j = 0; j < 8; j++) acc[k][j] = 0.f;
    for (int c = 0; c < 64; c++) {
        float wv[6];
        const float* wr = g_qwT + c * 192 + lane;
#pragma unroll
        for (int k = 0; k < 6; k++) wv[k] = wr[32 * k];
#pragma unroll
        for (int j = 0; j < 8; j++) {
            float l = sLn[w * 8 + j][c];
#pragma unroll
            for (int k = 0; k < 6; k++) acc[k][j] += wv[k] * l;
        }
    }
#pragma unroll
    for (int k = 0; k < 6; k++) {
        int o = lane + 32 * k;
        float bias = qb[o];
        float sc = (o < 64) ? QSCALE : 1.f;
#pragma unroll
        for (int j = 0; j < 8; j++)
            g_y[(size_t)(p0 + w * 8 + j) * 256 + o] = (acc[k][j] + bias) * sc;
    }
}

// ---- k2i: interior, 4-pixel horizontal strip per block ----
__global__ __launch_bounds__(256, 4) void k2i() {
    __shared__ float sQ[22 * SLOT_STRIDE];
    __shared__ float sED[4 * 1352];
    __shared__ float sInv[4 * 200];
    __shared__ float sW[4 * 104];
    __shared__ int   sSlot[4][13];

    int tid = threadIdx.x;
    int idx = blockIdx.x;
    int b = idx / 900, rem = idx - b * 900;
    int h0 = 2 + rem / 15, w0 = 2 + (rem % 15) * 4;
    int base = (b << 12) + (h0 << 6) + w0;

    if (tid < 52) {
        int j = tid / 13, ls = tid - j * 13;
        int g = (ls < 5) ? ls + j : (ls < 10) ? 8 + (ls - 5) + j : (ls < 12) ? 16 + (ls - 10) + j : 21;
        sSlot[j][ls] = g;
    }
    for (int i = tid; i < 22 * 64; i += 256) {
        int slot = i >> 6, jj = i & 63;
        float4 v;
        if (slot < 21) {
            int row, col;
            if (slot < 16) { row = slot >> 3; col = slot & 7; }
            else { row = 2; col = slot - 16; }
            int pp = base + (row - 2) * 64 + (col - 2);
            v = *(const float4*)(g_y + (size_t)pp * 256 + jj * 4);
        } else {
            v = (jj < 48) ? *(const float4*)(g_const + jj * 4) : make_float4(0.f, 0.f, 0.f, 0.f);
        }
        *(float4*)(sQ + slot * SLOT_STRIDE + jj * 4) = v;
    }
    __syncthreads();

    // dots: warp-broadcast scheme. Each half-warp group owns one (pix,h) pair per
    // iteration; lane qi keeps its q-row in registers, k-vectors are broadcast LDS.
    {
        int w = tid >> 5, lane = tid & 31;
        int grp = lane >> 4, qi = lane & 15;
        bool act = qi < 13;
#pragma unroll
        for (int it = 0; it < 2; it++) {
            int pairidx = w * 4 + it * 2 + grp;     // 0..31: pix = idx>>3, h = idx&7
            int pix = pairidx >> 3, h = pairidx & 7;
            const int* sm = sSlot[pix];
            float4 qa = make_float4(0.f, 0.f, 0.f, 0.f), qd = qa;
            if (act) {
                int gq = sm[qi];
                qa = *(const float4*)(sQ + gq * SLOT_STRIDE + h * 8);
                qd = *(const float4*)(sQ + gq * SLOT_STRIDE + h * 8 + 4);
            }
            float* ed = sED + pix * 1352 + h * 169 + qi * 13;
#pragma unroll
            for (int ki = 0; ki < 13; ki++) {
                const float* kb = sQ + sm[ki] * SLOT_STRIDE + 64 + h * 8;  // same addr per group -> broadcast
                float4 ka = *(const float4*)kb;
                float4 kd = *(const float4*)(kb + 4);
                float dot = qa.x * ka.x + qa.y * ka.y + qa.z * ka.z + qa.w * ka.w
                          + qd.x * kd.x + qd.y * kd.y + qd.z * kd.z + qd.w * kd.w;
                if (act) ed[ki] = __expf(dot);
            }
        }
    }
    __syncthreads();

    // pass1: 800 tasks (pix, h, r) — bias rows via vectorized __ldg (L1-resident)
    for (int i = tid; i < 800; i += 256) {
        int pix = i / 200, t = i - pix * 200;
        int h = t / 25, r = t - h * 25;
        int qi = (r < 12) ? r : 12;
        const float* ed = sED + pix * 1352 + h * 169 + qi * 13;
        const float* eb = g_eb12 + h * 300 + r * 12;
        float4 e0 = __ldg((const float4*)eb);
        float4 e1 = __ldg((const float4*)(eb + 4));
        float4 e2 = __ldg((const float4*)(eb + 8));
        float den = __ldg(g_cb + h * 25 + r) * ed[12];
        den += e0.x * ed[0] + e0.y * ed[1] + e0.z * ed[2] + e0.w * ed[3];
        den += e1.x * ed[4] + e1.y * ed[5] + e1.z * ed[6] + e1.w * ed[7];
        den += e2.x * ed[8] + e2.y * ed[9] + e2.z * ed[10] + e2.w * ed[11];
        sInv[pix * 200 + t] = 1.f / den;
    }
    __syncthreads();

    // pass2: 416 tasks (pix, h, c) — strided bias reads via __ldg (coalesce across lanes)
    for (int i = tid; i < 416; i += 256) {
        int pix = i / 104, t = i - pix * 104;
        int h = t / 13, c = t - h * 13;
        const float* ed = sED + pix * 1352 + h * 169;
        const float* iv = sInv + pix * 200 + h * 25;
        float w = 0.f, tt = 0.f;
        if (c < 12) {
            const float* eb = g_eb12 + h * 300 + c;
#pragma unroll
            for (int r = 0; r < 12; r++) w += iv[r] * ed[r * 13 + c] * __ldg(eb + r * 12);
#pragma unroll
            for (int r = 12; r < 25; r++) tt += iv[r] * __ldg(eb + r * 12);
            w += ed[156 + c] * tt;
        } else {
            const float* cb = g_cb + h * 25;
#pragma unroll
            for (int r = 0; r < 12; r++) w += iv[r] * ed[r * 13 + 12] * __ldg(cb + r);
#pragma unroll
            for (int r = 12; r < 25; r++) tt += iv[r] * __ldg(cb + r);
            w += ed[168] * tt;
        }
        sW[pix * 104 + t] = w;
    }
    __syncthreads();

    // pass3: 256 tasks (pix, ch)
    {
        int pix = tid >> 6, ch = tid & 63, h = ch >> 3;
        const float* w = sW + pix * 104 + h * 13;
        const int* sm = sSlot[pix];
        float acc = 0.f;
#pragma unroll
        for (int c = 0; c < 13; c++) acc += w[c] * sQ[sm[c] * SLOT_STRIDE + 128 + ch];
#pragma unroll
        for (int s = 0; s < 12; s++) acc += sQ[sm[s] * SLOT_STRIDE + 192 + ch];
        g_osum[(size_t)(base + pix) * 64 + ch] = acc;
    }
}

// ---- k2b: boundary pixels (generic masked path) ----
__global__ __launch_bounds__(256) void k2b() {
    __shared__ float sQ[13 * SLOT_STRIDE];
    __shared__ float sEB[5000];
    __shared__ float sED[8 * 169];
    __shared__ float sInv[200], sCB[200];
    __shared__ float sW[104];
    __shared__ int   sMap[25];
    __shared__ int   sOff[13];

    int tid = threadIdx.x;
    int t = blockIdx.x;
    int b = t / 496, u = t - b * 496;
    int h0, w0;
    if (u < 128)      { h0 = u >> 6; w0 = u & 63; }
    else if (u < 256) { int v = u - 128; h0 = 62 + (v >> 6); w0 = v & 63; }
    else              { int v = u - 256; h0 = 2 + v / 4; int c = v & 3; w0 = (c < 2) ? c : (60 + c); }
    int p = (b << 12) + (h0 << 6) + w0;

    for (int i = tid; i < 5000; i += 256) sEB[i] = g_ebias[i];
    if (tid < 25) {
        int ri = tid / 5 - 2, ci = tid % 5 - 2;
        int nh = h0 + ri, nw = w0 + ci;
        int ok = (tid < 12) && nh >= 0 && nh < 64 && nw >= 0 && nw < 64;
        sMap[tid] = ok ? tid : 12;
        if (tid < 13) sOff[tid] = -1;
        if (ok) sOff[tid] = ((b << 12) + (nh << 6) + nw) * 256;
    }
    __syncthreads();

    for (int i = tid; i < 13 * 64; i += 256) {
        int slot = i >> 6, j = i & 63;
        int off = sOff[slot];
        float4 v;
        if (off >= 0)    v = *(const float4*)(g_y + off + j * 4);
        else if (j < 48) v = *(const float4*)(g_const + j * 4);
        else             v = make_float4(0.f, 0.f, 0.f, 0.f);
        *(float4*)(sQ + slot * SLOT_STRIDE + j * 4) = v;
    }
    __syncthreads();

    if (tid < 104) {
        int h = tid / 13, qi = tid % 13;
        float4 qa = *(const float4*)(sQ + qi * SLOT_STRIDE + h * 8);
        float4 qd = *(const float4*)(sQ + qi * SLOT_STRIDE + h * 8 + 4);
        float* ed = sED + h * 169 + qi * 13;
#pragma unroll
        for (int ki = 0; ki < 13; ki++) {
            const float* kb = sQ + ki * SLOT_STRIDE + 64 + h * 8;
            float4 ka = *(const float4*)kb;
            float4 kd = *(const float4*)(kb + 4);
            float dot = qa.x * ka.x + qa.y * ka.y + qa.z * ka.z + qa.w * ka.w
                      + qd.x * kd.x + qd.y * kd.y + qd.z * kd.z + qd.w * kd.w;
            ed[ki] = __expf(dot);
        }
    }
    __syncthreads();

    if (tid < 200) {
        int h = tid / 25, r = tid % 25;
        int qi = sMap[r];
        const float* eb = sEB + h * 625 + r * 25;
        const float* ed = sED + h * 169 + qi * 13;
        float den = 0.f, cb = 0.f;
#pragma unroll
        for (int col = 0; col < 25; col++) {
            int ki = sMap[col];
            float e = eb[col];
            den += e * ed[ki];
            if (ki == 12) cb += e;
        }
        sInv[tid] = 1.f / den;
        sCB[tid] = cb;
    }
    __syncthreads();

    if (tid < 104) {
        int h = tid / 13, c = tid % 13;
        const float* ed = sED + h * 169;
        const float* iv = sInv + h * 25;
        float w = 0.f;
        if (c == 12) {
            const float* cb = sCB + h * 25;
#pragma unroll
            for (int r = 0; r < 25; r++) w += iv[r] * ed[sMap[r] * 13 + 12] * cb[r];
        } else if (sMap[c] == c) {
            const float* eb = sEB + h * 625 + c;
#pragma unroll
            for (int r = 0; r < 25; r++) w += iv[r] * ed[sMap[r] * 13 + c] * eb[r * 25];
        }
        sW[tid] = w;
    }
    __syncthreads();

    if (tid < 64) {
        int h = tid >> 3;
        const float* w = sW + h * 13;
        float acc = 0.f;
#pragma unroll
        for (int c = 0; c < 13; c++) acc += w[c] * sQ[c * SLOT_STRIDE + 128 + tid];
#pragma unroll
        for (int s = 0; s < 12; s++) acc += sQ[s * SLOT_STRIDE + 192 + tid];
        g_osum[(size_t)p * 64 + tid] = acc;
    }
}

// ---- k3: LN2 + MLP + proj, register-tiled: block=32 pixels, warp=4 pixels ----
__global__ __launch_bounds__(256) void k3(const float* __restrict__ n2w, const float* __restrict__ n2b,
                                          const float* __restrict__ b1, const float* __restrict__ b2,
                                          const float* __restrict__ pb, float* __restrict__ out) {
    __shared__ float sLn[32][68];     // reused as sY
    __shared__ float sH[32][260];
    int tid = threadIdx.x, lane = tid & 31, w = tid >> 5;
    int p0 = blockIdx.x * 32;

    float nw0 = n2w[lane], nw1 = n2w[lane + 32];
    float nb0 = n2b[lane], nb1 = n2b[lane + 32];
#pragma unroll
    for (int t = 0; t < 4; t++) {
        const float* os = g_osum + (size_t)(p0 + w * 4 + t) * 64;
        float x0 = os[lane], x1 = os[lane + 32];
        float m  = wsum(x0 + x1) * (1.f / 64.f);
        float vv = wsum(x0 * x0 + x1 * x1) * (1.f / 64.f) - m * m;
        float rs = rsqrtf(vv + 1e-5f);
        sLn[w * 4 + t][lane]      = (x0 - m) * rs * nw0 + nb0;
        sLn[w * 4 + t][lane + 32] = (x1 - m) * rs * nw1 + nb1;
    }
    __syncwarp();

    // fc1: thread = 8 outputs x 4 pixels
    float acc[8][4];
#pragma unroll
    for (int k = 0; k < 8; k++)
#pragma unroll
        for (int j = 0; j < 4; j++) acc[k][j] = 0.f;
    for (int c = 0; c < 64; c++) {
        float wv[8];
        const float* wr = g_w1T + c * 256 + lane;
#pragma unroll
        for (int k = 0; k < 8; k++) wv[k] = wr[32 * k];
#pragma unroll
        for (int j = 0; j < 4; j++) {
            float l = sLn[w * 4 + j][c];
#pragma unroll
            for (int k = 0; k < 8; k++) acc[k][j] += wv[k] * l;
        }
    }
#pragma unroll
    for (int k = 0; k < 8; k++) {
        float bb = b1[lane + 32 * k];
#pragma unroll
        for (int j = 0; j < 4; j++) {
            float v = acc[k][j] + bb;
            sH[w * 4 + j][lane + 32 * k] = 0.5f * v * (1.f + erff(v * 0.70710678118f));
        }
    }
    __syncwarp();

    // fc2 + residual: thread = 2 outputs x 4 pixels
    float a2[2][4];
#pragma unroll
    for (int k = 0; k < 2; k++)
#pragma unroll
        for (int j = 0; j < 4; j++) a2[k][j] = 0.f;
    for (int c0 = 0; c0 < 256; c0 += 4) {
        float4 h4[4];
#pragma unroll
        for (int j = 0; j < 4; j++) h4[j] = *(const float4*)&sH[w * 4 + j][c0];
#pragma unroll
        for (int d = 0; d < 4; d++) {
            const float* wr = g_w2T + (c0 + d) * 64;
            float w0v = wr[lane], w1v = wr[lane + 32];
#pragma unroll
            for (int j = 0; j < 4; j++) {
                float hv = (d == 0) ? h4[j].x : (d == 1) ? h4[j].y : (d == 2) ? h4[j].z : h4[j].w;
                a2[0][j] += w0v * hv; a2[1][j] += w1v * hv;
            }
        }
    }
    float bb0 = b2[lane], bb1 = b2[lane + 32];
#pragma unroll
    for (int j = 0; j < 4; j++) {
        const float* os = g_osum + (size_t)(p0 + w * 4 + j) * 64;
        sLn[w * 4 + j][lane]      = a2[0][j] + bb0 + os[lane];
        sLn[w * 4 + j][lane + 32] = a2[1][j] + bb1 + os[lane + 32];
    }
    __syncwarp();

    // proj: thread = 2 outputs x 4 pixels
    float a3[2][4];
#pragma unroll
    for (int k = 0; k < 2; k++)
#pragma unroll
        for (int j = 0; j < 4; j++) a3[k][j] = 0.f;
    for (int c0 = 0; c0 < 64; c0 += 4) {
        float4 y4[4];
#pragma unroll
        for (int j = 0; j < 4; j++) y4[j] = *(const float4*)&sLn[w * 4 + j][c0];
#pragma unroll
        for (int d = 0; d < 4; d++) {
            const float* wr = g_projT + (c0 + d) * 64;
            float w0v = wr[lane], w1v = wr[lane + 32];
#pragma unroll
            for (int j = 0; j < 4; j++) {
                float yv = (d == 0) ? y4[j].x : (d == 1) ? y4[j].y : (d == 2) ? y4[j].z : y4[j].w;
                a3[0][j] += w0v * yv; a3[1][j] += w1v * yv;
            }
        }
    }
    float pb0 = pb[lane], pb1 = pb[lane + 32];
#pragma unroll
    for (int j = 0; j < 4; j++) {
        int wid = p0 + w * 4 + j;
        int b = wid >> 12, hw = wid & 4095;
        float* ob = out + (size_t)b * 262144 + hw;
        ob[(size_t)lane * 4096]        = a3[0][j] + pb0;
        ob[(size_t)(lane + 32) * 4096] = a3[1][j] + pb1;
    }
}

extern "C" void kernel_launch(void* const* d_in, const int* in_sizes, int n_in,
                              void* d_out, int out_size) {
    const float* x    = (const float*)d_in[0];
    const float* n1w  = (const float*)d_in[1];
    const float* n1b  = (const float*)d_in[2];
    const float* qw   = (const float*)d_in[3];
    const float* qb   = (const float*)d_in[4];
    const float* rpb  = (const float*)d_in[5];
    const float* n2w  = (const float*)d_in[6];
    const float* n2b  = (const float*)d_in[7];
    const float* w1   = (const float*)d_in[8];
    const float* b1   = (const float*)d_in[9];
    const float* w2   = (const float*)d_in[10];
    const float* b2   = (const float*)d_in[11];
    const float* pw   = (const float*)d_in[12];
    const float* pb   = (const float*)d_in[13];
    float* out = (float*)d_out;

    prep<<<64, 256>>>(qw, w1, w2, pw, rpb);
    prep_const<<<1, 192>>>(n1b, qw, qb);
    k1<<<256, 256>>>(x, n1w, n1b, qb);
    k2i<<<3600, 256>>>();
    k2b<<<1984, 256>>>();
    k3<<<512, 256>>>(n2w, n2b, b1, b2, pb, out);
}

// round 9
// speedup vs baseline: 2.4779x; 1.0507x over previous
#include <cuda_runtime.h>
#include <math.h>

#define NPIX 16384
#define QSCALE 0.35355339059327373f
#define SLOT_STRIDE 260
#define NBI 3600   // interior blocks
#define NBB 1984   // boundary blocks

__device__ __align__(16) float g_y[NPIX * 256];   // per pixel: q*s | k | v | raw x
__device__ __align__(16) float g_osum[NPIX * 64];
__device__ __align__(16) float g_const[192];      // qkv row for masked/OOB slots
__device__ float g_qwT[64 * 192];                 // [c][o]
__device__ float g_w1T[64 * 256];                 // [c][u]
__device__ float g_w2T[256 * 64];                 // [u][o]
__device__ float g_projT[64 * 64];                // [c][o]
__device__ __align__(16) float g_ebias[8 * 25 * 25];   // exp(bias) full (boundary)
__device__ __align__(16) float g_eb12[8 * 25 * 12];    // exp(bias)[h][r][c<12] (interior)
__device__ float g_cb[8 * 25];                    // sum_{c>=12} exp(bias)

__device__ __forceinline__ float wsum(float v) {
#pragma unroll
    for (int o = 16; o; o >>= 1) v += __shfl_xor_sync(0xffffffffu, v, o);
    return v;
}

// ---- prep: transposed weights + exp(bias) tables + const qkv row ----
__global__ void prep(const float* __restrict__ qw, const float* __restrict__ w1,
                     const float* __restrict__ w2, const float* __restrict__ pw,
                     const float* __restrict__ rpb,
                     const float* __restrict__ n1b, const float* __restrict__ qb) {
    for (int i = blockIdx.x * blockDim.x + threadIdx.x; i < 56944; i += gridDim.x * blockDim.x) {
        if (i < 12288) { int c = i / 192, o = i % 192; g_qwT[i] = qw[o * 64 + c]; }
        else if (i < 28672) { int j = i - 12288; int c = j / 256, u = j % 256; g_w1T[j] = w1[u * 64 + c]; }
        else if (i < 45056) { int j = i - 28672; int u = j / 64, c = j % 64; g_w2T[j] = w2[c * 256 + u]; }
        else if (i < 49152) { int j = i - 45056; int c = j / 64, o = j % 64; g_projT[j] = pw[o * 64 + c]; }
        else if (i < 54152) {
            int j = i - 49152; int h = j / 625, r = j % 625; int qi = r / 25, kj = r % 25;
            int idx = (qi / 5 - kj / 5 + 4) * 9 + (qi % 5 - kj % 5 + 4);
            g_ebias[j] = __expf(rpb[idx * 8 + h]);
        } else if (i < 56552) {
            int j = i - 54152; int h = j / 300, rem = j % 300; int r = rem / 12, c = rem % 12;
            int idx = (r / 5 - c / 5 + 4) * 9 + (r % 5 - c % 5 + 4);
            g_eb12[j] = __expf(rpb[idx * 8 + h]);
        } else if (i < 56752) {
            int j = i - 56552; int h = j / 25, r = j % 25;
            float s = 0.f;
            for (int c = 12; c < 25; c++) {
                int idx = (r / 5 - c / 5 + 4) * 9 + (r % 5 - c % 5 + 4);
                s += __expf(rpb[idx * 8 + h]);
            }
            g_cb[j] = s;
        } else {
            int o = i - 56752;   // const qkv row: LN(0) = n1b
            float a = qb[o];
            for (int c = 0; c < 64; c++) a += n1b[c] * qw[o * 64 + c];
            if (o < 64) a *= QSCALE;
            g_const[o] = a;
        }
    }
}

// ---- k1: LN1 + QKV, register-tiled: block=64 pixels, warp=8 pixels ----
__global__ __launch_bounds__(256) void k1(const float* __restrict__ x,
                                          const float* __restrict__ n1w,
                                          const float* __restrict__ n1b,
                                          const float* __restrict__ qb) {
    __shared__ float sLn[64][65];
    int tid = threadIdx.x, lane = tid & 31, w = tid >> 5;
    int p0 = blockIdx.x * 64;
    float nw0 = n1w[lane], nw1 = n1w[lane + 32];
    float nb0 = n1b[lane], nb1 = n1b[lane + 32];
#pragma unroll
    for (int t = 0; t < 8; t++) {
        int wid = p0 + w * 8 + t;
        int b = wid >> 12, hw = wid & 4095;
        const float* xb = x + (size_t)b * 262144 + hw;
        float x0 = __ldg(xb + (size_t)lane * 4096);
        float x1 = __ldg(xb + (size_t)(lane + 32) * 4096);
        float m  = wsum(x0 + x1) * (1.f / 64.f);
        float vv = wsum(x0 * x0 + x1 * x1) * (1.f / 64.f) - m * m;
        float rs = rsqrtf(vv + 1e-5f);
        sLn[w * 8 + t][lane]      = (x0 - m) * rs * nw0 + nb0;
        sLn[w * 8 + t][lane + 32] = (x1 - m) * rs * nw1 + nb1;
        float* yp = g_y + (size_t)wid * 256;
        yp[192 + lane] = x0; yp[224 + lane] = x1;
    }
    __syncwarp();
    float acc[6][8];
#pragma unroll
    for (int k = 0; k < 6; k++)
#pragma unroll
        for (int j = 0; j < 8; j++) acc[k][j] = 0.f;
    for (int c = 0; c < 64; c++) {
        float wv[6];
        const float* wr = g_qwT + c * 192 + lane;
#pragma unroll
        for (int k = 0; k < 6; k++) wv[k] = wr[32 * k];
#pragma unroll
        for (int j = 0; j < 8; j++) {
            float l = sLn[w * 8 + j][c];
#pragma unroll
            for (int k = 0; k < 6; k++) acc[k][j] += wv[k] * l;
        }
    }
#pragma unroll
    for (int k = 0; k < 6; k++) {
        int o = lane + 32 * k;
        float bias = qb[o];
        float sc = (o < 64) ? QSCALE : 1.f;
#pragma unroll
        for (int j = 0; j < 8; j++)
            g_y[(size_t)(p0 + w * 8 + j) * 256 + o] = (acc[k][j] + bias) * sc;
    }
}

// ---- k2: merged window attention. blocks [0,NBI): interior 4-pixel strips;
//      blocks [NBI, NBI+NBB): boundary single pixels (generic masked path). ----
__global__ __launch_bounds__(256, 4) void k2() {
    __shared__ float sQ[22 * SLOT_STRIDE];
    __shared__ float sED[4 * 1352];     // boundary overlays its CB scratch at +1360
    __shared__ float sInv[4 * 200];
    __shared__ float sW[4 * 104];
    __shared__ int   sSlot[4][13];
    __shared__ int   sMap[25];
    __shared__ int   sOff[13];

    int tid = threadIdx.x;

    if (blockIdx.x < NBI) {
        // ================= interior path =================
        int idx = blockIdx.x;
        int b = idx / 900, rem = idx - b * 900;
        int h0 = 2 + rem / 15, w0 = 2 + (rem % 15) * 4;
        int base = (b << 12) + (h0 << 6) + w0;

        if (tid < 52) {
            int j = tid / 13, ls = tid - j * 13;
            int g = (ls < 5) ? ls + j : (ls < 10) ? 8 + (ls - 5) + j : (ls < 12) ? 16 + (ls - 10) + j : 21;
            sSlot[j][ls] = g;
        }
        for (int i = tid; i < 22 * 64; i += 256) {
            int slot = i >> 6, jj = i & 63;
            float4 v;
            if (slot < 21) {
                int row, col;
                if (slot < 16) { row = slot >> 3; col = slot & 7; }
                else { row = 2; col = slot - 16; }
                int pp = base + (row - 2) * 64 + (col - 2);
                v = *(const float4*)(g_y + (size_t)pp * 256 + jj * 4);
            } else {
                v = (jj < 48) ? *(const float4*)(g_const + jj * 4) : make_float4(0.f, 0.f, 0.f, 0.f);
            }
            *(float4*)(sQ + slot * SLOT_STRIDE + jj * 4) = v;
        }
        __syncthreads();

        // dots: broadcast-k scheme, half-warp group per (pix,h) pair
        {
            int w = tid >> 5, lane = tid & 31;
            int grp = lane >> 4, qi = lane & 15;
            bool act = qi < 13;
#pragma unroll
            for (int it = 0; it < 2; it++) {
                int pairidx = w * 4 + it * 2 + grp;
                int pix = pairidx >> 3, h = pairidx & 7;
                const int* sm = sSlot[pix];
                float4 qa = make_float4(0.f, 0.f, 0.f, 0.f), qd = qa;
                if (act) {
                    int gq = sm[qi];
                    qa = *(const float4*)(sQ + gq * SLOT_STRIDE + h * 8);
                    qd = *(const float4*)(sQ + gq * SLOT_STRIDE + h * 8 + 4);
                }
                float* ed = sED + pix * 1352 + h * 169 + qi * 13;
#pragma unroll
                for (int ki = 0; ki < 13; ki++) {
                    const float* kb = sQ + sm[ki] * SLOT_STRIDE + 64 + h * 8;
                    float4 ka = *(const float4*)kb;
                    float4 kd = *(const float4*)(kb + 4);
                    float dot = qa.x * ka.x + qa.y * ka.y + qa.z * ka.z + qa.w * ka.w
                              + qd.x * kd.x + qd.y * kd.y + qd.z * kd.z + qd.w * kd.w;
                    if (act) ed[ki] = __expf(dot);
                }
            }
        }
        __syncthreads();

        // pass1
        for (int i = tid; i < 800; i += 256) {
            int pix = i / 200, t = i - pix * 200;
            int h = t / 25, r = t - h * 25;
            int qi = (r < 12) ? r : 12;
            const float* ed = sED + pix * 1352 + h * 169 + qi * 13;
            const float* eb = g_eb12 + h * 300 + r * 12;
            float4 e0 = __ldg((const float4*)eb);
            float4 e1 = __ldg((const float4*)(eb + 4));
            float4 e2 = __ldg((const float4*)(eb + 8));
            float den = __ldg(g_cb + h * 25 + r) * ed[12];
            den += e0.x * ed[0] + e0.y * ed[1] + e0.z * ed[2] + e0.w * ed[3];
            den += e1.x * ed[4] + e1.y * ed[5] + e1.z * ed[6] + e1.w * ed[7];
            den += e2.x * ed[8] + e2.y * ed[9] + e2.z * ed[10] + e2.w * ed[11];
            sInv[pix * 200 + t] = 1.f / den;
        }
        __syncthreads();

        // pass2
        for (int i = tid; i < 416; i += 256) {
            int pix = i / 104, t = i - pix * 104;
            int h = t / 13, c = t - h * 13;
            const float* ed = sED + pix * 1352 + h * 169;
            const float* iv = sInv + pix * 200 + h * 25;
            float w = 0.f, tt = 0.f;
            if (c < 12) {
                const float* eb = g_eb12 + h * 300 + c;
#pragma unroll
                for (int r = 0; r < 12; r++) w += iv[r] * ed[r * 13 + c] * __ldg(eb + r * 12);
#pragma unroll
                for (int r = 12; r < 25; r++) tt += iv[r] * __ldg(eb + r * 12);
                w += ed[156 + c] * tt;
            } else {
                const float* cb = g_cb + h * 25;
#pragma unroll
                for (int r = 0; r < 12; r++) w += iv[r] * ed[r * 13 + 12] * __ldg(cb + r);
#pragma unroll
                for (int r = 12; r < 25; r++) tt += iv[r] * __ldg(cb + r);
                w += ed[168] * tt;
            }
            sW[pix * 104 + t] = w;
        }
        __syncthreads();

        // pass3
        {
            int pix = tid >> 6, ch = tid & 63, h = ch >> 3;
            const float* w = sW + pix * 104 + h * 13;
            const int* sm = sSlot[pix];
            float acc = 0.f;
#pragma unroll
            for (int c = 0; c < 13; c++) acc += w[c] * sQ[sm[c] * SLOT_STRIDE + 128 + ch];
#pragma unroll
            for (int s = 0; s < 12; s++) acc += sQ[sm[s] * SLOT_STRIDE + 192 + ch];
            g_osum[(size_t)(base + pix) * 64 + ch] = acc;
        }
    } else {
        // ================= boundary path =================
        float* sCB = sED + 1360;   // overlay (ED uses [0,1352))
        int t = blockIdx.x - NBI;
        int b = t / 496, u = t - b * 496;
        int h0, w0;
        if (u < 128)      { h0 = u >> 6; w0 = u & 63; }
        else if (u < 256) { int v = u - 128; h0 = 62 + (v >> 6); w0 = v & 63; }
        else              { int v = u - 256; h0 = 2 + v / 4; int c = v & 3; w0 = (c < 2) ? c : (60 + c); }
        int p = (b << 12) + (h0 << 6) + w0;

        if (tid < 25) {
            int ri = tid / 5 - 2, ci = tid % 5 - 2;
            int nh = h0 + ri, nw = w0 + ci;
            int ok = (tid < 12) && nh >= 0 && nh < 64 && nw >= 0 && nw < 64;
            sMap[tid] = ok ? tid : 12;
            if (tid < 13) sOff[tid] = -1;
            if (ok) sOff[tid] = ((b << 12) + (nh << 6) + nw) * 256;
        }
        __syncthreads();

        for (int i = tid; i < 13 * 64; i += 256) {
            int slot = i >> 6, j = i & 63;
            int off = sOff[slot];
            float4 v;
            if (off >= 0)    v = *(const float4*)(g_y + off + j * 4);
            else if (j < 48) v = *(const float4*)(g_const + j * 4);
            else             v = make_float4(0.f, 0.f, 0.f, 0.f);
            *(float4*)(sQ + slot * SLOT_STRIDE + j * 4) = v;
        }
        __syncthreads();

        if (tid < 104) {
            int h = tid / 13, qi = tid % 13;
            float4 qa = *(const float4*)(sQ + qi * SLOT_STRIDE + h * 8);
            float4 qd = *(const float4*)(sQ + qi * SLOT_STRIDE + h * 8 + 4);
            float* ed = sED + h * 169 + qi * 13;
#pragma unroll
            for (int ki = 0; ki < 13; ki++) {
                const float* kb = sQ + ki * SLOT_STRIDE + 64 + h * 8;
                float4 ka = *(const float4*)kb;
                float4 kd = *(const float4*)(kb + 4);
                float dot = qa.x * ka.x + qa.y * ka.y + qa.z * ka.z + qa.w * ka.w
                          + qd.x * kd.x + qd.y * kd.y + qd.z * kd.z + qd.w * kd.w;
                ed[ki] = __expf(dot);
            }
        }
        __syncthreads();

        if (tid < 200) {
            int h = tid / 25, r = tid % 25;
            int qi = sMap[r];
            const float* eb = g_ebias + h * 625 + r * 25;
            const float* ed = sED + h * 169 + qi * 13;
            float den = 0.f, cb = 0.f;
#pragma unroll
            for (int col = 0; col < 25; col++) {
                int ki = sMap[col];
                float e = __ldg(eb + col);
                den += e * ed[ki];
                if (ki == 12) cb += e;
            }
            sInv[tid] = 1.f / den;
            sCB[tid] = cb;
        }
        __syncthreads();

        if (tid < 104) {
            int h = tid / 13, c = tid % 13;
            const float* ed = sED + h * 169;
            const float* iv = sInv + h * 25;
            float w = 0.f;
            if (c == 12) {
                const float* cb = sCB + h * 25;
#pragma unroll
                for (int r = 0; r < 25; r++) w += iv[r] * ed[sMap[r] * 13 + 12] * cb[r];
            } else if (sMap[c] == c) {
                const float* eb = g_ebias + h * 625 + c;
#pragma unroll
                for (int r = 0; r < 25; r++) w += iv[r] * ed[sMap[r] * 13 + c] * __ldg(eb + r * 25);
            }
            sW[tid] = w;
        }
        __syncthreads();

        if (tid < 64) {
            int h = tid >> 3;
            const float* w = sW + h * 13;
            float acc = 0.f;
#pragma unroll
            for (int c = 0; c < 13; c++) acc += w[c] * sQ[c * SLOT_STRIDE + 128 + tid];
#pragma unroll
            for (int s = 0; s < 12; s++) acc += sQ[s * SLOT_STRIDE + 192 + tid];
            g_osum[(size_t)p * 64 + tid] = acc;
        }
    }
}

// ---- k3: LN2 + MLP + proj, register-tiled: block=32 pixels, warp=4 pixels ----
__global__ __launch_bounds__(256) void k3(const float* __restrict__ n2w, const float* __restrict__ n2b,
                                          const float* __restrict__ b1, const float* __restrict__ b2,
                                          const float* __restrict__ pb, float* __restrict__ out) {
    __shared__ float sLn[32][68];     // reused as sY
    __shared__ float sH[32][260];
    int tid = threadIdx.x, lane = tid & 31, w = tid >> 5;
    int p0 = blockIdx.x * 32;

    float nw0 = n2w[lane], nw1 = n2w[lane + 32];
    float nb0 = n2b[lane], nb1 = n2b[lane + 32];
#pragma unroll
    for (int t = 0; t < 4; t++) {
        const float* os = g_osum + (size_t)(p0 + w * 4 + t) * 64;
        float x0 = os[lane], x1 = os[lane + 32];
        float m  = wsum(x0 + x1) * (1.f / 64.f);
        float vv = wsum(x0 * x0 + x1 * x1) * (1.f / 64.f) - m * m;
        float rs = rsqrtf(vv + 1e-5f);
        sLn[w * 4 + t][lane]      = (x0 - m) * rs * nw0 + nb0;
        sLn[w * 4 + t][lane + 32] = (x1 - m) * rs * nw1 + nb1;
    }
    __syncwarp();

    float acc[8][4];
#pragma unroll
    for (int k = 0; k < 8; k++)
#pragma unroll
        for (int j = 0; j < 4; j++) acc[k][j] = 0.f;
    for (int c = 0; c < 64; c++) {
        float wv[8];
        const float* wr = g_w1T + c * 256 + lane;
#pragma unroll
        for (int k = 0; k < 8; k++) wv[k] = wr[32 * k];
#pragma unroll
        for (int j = 0; j < 4; j++) {
            float l = sLn[w * 4 + j][c];
#pragma unroll
            for (int k = 0; k < 8; k++) acc[k][j] += wv[k] * l;
        }
    }
#pragma unroll
    for (int k = 0; k < 8; k++) {
        float bb = b1[lane + 32 * k];
#pragma unroll
        for (int j = 0; j < 4; j++) {
            float v = acc[k][j] + bb;
            sH[w * 4 + j][lane + 32 * k] = 0.5f * v * (1.f + erff(v * 0.70710678118f));
        }
    }
    __syncwarp();

    float a2[2][4];
#pragma unroll
    for (int k = 0; k < 2; k++)
#pragma unroll
        for (int j = 0; j < 4; j++) a2[k][j] = 0.f;
    for (int c0 = 0; c0 < 256; c0 += 4) {
        float4 h4[4];
#pragma unroll
        for (int j = 0; j < 4; j++) h4[j] = *(const float4*)&sH[w * 4 + j][c0];
#pragma unroll
        for (int d = 0; d < 4; d++) {
            const float* wr = g_w2T + (c0 + d) * 64;
            float w0v = wr[lane], w1v = wr[lane + 32];
#pragma unroll
            for (int j = 0; j < 4; j++) {
                float hv = (d == 0) ? h4[j].x : (d == 1) ? h4[j].y : (d == 2) ? h4[j].z : h4[j].w;
                a2[0][j] += w0v * hv; a2[1][j] += w1v * hv;
            }
        }
    }
    float bb0 = b2[lane], bb1 = b2[lane + 32];
#pragma unroll
    for (int j = 0; j < 4; j++) {
        const float* os = g_osum + (size_t)(p0 + w * 4 + j) * 64;
        sLn[w * 4 + j][lane]      = a2[0][j] + bb0 + os[lane];
        sLn[w * 4 + j][lane + 32] = a2[1][j] + bb1 + os[lane + 32];
    }
    __syncwarp();

    float a3[2][4];
#pragma unroll
    for (int k = 0; k < 2; k++)
#pragma unroll
        for (int j = 0; j < 4; j++) a3[k][j] = 0.f;
    for (int c0 = 0; c0 < 64; c0 += 4) {
        float4 y4[4];
#pragma unroll
        for (int j = 0; j < 4; j++) y4[j] = *(const float4*)&sLn[w * 4 + j][c0];
#pragma unroll
        for (int d = 0; d < 4; d++) {
            const float* wr = g_projT + (c0 + d) * 64;
            float w0v = wr[lane], w1v = wr[lane + 32];
#pragma unroll
            for (int j = 0; j < 4; j++) {
                float yv = (d == 0) ? y4[j].x : (d == 1) ? y4[j].y : (d == 2) ? y4[j].z : y4[j].w;
                a3[0][j] += w0v * yv; a3[1][j] += w1v * yv;
            }
        }
    }
    float pb0 = pb[lane], pb1 = pb[lane + 32];
#pragma unroll
    for (int j = 0; j < 4; j++) {
        int wid = p0 + w * 4 + j;
        int b = wid >> 12, hw = wid & 4095;
        float* ob = out + (size_t)b * 262144 + hw;
        ob[(size_t)lane * 4096]        = a3[0][j] + pb0;
        ob[(size_t)(lane + 32) * 4096] = a3[1][j] + pb1;
    }
}

extern "C" void kernel_launch(void* const* d_in, const int* in_sizes, int n_in,
                              void* d_out, int out_size) {
    const float* x    = (const float*)d_in[0];
    const float* n1w  = (const float*)d_in[1];
    const float* n1b  = (const float*)d_in[2];
    const float* qw   = (const float*)d_in[3];
    const float* qb   = (const float*)d_in[4];
    const float* rpb  = (const float*)d_in[5];
    const float* n2w  = (const float*)d_in[6];
    const float* n2b  = (const float*)d_in[7];
    const float* w1   = (const float*)d_in[8];
    const float* b1   = (const float*)d_in[9];
    const float* w2   = (const float*)d_in[10];
    const float* b2   = (const float*)d_in[11];
    const float* pw   = (const float*)d_in[12];
    const float* pb   = (const float*)d_in[13];
    float* out = (float*)d_out;

    prep<<<64, 256>>>(qw, w1, w2, pw, rpb, n1b, qb);
    k1<<<256, 256>>>(x, n1w, n1b, qb);
    k2<<<NBI + NBB, 256>>>();
    k3<<<512, 256>>>(n2w, n2b, b1, b2, pb, out);
}

// round 10
// speedup vs baseline: 2.4786x; 1.0003x over previous
#include <cuda_runtime.h>
#include <math.h>

#define NPIX 16384
#define QSCALE 0.35355339059327373f
#define SLOT_STRIDE 260
#define NBI 3600   // interior blocks
#define NBB 1984   // boundary blocks

__device__ __align__(16) float g_y[NPIX * 256];   // per pixel: q*s | k | v | raw x
__device__ __align__(16) float g_osum[NPIX * 64];
__device__ __align__(16) float g_const[192];      // qkv row for masked/OOB slots
__device__ float g_qwT[64 * 192];                 // [c][o]
__device__ __align__(16) float g_w1T[64 * 256];   // [c][u]
__device__ __align__(16) float g_w2T[256 * 64];   // [u][o]
__device__ __align__(16) float g_projT[64 * 64];  // [c][o]
__device__ __align__(16) float g_ebias[8 * 25 * 25];   // exp(bias) full (boundary)
__device__ __align__(16) float g_eb12[8 * 25 * 12];    // exp(bias)[h][r][c<12] (interior)
__device__ float g_cb[8 * 25];                    // sum_{c>=12} exp(bias)

__device__ __forceinline__ float wsum(float v) {
#pragma unroll
    for (int o = 16; o; o >>= 1) v += __shfl_xor_sync(0xffffffffu, v, o);
    return v;
}

// ---- prep: transposed weights + exp(bias) tables + const qkv row ----
__global__ void prep(const float* __restrict__ qw, const float* __restrict__ w1,
                     const float* __restrict__ w2, const float* __restrict__ pw,
                     const float* __restrict__ rpb,
                     const float* __restrict__ n1b, const float* __restrict__ qb) {
    for (int i = blockIdx.x * blockDim.x + threadIdx.x; i < 56944; i += gridDim.x * blockDim.x) {
        if (i < 12288) { int c = i / 192, o = i % 192; g_qwT[i] = qw[o * 64 + c]; }
        else if (i < 28672) { int j = i - 12288; int c = j / 256, u = j % 256; g_w1T[j] = w1[u * 64 + c]; }
        else if (i < 45056) { int j = i - 28672; int u = j / 64, c = j % 64; g_w2T[j] = w2[c * 256 + u]; }
        else if (i < 49152) { int j = i - 45056; int c = j / 64, o = j % 64; g_projT[j] = pw[o * 64 + c]; }
        else if (i < 54152) {
            int j = i - 49152; int h = j / 625, r = j % 625; int qi = r / 25, kj = r % 25;
            int idx = (qi / 5 - kj / 5 + 4) * 9 + (qi % 5 - kj % 5 + 4);
            g_ebias[j] = __expf(rpb[idx * 8 + h]);
        } else if (i < 56552) {
            int j = i - 54152; int h = j / 300, rem = j % 300; int r = rem / 12, c = rem % 12;
            int idx = (r / 5 - c / 5 + 4) * 9 + (r % 5 - c % 5 + 4);
            g_eb12[j] = __expf(rpb[idx * 8 + h]);
        } else if (i < 56752) {
            int j = i - 56552; int h = j / 25, r = j % 25;
            float s = 0.f;
            for (int c = 12; c < 25; c++) {
                int idx = (r / 5 - c / 5 + 4) * 9 + (r % 5 - c % 5 + 4);
                s += __expf(rpb[idx * 8 + h]);
            }
            g_cb[j] = s;
        } else {
            int o = i - 56752;   // const qkv row: LN(0) = n1b
            float a = qb[o];
            for (int c = 0; c < 64; c++) a += n1b[c] * qw[o * 64 + c];
            if (o < 64) a *= QSCALE;
            g_const[o] = a;
        }
    }
}

// ---- k1: LN1 + QKV, register-tiled: block=64 pixels, warp=8 pixels ----
__global__ __launch_bounds__(256) void k1(const float* __restrict__ x,
                                          const float* __restrict__ n1w,
                                          const float* __restrict__ n1b,
                                          const float* __restrict__ qb) {
    __shared__ float sLn[64][65];
    int tid = threadIdx.x, lane = tid & 31, w = tid >> 5;
    int p0 = blockIdx.x * 64;
    float nw0 = n1w[lane], nw1 = n1w[lane + 32];
    float nb0 = n1b[lane], nb1 = n1b[lane + 32];
#pragma unroll
    for (int t = 0; t < 8; t++) {
        int wid = p0 + w * 8 + t;
        int b = wid >> 12, hw = wid & 4095;
        const float* xb = x + (size_t)b * 262144 + hw;
        float x0 = __ldg(xb + (size_t)lane * 4096);
        float x1 = __ldg(xb + (size_t)(lane + 32) * 4096);
        float m  = wsum(x0 + x1) * (1.f / 64.f);
        float vv = wsum(x0 * x0 + x1 * x1) * (1.f / 64.f) - m * m;
        float rs = rsqrtf(vv + 1e-5f);
        sLn[w * 8 + t][lane]      = (x0 - m) * rs * nw0 + nb0;
        sLn[w * 8 + t][lane + 32] = (x1 - m) * rs * nw1 + nb1;
        float* yp = g_y + (size_t)wid * 256;
        yp[192 + lane] = x0; yp[224 + lane] = x1;
    }
    __syncwarp();
    float acc[6][8];
#pragma unroll
    for (int k = 0; k < 6; k++)
#pragma unroll
        for (int j = 0; j < 8; j++) acc[k][j] = 0.f;
    for (int c = 0; c < 64; c++) {
        float wv[6];
        const float* wr = g_qwT + c * 192 + lane;
#pragma unroll
        for (int k = 0; k < 6; k++) wv[k] = wr[32 * k];
#pragma unroll
        for (int j = 0; j < 8; j++) {
            float l = sLn[w * 8 + j][c];
#pragma unroll
            for (int k = 0; k < 6; k++) acc[k][j] += wv[k] * l;
        }
    }
#pragma unroll
    for (int k = 0; k < 6; k++) {
        int o = lane + 32 * k;
        float bias = qb[o];
        float sc = (o < 64) ? QSCALE : 1.f;
#pragma unroll
        for (int j = 0; j < 8; j++)
            g_y[(size_t)(p0 + w * 8 + j) * 256 + o] = (acc[k][j] + bias) * sc;
    }
}

// ---- k2: merged window attention. blocks [0,NBI): interior 4-pixel strips;
//      blocks [NBI, NBI+NBB): boundary single pixels (generic masked path). ----
__global__ __launch_bounds__(256, 4) void k2() {
    __shared__ float sQ[22 * SLOT_STRIDE];
    __shared__ float sED[4 * 1352];     // boundary overlays its CB scratch at +1360
    __shared__ float sInv[4 * 200];
    __shared__ float sW[4 * 104];
    __shared__ int   sSlot[4][13];
    __shared__ int   sMap[25];
    __shared__ int   sOff[13];

    int tid = threadIdx.x;

    if (blockIdx.x < NBI) {
        // ================= interior path =================
        int idx = blockIdx.x;
        int b = idx / 900, rem = idx - b * 900;
        int h0 = 2 + rem / 15, w0 = 2 + (rem % 15) * 4;
        int base = (b << 12) + (h0 << 6) + w0;

        if (tid < 52) {
            int j = tid / 13, ls = tid - j * 13;
            int g = (ls < 5) ? ls + j : (ls < 10) ? 8 + (ls - 5) + j : (ls < 12) ? 16 + (ls - 10) + j : 21;
            sSlot[j][ls] = g;
        }
        for (int i = tid; i < 22 * 64; i += 256) {
            int slot = i >> 6, jj = i & 63;
            float4 v;
            if (slot < 21) {
                int row, col;
                if (slot < 16) { row = slot >> 3; col = slot & 7; }
                else { row = 2; col = slot - 16; }
                int pp = base + (row - 2) * 64 + (col - 2);
                v = *(const float4*)(g_y + (size_t)pp * 256 + jj * 4);
            } else {
                v = (jj < 48) ? *(const float4*)(g_const + jj * 4) : make_float4(0.f, 0.f, 0.f, 0.f);
            }
            *(float4*)(sQ + slot * SLOT_STRIDE + jj * 4) = v;
        }
        __syncthreads();

        // dots: broadcast-k scheme, half-warp group per (pix,h) pair
        {
            int w = tid >> 5, lane = tid & 31;
            int grp = lane >> 4, qi = lane & 15;
            bool act = qi < 13;
#pragma unroll
            for (int it = 0; it < 2; it++) {
                int pairidx = w * 4 + it * 2 + grp;
                int pix = pairidx >> 3, h = pairidx & 7;
                const int* sm = sSlot[pix];
                float4 qa = make_float4(0.f, 0.f, 0.f, 0.f), qd = qa;
                if (act) {
                    int gq = sm[qi];
                    qa = *(const float4*)(sQ + gq * SLOT_STRIDE + h * 8);
                    qd = *(const float4*)(sQ + gq * SLOT_STRIDE + h * 8 + 4);
                }
                float* ed = sED + pix * 1352 + h * 169 + qi * 13;
#pragma unroll
                for (int ki = 0; ki < 13; ki++) {
                    const float* kb = sQ + sm[ki] * SLOT_STRIDE + 64 + h * 8;
                    float4 ka = *(const float4*)kb;
                    float4 kd = *(const float4*)(kb + 4);
                    float dot = qa.x * ka.x + qa.y * ka.y + qa.z * ka.z + qa.w * ka.w
                              + qd.x * kd.x + qd.y * kd.y + qd.z * kd.z + qd.w * kd.w;
                    if (act) ed[ki] = __expf(dot);
                }
            }
        }
        __syncthreads();

        // pass1
        for (int i = tid; i < 800; i += 256) {
            int pix = i / 200, t = i - pix * 200;
            int h = t / 25, r = t - h * 25;
            int qi = (r < 12) ? r : 12;
            const float* ed = sED + pix * 1352 + h * 169 + qi * 13;
            const float* eb = g_eb12 + h * 300 + r * 12;
            float4 e0 = __ldg((const float4*)eb);
            float4 e1 = __ldg((const float4*)(eb + 4));
            float4 e2 = __ldg((const float4*)(eb + 8));
            float den = __ldg(g_cb + h * 25 + r) * ed[12];
            den += e0.x * ed[0] + e0.y * ed[1] + e0.z * ed[2] + e0.w * ed[3];
            den += e1.x * ed[4] + e1.y * ed[5] + e1.z * ed[6] + e1.w * ed[7];
            den += e2.x * ed[8] + e2.y * ed[9] + e2.z * ed[10] + e2.w * ed[11];
            sInv[pix * 200 + t] = 1.f / den;
        }
        __syncthreads();

        // pass2
        for (int i = tid; i < 416; i += 256) {
            int pix = i / 104, t = i - pix * 104;
            int h = t / 13, c = t - h * 13;
            const float* ed = sED + pix * 1352 + h * 169;
            const float* iv = sInv + pix * 200 + h * 25;
            float w = 0.f, tt = 0.f;
            if (c < 12) {
                const float* eb = g_eb12 + h * 300 + c;
#pragma unroll
                for (int r = 0; r < 12; r++) w += iv[r] * ed[r * 13 + c] * __ldg(eb + r * 12);
#pragma unroll
                for (int r = 12; r < 25; r++) tt += iv[r] * __ldg(eb + r * 12);
                w += ed[156 + c] * tt;
            } else {
                const float* cb = g_cb + h * 25;
#pragma unroll
                for (int r = 0; r < 12; r++) w += iv[r] * ed[r * 13 + 12] * __ldg(cb + r);
#pragma unroll
                for (int r = 12; r < 25; r++) tt += iv[r] * __ldg(cb + r);
                w += ed[168] * tt;
            }
            sW[pix * 104 + t] = w;
        }
        __syncthreads();

        // pass3
        {
            int pix = tid >> 6, ch = tid & 63, h = ch >> 3;
            const float* w = sW + pix * 104 + h * 13;
            const int* sm = sSlot[pix];
            float acc = 0.f;
#pragma unroll
            for (int c = 0; c < 13; c++) acc += w[c] * sQ[sm[c] * SLOT_STRIDE + 128 + ch];
#pragma unroll
            for (int s = 0; s < 12; s++) acc += sQ[sm[s] * SLOT_STRIDE + 192 + ch];
            g_osum[(size_t)(base + pix) * 64 + ch] = acc;
        }
    } else {
        // ================= boundary path =================
        float* sCB = sED + 1360;   // overlay (ED uses [0,1352))
        int t = blockIdx.x - NBI;
        int b = t / 496, u = t - b * 496;
        int h0, w0;
        if (u < 128)      { h0 = u >> 6; w0 = u & 63; }
        else if (u < 256) { int v = u - 128; h0 = 62 + (v >> 6); w0 = v & 63; }
        else              { int v = u - 256; h0 = 2 + v / 4; int c = v & 3; w0 = (c < 2) ? c : (60 + c); }
        int p = (b << 12) + (h0 << 6) + w0;

        if (tid < 25) {
            int ri = tid / 5 - 2, ci = tid % 5 - 2;
            int nh = h0 + ri, nw = w0 + ci;
            int ok = (tid < 12) && nh >= 0 && nh < 64 && nw >= 0 && nw < 64;
            sMap[tid] = ok ? tid : 12;
            if (tid < 13) sOff[tid] = -1;
            if (ok) sOff[tid] = ((b << 12) + (nh << 6) + nw) * 256;
        }
        __syncthreads();

        for (int i = tid; i < 13 * 64; i += 256) {
            int slot = i >> 6, j = i & 63;
            int off = sOff[slot];
            float4 v;
            if (off >= 0)    v = *(const float4*)(g_y + off + j * 4);
            else if (j < 48) v = *(const float4*)(g_const + j * 4);
            else             v = make_float4(0.f, 0.f, 0.f, 0.f);
            *(float4*)(sQ + slot * SLOT_STRIDE + j * 4) = v;
        }
        __syncthreads();

        if (tid < 104) {
            int h = tid / 13, qi = tid % 13;
            float4 qa = *(const float4*)(sQ + qi * SLOT_STRIDE + h * 8);
            float4 qd = *(const float4*)(sQ + qi * SLOT_STRIDE + h * 8 + 4);
            float* ed = sED + h * 169 + qi * 13;
#pragma unroll
            for (int ki = 0; ki < 13; ki++) {
                const float* kb = sQ + ki * SLOT_STRIDE + 64 + h * 8;
                float4 ka = *(const float4*)kb;
                float4 kd = *(const float4*)(kb + 4);
                float dot = qa.x * ka.x + qa.y * ka.y + qa.z * ka.z + qa.w * ka.w
                          + qd.x * kd.x + qd.y * kd.y + qd.z * kd.z + qd.w * kd.w;
                ed[ki] = __expf(dot);
            }
        }
        __syncthreads();

        if (tid < 200) {
            int h = tid / 25, r = tid % 25;
            int qi = sMap[r];
            const float* eb = g_ebias + h * 625 + r * 25;
            const float* ed = sED + h * 169 + qi * 13;
            float den = 0.f, cb = 0.f;
#pragma unroll
            for (int col = 0; col < 25; col++) {
                int ki = sMap[col];
                float e = __ldg(eb + col);
                den += e * ed[ki];
                if (ki == 12) cb += e;
            }
            sInv[tid] = 1.f / den;
            sCB[tid] = cb;
        }
        __syncthreads();

        if (tid < 104) {
            int h = tid / 13, c = tid % 13;
            const float* ed = sED + h * 169;
            const float* iv = sInv + h * 25;
            float w = 0.f;
            if (c == 12) {
                const float* cb = sCB + h * 25;
#pragma unroll
                for (int r = 0; r < 25; r++) w += iv[r] * ed[sMap[r] * 13 + 12] * cb[r];
            } else if (sMap[c] == c) {
                const float* eb = g_ebias + h * 625 + c;
#pragma unroll
                for (int r = 0; r < 25; r++) w += iv[r] * ed[sMap[r] * 13 + c] * __ldg(eb + r * 25);
            }
            sW[tid] = w;
        }
        __syncthreads();

        if (tid < 64) {
            int h = tid >> 3;
            const float* w = sW + h * 13;
            float acc = 0.f;
#pragma unroll
            for (int c = 0; c < 13; c++) acc += w[c] * sQ[c * SLOT_STRIDE + 128 + tid];
#pragma unroll
            for (int s = 0; s < 12; s++) acc += sQ[s * SLOT_STRIDE + 192 + tid];
            g_osum[(size_t)p * 64 + tid] = acc;
        }
    }
}

// ---- k3: LN2 + MLP + proj. 128-thread blocks, 8 pixels/block, 2 pixels/thread,
//      float4/float2 weight loads. High occupancy, low register pressure. ----
__global__ __launch_bounds__(128) void k3(const float* __restrict__ n2w, const float* __restrict__ n2b,
                                          const float* __restrict__ b1, const float* __restrict__ b2,
                                          const float* __restrict__ pb, float* __restrict__ out) {
    __shared__ float sLn[8][68];      // LN output, later reused as y (fc2+residual)
    __shared__ float sH[8][260];      // gelu(fc1) activations
    int tid = threadIdx.x, lane = tid & 31, w = tid >> 5;
    int p0 = blockIdx.x * 8;

    float nw0 = n2w[lane], nw1 = n2w[lane + 32];
    float nb0 = n2b[lane], nb1 = n2b[lane + 32];
#pragma unroll
    for (int t = 0; t < 2; t++) {
        const float* os = g_osum + (size_t)(p0 + w * 2 + t) * 64;
        float x0 = os[lane], x1 = os[lane + 32];
        float m  = wsum(x0 + x1) * (1.f / 64.f);
        float vv = wsum(x0 * x0 + x1 * x1) * (1.f / 64.f) - m * m;
        float rs = rsqrtf(vv + 1e-5f);
        sLn[w * 2 + t][lane]      = (x0 - m) * rs * nw0 + nb0;
        sLn[w * 2 + t][lane + 32] = (x1 - m) * rs * nw1 + nb1;
    }
    __syncwarp();

    // fc1: lane owns hidden outputs [8*lane, 8*lane+8), 2 pixels
    float acc[8][2];
#pragma unroll
    for (int k = 0; k < 8; k++) { acc[k][0] = 0.f; acc[k][1] = 0.f; }
    for (int c = 0; c < 64; c++) {
        float4 wa = __ldg((const float4*)(g_w1T + c * 256 + lane * 8));
        float4 wb = __ldg((const float4*)(g_w1T + c * 256 + lane * 8 + 4));
        float l0 = sLn[w * 2][c], l1 = sLn[w * 2 + 1][c];
        acc[0][0] += wa.x * l0; acc[1][0] += wa.y * l0; acc[2][0] += wa.z * l0; acc[3][0] += wa.w * l0;
        acc[4][0] += wb.x * l0; acc[5][0] += wb.y * l0; acc[6][0] += wb.z * l0; acc[7][0] += wb.w * l0;
        acc[0][1] += wa.x * l1; acc[1][1] += wa.y * l1; acc[2][1] += wa.z * l1; acc[3][1] += wa.w * l1;
        acc[4][1] += wb.x * l1; acc[5][1] += wb.y * l1; acc[6][1] += wb.z * l1; acc[7][1] += wb.w * l1;
    }
    {
        float4 ba = __ldg((const float4*)(b1 + lane * 8));
        float4 bb = __ldg((const float4*)(b1 + lane * 8 + 4));
        float bv[8] = {ba.x, ba.y, ba.z, ba.w, bb.x, bb.y, bb.z, bb.w};
#pragma unroll
        for (int j = 0; j < 2; j++) {
            float g[8];
#pragma unroll
            for (int k = 0; k < 8; k++) {
                float v = acc[k][j] + bv[k];
                g[k] = 0.5f * v * (1.f + erff(v * 0.70710678118f));
            }
            *(float4*)&sH[w * 2 + j][lane * 8]     = make_float4(g[0], g[1], g[2], g[3]);
            *(float4*)&sH[w * 2 + j][lane * 8 + 4] = make_float4(g[4], g[5], g[6], g[7]);
        }
    }
    __syncwarp();

    // fc2 + residual: lane owns outputs {2*lane, 2*lane+1}
    float a2[2][2] = {{0.f, 0.f}, {0.f, 0.f}};
    for (int c0 = 0; c0 < 256; c0 += 4) {
        float4 h0 = *(const float4*)&sH[w * 2][c0];
        float4 h1 = *(const float4*)&sH[w * 2 + 1][c0];
#pragma unroll
        for (int d = 0; d < 4; d++) {
            float2 wv = __ldg((const float2*)(g_w2T + (c0 + d) * 64 + 2 * lane));
            float hv0 = (d == 0) ? h0.x : (d == 1) ? h0.y : (d == 2) ? h0.z : h0.w;
            float hv1 = (d == 0) ? h1.x : (d == 1) ? h1.y : (d == 2) ? h1.z : h1.w;
            a2[0][0] += wv.x * hv0; a2[1][0] += wv.y * hv0;
            a2[0][1] += wv.x * hv1; a2[1][1] += wv.y * hv1;
        }
    }
    {
        float2 bb = __ldg((const float2*)(b2 + 2 * lane));
#pragma unroll
        for (int j = 0; j < 2; j++) {
            float2 os2 = __ldg((const float2*)(g_osum + (size_t)(p0 + w * 2 + j) * 64 + 2 * lane));
            sLn[w * 2 + j][2 * lane]     = a2[0][j] + bb.x + os2.x;
            sLn[w * 2 + j][2 * lane + 1] = a2[1][j] + bb.y + os2.y;
        }
    }
    __syncwarp();

    // proj: lane owns outputs {2*lane, 2*lane+1}
    float a3[2][2] = {{0.f, 0.f}, {0.f, 0.f}};
    for (int c0 = 0; c0 < 64; c0 += 4) {
        float4 y0 = *(const float4*)&sLn[w * 2][c0];
        float4 y1 = *(const float4*)&sLn[w * 2 + 1][c0];
#pragma unroll
        for (int d = 0; d < 4; d++) {
            float2 wv = __ldg((const float2*)(g_projT + (c0 + d) * 64 + 2 * lane));
            float yv0 = (d == 0) ? y0.x : (d == 1) ? y0.y : (d == 2) ? y0.z : y0.w;
            float yv1 = (d == 0) ? y1.x : (d == 1) ? y1.y : (d == 2) ? y1.z : y1.w;
            a3[0][0] += wv.x * yv0; a3[1][0] += wv.y * yv0;
            a3[0][1] += wv.x * yv1; a3[1][1] += wv.y * yv1;
        }
    }
    {
        float2 pbv = __ldg((const float2*)(pb + 2 * lane));
#pragma unroll
        for (int j = 0; j < 2; j++) {
            int wid = p0 + w * 2 + j;
            int b = wid >> 12, hw = wid & 4095;
            float* ob = out + (size_t)b * 262144 + hw;
            ob[(size_t)(2 * lane) * 4096]     = a3[0][j] + pbv.x;
            ob[(size_t)(2 * lane + 1) * 4096] = a3[1][j] + pbv.y;
        }
    }
}

extern "C" void kernel_launch(void* const* d_in, const int* in_sizes, int n_in,
                              void* d_out, int out_size) {
    const float* x    = (const float*)d_in[0];
    const float* n1w  = (const float*)d_in[1];
    const float* n1b  = (const float*)d_in[2];
    const float* qw   = (const float*)d_in[3];
    const float* qb   = (const float*)d_in[4];
    const float* rpb  = (const float*)d_in[5];
    const float* n2w  = (const float*)d_in[6];
    const float* n2b  = (const float*)d_in[7];
    const float* w1   = (const float*)d_in[8];
    const float* b1   = (const float*)d_in[9];
    const float* w2   = (const float*)d_in[10];
    const float* b2   = (const float*)d_in[11];
    const float* pw   = (const float*)d_in[12];
    const float* pb   = (const float*)d_in[13];
    float* out = (float*)d_out;

    prep<<<64, 256>>>(qw, w1, w2, pw, rpb, n1b, qb);
    k1<<<256, 256>>>(x, n1w, n1b, qb);
    k2<<<NBI + NBB, 256>>>();
    k3<<<2048, 128>>>(n2w, n2b, b1, b2, pb, out);
}

// round 11
// speedup vs baseline: 2.6910x; 1.0857x over previous
#include <cuda_runtime.h>
#include <math.h>

#define NPIX 16384
#define QSCALE 0.35355339059327373f
#define SLOT_STRIDE 260
#define NBI 3600   // interior blocks
#define NBB 1984   // boundary blocks
#define K3_SMEM ((16384 + 32 * 65 + 32 * 257) * 4)

__device__ __align__(16) float g_y[NPIX * 256];   // per pixel: q*s | k | v | raw x
__device__ __align__(16) float g_osum[NPIX * 64];
__device__ __align__(16) float g_const[192];      // qkv row for masked/OOB slots
__device__ float g_qwT[64 * 192];                 // [c][o]
__device__ __align__(16) float g_w1T[64 * 256];   // [c][u]
__device__ __align__(16) float g_w2T[256 * 64];   // [u][o]
__device__ __align__(16) float g_projT[64 * 64];  // [c][o]
__device__ __align__(16) float g_ebias[8 * 25 * 25];   // exp(bias) full (boundary)
__device__ __align__(16) float g_eb12[8 * 25 * 12];    // exp(bias)[h][r][c<12] (interior)
__device__ float g_cb[8 * 25];                    // sum_{c>=12} exp(bias)

__device__ __forceinline__ float wsum(float v) {
#pragma unroll
    for (int o = 16; o; o >>= 1) v += __shfl_xor_sync(0xffffffffu, v, o);
    return v;
}

// ---- prep: transposed weights + exp(bias) tables + const qkv row ----
__global__ void prep(const float* __restrict__ qw, const float* __restrict__ w1,
                     const float* __restrict__ w2, const float* __restrict__ pw,
                     const float* __restrict__ rpb,
                     const float* __restrict__ n1b, const float* __restrict__ qb) {
    for (int i = blockIdx.x * blockDim.x + threadIdx.x; i < 56944; i += gridDim.x * blockDim.x) {
        if (i < 12288) { int c = i / 192, o = i % 192; g_qwT[i] = qw[o * 64 + c]; }
        else if (i < 28672) { int j = i - 12288; int c = j / 256, u = j % 256; g_w1T[j] = w1[u * 64 + c]; }
        else if (i < 45056) { int j = i - 28672; int u = j / 64, c = j % 64; g_w2T[j] = w2[c * 256 + u]; }
        else if (i < 49152) { int j = i - 45056; int c = j / 64, o = j % 64; g_projT[j] = pw[o * 64 + c]; }
        else if (i < 54152) {
            int j = i - 49152; int h = j / 625, r = j % 625; int qi = r / 25, kj = r % 25;
            int idx = (qi / 5 - kj / 5 + 4) * 9 + (qi % 5 - kj % 5 + 4);
            g_ebias[j] = __expf(rpb[idx * 8 + h]);
        } else if (i < 56552) {
            int j = i - 54152; int h = j / 300, rem = j % 300; int r = rem / 12, c = rem % 12;
            int idx = (r / 5 - c / 5 + 4) * 9 + (r % 5 - c % 5 + 4);
            g_eb12[j] = __expf(rpb[idx * 8 + h]);
        } else if (i < 56752) {
            int j = i - 56552; int h = j / 25, r = j % 25;
            float s = 0.f;
            for (int c = 12; c < 25; c++) {
                int idx = (r / 5 - c / 5 + 4) * 9 + (r % 5 - c % 5 + 4);
                s += __expf(rpb[idx * 8 + h]);
            }
            g_cb[j] = s;
        } else {
            int o = i - 56752;   // const qkv row: LN(0) = n1b
            float a = qb[o];
            for (int c = 0; c < 64; c++) a += n1b[c] * qw[o * 64 + c];
            if (o < 64) a *= QSCALE;
            g_const[o] = a;
        }
    }
}

// ---- k1: LN1 + QKV, register-tiled: block=64 pixels, warp=8 pixels ----
__global__ __launch_bounds__(256) void k1(const float* __restrict__ x,
                                          const float* __restrict__ n1w,
                                          const float* __restrict__ n1b,
                                          const float* __restrict__ qb) {
    __shared__ float sLn[64][65];
    int tid = threadIdx.x, lane = tid & 31, w = tid >> 5;
    int p0 = blockIdx.x * 64;
    float nw0 = n1w[lane], nw1 = n1w[lane + 32];
    float nb0 = n1b[lane], nb1 = n1b[lane + 32];
#pragma unroll
    for (int t = 0; t < 8; t++) {
        int wid = p0 + w * 8 + t;
        int b = wid >> 12, hw = wid & 4095;
        const float* xb = x + (size_t)b * 262144 + hw;
        float x0 = __ldg(xb + (size_t)lane * 4096);
        float x1 = __ldg(xb + (size_t)(lane + 32) * 4096);
        float m  = wsum(x0 + x1) * (1.f / 64.f);
        float vv = wsum(x0 * x0 + x1 * x1) * (1.f / 64.f) - m * m;
        float rs = rsqrtf(vv + 1e-5f);
        sLn[w * 8 + t][lane]      = (x0 - m) * rs * nw0 + nb0;
        sLn[w * 8 + t][lane + 32] = (x1 - m) * rs * nw1 + nb1;
        float* yp = g_y + (size_t)wid * 256;
        yp[192 + lane] = x0; yp[224 + lane] = x1;
    }
    __syncwarp();
    float acc[6][8];
#pragma unroll
    for (int k = 0; k < 6; k++)
#pragma unroll
        for (int j = 0; j < 8; j++) acc[k][j] = 0.f;
    for (int c = 0; c < 64; c++) {
        float wv[6];
        const float* wr = g_qwT + c * 192 + lane;
#pragma unroll
        for (int k = 0; k < 6; k++) wv[k] = wr[32 * k];
#pragma unroll
        for (int j = 0; j < 8; j++) {
            float l = sLn[w * 8 + j][c];
#pragma unroll
            for (int k = 0; k < 6; k++) acc[k][j] += wv[k] * l;
        }
    }
#pragma unroll
    for (int k = 0; k < 6; k++) {
        int o = lane + 32 * k;
        float bias = qb[o];
        float sc = (o < 64) ? QSCALE : 1.f;
#pragma unroll
        for (int j = 0; j < 8; j++)
            g_y[(size_t)(p0 + w * 8 + j) * 256 + o] = (acc[k][j] + bias) * sc;
    }
}

// ---- k2: merged window attention. blocks [0,NBI): interior 4-pixel strips;
//      blocks [NBI, NBI+NBB): boundary single pixels (generic masked path). ----
__global__ __launch_bounds__(256, 4) void k2() {
    __shared__ float sQ[22 * SLOT_STRIDE];
    __shared__ float sED[4 * 1352];     // boundary overlays its CB scratch at +1360
    __shared__ float sInv[4 * 200];
    __shared__ float sW[4 * 104];
    __shared__ int   sSlot[4][13];
    __shared__ int   sMap[25];
    __shared__ int   sOff[13];

    int tid = threadIdx.x;

    if (blockIdx.x < NBI) {
        // ================= interior path =================
        int idx = blockIdx.x;
        int b = idx / 900, rem = idx - b * 900;
        int h0 = 2 + rem / 15, w0 = 2 + (rem % 15) * 4;
        int base = (b << 12) + (h0 << 6) + w0;

        if (tid < 52) {
            int j = tid / 13, ls = tid - j * 13;
            int g = (ls < 5) ? ls + j : (ls < 10) ? 8 + (ls - 5) + j : (ls < 12) ? 16 + (ls - 10) + j : 21;
            sSlot[j][ls] = g;
        }
        for (int i = tid; i < 22 * 64; i += 256) {
            int slot = i >> 6, jj = i & 63;
            float4 v;
            if (slot < 21) {
                int row, col;
                if (slot < 16) { row = slot >> 3; col = slot & 7; }
                else { row = 2; col = slot - 16; }
                int pp = base + (row - 2) * 64 + (col - 2);
                v = *(const float4*)(g_y + (size_t)pp * 256 + jj * 4);
            } else {
                v = (jj < 48) ? *(const float4*)(g_const + jj * 4) : make_float4(0.f, 0.f, 0.f, 0.f);
            }
            *(float4*)(sQ + slot * SLOT_STRIDE + jj * 4) = v;
        }
        __syncthreads();

        // dots: broadcast-k scheme, half-warp group per (pix,h) pair
        {
            int w = tid >> 5, lane = tid & 31;
            int grp = lane >> 4, qi = lane & 15;
            bool act = qi < 13;
#pragma unroll
            for (int it = 0; it < 2; it++) {
                int pairidx = w * 4 + it * 2 + grp;
                int pix = pairidx >> 3, h = pairidx & 7;
                const int* sm = sSlot[pix];
                float4 qa = make_float4(0.f, 0.f, 0.f, 0.f), qd = qa;
                if (act) {
                    int gq = sm[qi];
                    qa = *(const float4*)(sQ + gq * SLOT_STRIDE + h * 8);
                    qd = *(const float4*)(sQ + gq * SLOT_STRIDE + h * 8 + 4);
                }
                float* ed = sED + pix * 1352 + h * 169 + qi * 13;
#pragma unroll
                for (int ki = 0; ki < 13; ki++) {
                    const float* kb = sQ + sm[ki] * SLOT_STRIDE + 64 + h * 8;
                    float4 ka = *(const float4*)kb;
                    float4 kd = *(const float4*)(kb + 4);
                    float dot = qa.x * ka.x + qa.y * ka.y + qa.z * ka.z + qa.w * ka.w
                              + qd.x * kd.x + qd.y * kd.y + qd.z * kd.z + qd.w * kd.w;
                    if (act) ed[ki] = __expf(dot);
                }
            }
        }
        __syncthreads();

        // pass1
        for (int i = tid; i < 800; i += 256) {
            int pix = i / 200, t = i - pix * 200;
            int h = t / 25, r = t - h * 25;
            int qi = (r < 12) ? r : 12;
            const float* ed = sED + pix * 1352 + h * 169 + qi * 13;
            const float* eb = g_eb12 + h * 300 + r * 12;
            float4 e0 = __ldg((const float4*)eb);
            float4 e1 = __ldg((const float4*)(eb + 4));
            float4 e2 = __ldg((const float4*)(eb + 8));
            float den = __ldg(g_cb + h * 25 + r) * ed[12];
            den += e0.x * ed[0] + e0.y * ed[1] + e0.z * ed[2] + e0.w * ed[3];
            den += e1.x * ed[4] + e1.y * ed[5] + e1.z * ed[6] + e1.w * ed[7];
            den += e2.x * ed[8] + e2.y * ed[9] + e2.z * ed[10] + e2.w * ed[11];
            sInv[pix * 200 + t] = 1.f / den;
        }
        __syncthreads();

        // pass2
        for (int i = tid; i < 416; i += 256) {
            int pix = i / 104, t = i - pix * 104;
            int h = t / 13, c = t - h * 13;
            const float* ed = sED + pix * 1352 + h * 169;
            const float* iv = sInv + pix * 200 + h * 25;
            float w = 0.f, tt = 0.f;
            if (c < 12) {
                const float* eb = g_eb12 + h * 300 + c;
#pragma unroll
                for (int r = 0; r < 12; r++) w += iv[r] * ed[r * 13 + c] * __ldg(eb + r * 12);
#pragma unroll
                for (int r = 12; r < 25; r++) tt += iv[r] * __ldg(eb + r * 12);
                w += ed[156 + c] * tt;
            } else {
                const float* cb = g_cb + h * 25;
#pragma unroll
                for (int r = 0; r < 12; r++) w += iv[r] * ed[r * 13 + 12] * __ldg(cb + r);
#pragma unroll
                for (int r = 12; r < 25; r++) tt += iv[r] * __ldg(cb + r);
                w += ed[168] * tt;
            }
            sW[pix * 104 + t] = w;
        }
        __syncthreads();

        // pass3
        {
            int pix = tid >> 6, ch = tid & 63, h = ch >> 3;
            const float* w = sW + pix * 104 + h * 13;
            const int* sm = sSlot[pix];
            float acc = 0.f;
#pragma unroll
            for (int c = 0; c < 13; c++) acc += w[c] * sQ[sm[c] * SLOT_STRIDE + 128 + ch];
#pragma unroll
            for (int s = 0; s < 12; s++) acc += sQ[sm[s] * SLOT_STRIDE + 192 + ch];
            g_osum[(size_t)(base + pix) * 64 + ch] = acc;
        }
    } else {
        // ================= boundary path =================
        float* sCB = sED + 1360;   // overlay (ED uses [0,1352))
        int t = blockIdx.x - NBI;
        int b = t / 496, u = t - b * 496;
        int h0, w0;
        if (u < 128)      { h0 = u >> 6; w0 = u & 63; }
        else if (u < 256) { int v = u - 128; h0 = 62 + (v >> 6); w0 = v & 63; }
        else              { int v = u - 256; h0 = 2 + v / 4; int c = v & 3; w0 = (c < 2) ? c : (60 + c); }
        int p = (b << 12) + (h0 << 6) + w0;

        if (tid < 25) {
            int ri = tid / 5 - 2, ci = tid % 5 - 2;
            int nh = h0 + ri, nw = w0 + ci;
            int ok = (tid < 12) && nh >= 0 && nh < 64 && nw >= 0 && nw < 64;
            sMap[tid] = ok ? tid : 12;
            if (tid < 13) sOff[tid] = -1;
            if (ok) sOff[tid] = ((b << 12) + (nh << 6) + nw) * 256;
        }
        __syncthreads();

        for (int i = tid; i < 13 * 64; i += 256) {
            int slot = i >> 6, j = i & 63;
            int off = sOff[slot];
            float4 v;
            if (off >= 0)    v = *(const float4*)(g_y + off + j * 4);
            else if (j < 48) v = *(const float4*)(g_const + j * 4);
            else             v = make_float4(0.f, 0.f, 0.f, 0.f);
            *(float4*)(sQ + slot * SLOT_STRIDE + j * 4) = v;
        }
        __syncthreads();

        if (tid < 104) {
            int h = tid / 13, qi = tid % 13;
            float4 qa = *(const float4*)(sQ + qi * SLOT_STRIDE + h * 8);
            float4 qd = *(const float4*)(sQ + qi * SLOT_STRIDE + h * 8 + 4);
            float* ed = sED + h * 169 + qi * 13;
#pragma unroll
            for (int ki = 0; ki < 13; ki++) {
                const float* kb = sQ + ki * SLOT_STRIDE + 64 + h * 8;
                float4 ka = *(const float4*)kb;
                float4 kd = *(const float4*)(kb + 4);
                float dot = qa.x * ka.x + qa.y * ka.y + qa.z * ka.z + qa.w * ka.w
                          + qd.x * kd.x + qd.y * kd.y + qd.z * kd.z + qd.w * kd.w;
                ed[ki] = __expf(dot);
            }
        }
        __syncthreads();

        if (tid < 200) {
            int h = tid / 25, r = tid % 25;
            int qi = sMap[r];
            const float* eb = g_ebias + h * 625 + r * 25;
            const float* ed = sED + h * 169 + qi * 13;
            float den = 0.f, cb = 0.f;
#pragma unroll
            for (int col = 0; col < 25; col++) {
                int ki = sMap[col];
                float e = __ldg(eb + col);
                den += e * ed[ki];
                if (ki == 12) cb += e;
            }
            sInv[tid] = 1.f / den;
            sCB[tid] = cb;
        }
        __syncthreads();

        if (tid < 104) {
            int h = tid / 13, c = tid % 13;
            const float* ed = sED + h * 169;
            const float* iv = sInv + h * 25;
            float w = 0.f;
            if (c == 12) {
                const float* cb = sCB + h * 25;
#pragma unroll
                for (int r = 0; r < 25; r++) w += iv[r] * ed[sMap[r] * 13 + 12] * cb[r];
            } else if (sMap[c] == c) {
                const float* eb = g_ebias + h * 625 + c;
#pragma unroll
                for (int r = 0; r < 25; r++) w += iv[r] * ed[sMap[r] * 13 + c] * __ldg(eb + r * 25);
            }
            sW[tid] = w;
        }
        __syncthreads();

        if (tid < 64) {
            int h = tid >> 3;
            const float* w = sW + h * 13;
            float acc = 0.f;
#pragma unroll
            for (int c = 0; c < 13; c++) acc += w[c] * sQ[c * SLOT_STRIDE + 128 + tid];
#pragma unroll
            for (int s = 0; s < 12; s++) acc += sQ[s * SLOT_STRIDE + 192 + tid];
            g_osum[(size_t)p * 64 + tid] = acc;
        }
    }
}

// ---- k3: fused LN2+MLP+proj, smem-staged weights. block = 32 pixels, 256 thr.
//      lane = pixel, warp = output slice; weights staged once per block. ----
__global__ __launch_bounds__(256) void k3(const float* __restrict__ n2w, const float* __restrict__ n2b,
                                          const float* __restrict__ b1, const float* __restrict__ b2,
                                          const float* __restrict__ pb, float* __restrict__ out) {
    extern __shared__ float smem[];
    float* sWt = smem;                  // 16384 floats: w1T / w2T / projT staging
    float* sA  = smem + 16384;          // 32 x 65: LN values, later y
    float* sH  = sA + 32 * 65;          // 32 x 257: gelu activations
    int tid = threadIdx.x, lane = tid & 31, w = tid >> 5;
    int p0 = blockIdx.x * 32;

    // stage w1T (64KB)
    {
        const float4* src = (const float4*)g_w1T;
        float4* dst = (float4*)sWt;
        for (int i = tid; i < 4096; i += 256) dst[i] = src[i];
    }
    // LN: warp w handles pixels w*4 .. w*4+3
#pragma unroll
    for (int t = 0; t < 4; t++) {
        int pix = w * 4 + t;
        const float* os = g_osum + (size_t)(p0 + pix) * 64;
        float x0 = os[lane], x1 = os[lane + 32];
        float m  = wsum(x0 + x1) * (1.f / 64.f);
        float vv = wsum(x0 * x0 + x1 * x1) * (1.f / 64.f) - m * m;
        float rs = rsqrtf(vv + 1e-5f);
        sA[pix * 65 + lane]      = (x0 - m) * rs * n2w[lane] + n2b[lane];
        sA[pix * 65 + lane + 32] = (x0 = (x1 - m) * rs * n2w[lane + 32] + n2b[lane + 32], x0);
    }
    __syncthreads();

    // fc1: lane = pixel, warp owns outputs [32w, 32w+32)
    float acc[32];
#pragma unroll
    for (int j = 0; j < 32; j++) acc[j] = 0.f;
    {
        const float* aRow = sA + lane * 65;
        const float* wBase = sWt + w * 32;
        for (int k = 0; k < 64; k++) {
            float a = aRow[k];
            const float4* wr = (const float4*)(wBase + k * 256);
#pragma unroll
            for (int j4 = 0; j4 < 8; j4++) {
                float4 wv = wr[j4];
                acc[4 * j4 + 0] += wv.x * a;
                acc[4 * j4 + 1] += wv.y * a;
                acc[4 * j4 + 2] += wv.z * a;
                acc[4 * j4 + 3] += wv.w * a;
            }
        }
    }
    // bias + gelu -> sH
    {
        float* hRow = sH + lane * 257 + w * 32;
#pragma unroll
        for (int j4 = 0; j4 < 8; j4++) {
            float4 bv = __ldg((const float4*)(b1 + w * 32 + 4 * j4));
            float v0 = acc[4 * j4 + 0] + bv.x;
            float v1 = acc[4 * j4 + 1] + bv.y;
            float v2 = acc[4 * j4 + 2] + bv.z;
            float v3 = acc[4 * j4 + 3] + bv.w;
            hRow[4 * j4 + 0] = 0.5f * v0 * (1.f + erff(v0 * 0.70710678118f));
            hRow[4 * j4 + 1] = 0.5f * v1 * (1.f + erff(v1 * 0.70710678118f));
            hRow[4 * j4 + 2] = 0.5f * v2 * (1.f + erff(v2 * 0.70710678118f));
            hRow[4 * j4 + 3] = 0.5f * v3 * (1.f + erff(v3 * 0.70710678118f));
        }
    }
    __syncthreads();

    // stage w2T (64KB)
    {
        const float4* src = (const float4*)g_w2T;
        float4* dst = (float4*)sWt;
        for (int i = tid; i < 4096; i += 256) dst[i] = src[i];
    }
    __syncthreads();

    // fc2: lane = pixel, warp owns outputs [8w, 8w+8)
    float a2[8];
#pragma unroll
    for (int j = 0; j < 8; j++) a2[j] = 0.f;
    {
        const float* hRow = sH + lane * 257;
        const float* wBase = sWt + w * 8;
        for (int k = 0; k < 256; k++) {
            float hv = hRow[k];
            float4 w0 = *(const float4*)(wBase + k * 64);
            float4 w1v = *(const float4*)(wBase + k * 64 + 4);
            a2[0] += w0.x * hv; a2[1] += w0.y * hv; a2[2] += w0.z * hv; a2[3] += w0.w * hv;
            a2[4] += w1v.x * hv; a2[5] += w1v.y * hv; a2[6] += w1v.z * hv; a2[7] += w1v.w * hv;
        }
    }
    // + b2 + residual -> y in sA
    {
        float4 bva = __ldg((const float4*)(b2 + w * 8));
        float4 bvb = __ldg((const float4*)(b2 + w * 8 + 4));
        const float* os = g_osum + (size_t)(p0 + lane) * 64 + w * 8;
        float4 ra = __ldg((const float4*)os);
        float4 rb = __ldg((const float4*)(os + 4));
        float* yRow = sA + lane * 65 + w * 8;
        yRow[0] = a2[0] + bva.x + ra.x;
        yRow[1] = a2[1] + bva.y + ra.y;
        yRow[2] = a2[2] + bva.z + ra.z;
        yRow[3] = a2[3] + bva.w + ra.w;
        yRow[4] = a2[4] + bvb.x + rb.x;
        yRow[5] = a2[5] + bvb.y + rb.y;
        yRow[6] = a2[6] + bvb.z + rb.z;
        yRow[7] = a2[7] + bvb.w + rb.w;
    }
    __syncthreads();

    // stage projT (16KB)
    {
        const float4* src = (const float4*)g_projT;
        float4* dst = (float4*)sWt;
        for (int i = tid; i < 1024; i += 256) dst[i] = src[i];
    }
    __syncthreads();

    // proj: lane = pixel, warp owns outputs [8w, 8w+8)
    float a3[8];
#pragma unroll
    for (int j = 0; j < 8; j++) a3[j] = 0.f;
    {
        const float* yRow = sA + lane * 65;
        const float* wBase = sWt + w * 8;
        for (int k = 0; k < 64; k++) {
            float yv = yRow[k];
            float4 w0 = *(const float4*)(wBase + k * 64);
            float4 w1v = *(const float4*)(wBase + k * 64 + 4);
            a3[0] += w0.x * yv; a3[1] += w0.y * yv; a3[2] += w0.z * yv; a3[3] += w0.w * yv;
            a3[4] += w1v.x * yv; a3[5] += w1v.y * yv; a3[6] += w1v.z * yv; a3[7] += w1v.w * yv;
        }
    }
    {
        float4 pa = __ldg((const float4*)(pb + w * 8));
        float4 pbv = __ldg((const float4*)(pb + w * 8 + 4));
        int wid = p0 + lane;
        int b = wid >> 12, hw = wid & 4095;
        float* ob = out + (size_t)b * 262144 + hw;
        ob[(size_t)(w * 8 + 0) * 4096] = a3[0] + pa.x;
        ob[(size_t)(w * 8 + 1) * 4096] = a3[1] + pa.y;
        ob[(size_t)(w * 8 + 2) * 4096] = a3[2] + pa.z;
        ob[(size_t)(w * 8 + 3) * 4096] = a3[3] + pa.w;
        ob[(size_t)(w * 8 + 4) * 4096] = a3[4] + pbv.x;
        ob[(size_t)(w * 8 + 5) * 4096] = a3[5] + pbv.y;
        ob[(size_t)(w * 8 + 6) * 4096] = a3[6] + pbv.z;
        ob[(size_t)(w * 8 + 7) * 4096] = a3[7] + pbv.w;
    }
}

extern "C" void kernel_launch(void* const* d_in, const int* in_sizes, int n_in,
                              void* d_out, int out_size) {
    const float* x    = (const float*)d_in[0];
    const float* n1w  = (const float*)d_in[1];
    const float* n1b  = (const float*)d_in[2];
    const float* qw   = (const float*)d_in[3];
    const float* qb   = (const float*)d_in[4];
    const float* rpb  = (const float*)d_in[5];
    const float* n2w  = (const float*)d_in[6];
    const float* n2b  = (const float*)d_in[7];
    const float* w1   = (const float*)d_in[8];
    const float* b1   = (const float*)d_in[9];
    const float* w2   = (const float*)d_in[10];
    const float* b2   = (const float*)d_in[11];
    const float* pw   = (const float*)d_in[12];
    const float* pb   = (const float*)d_in[13];
    float* out = (float*)d_out;

    cudaFuncSetAttribute(k3, cudaFuncAttributeMaxDynamicSharedMemorySize, K3_SMEM);

    prep<<<64, 256>>>(qw, w1, w2, pw, rpb, n1b, qb);
    k1<<<256, 256>>>(x, n1w, n1b, qb);
    k2<<<NBI + NBB, 256>>>();
    k3<<<512, 256, K3_SMEM>>>(n2w, n2b, b1, b2, pb, out);
}

// round 12
// speedup vs baseline: 2.7495x; 1.0217x over previous
#include <cuda_runtime.h>
#include <math.h>

#define NPIX 16384
#define QSCALE 0.35355339059327373f
#define SLOT_STRIDE 260
#define NBI 3600   // interior blocks
#define NBB 1984   // boundary blocks
#define K3_SMEM ((8192 + 32 * 65 + 32 * 257) * 4)

__device__ __align__(16) float g_y[NPIX * 256];   // per pixel: q*s | k | v | raw x
__device__ __align__(16) float g_osum[NPIX * 64];
__device__ __align__(16) float g_const[192];      // qkv row for masked/OOB slots
__device__ float g_qwT[64 * 192];                 // [c][o]
__device__ __align__(16) float g_w1T[64 * 256];   // [c][u]
__device__ __align__(16) float g_w2T[256 * 64];   // [u][o]
__device__ __align__(16) float g_projT[64 * 64];  // [c][o]
__device__ __align__(16) float g_ebias[8 * 25 * 25];   // exp(bias) full (boundary)
__device__ __align__(16) float g_eb12[8 * 25 * 12];    // exp(bias)[h][r][c<12] (interior)
__device__ float g_cb[8 * 25];                    // sum_{c>=12} exp(bias)

__device__ __forceinline__ float wsum(float v) {
#pragma unroll
    for (int o = 16; o; o >>= 1) v += __shfl_xor_sync(0xffffffffu, v, o);
    return v;
}

// ---- prep: transposed weights + exp(bias) tables + const qkv row ----
__global__ void prep(const float* __restrict__ qw, const float* __restrict__ w1,
                     const float* __restrict__ w2, const float* __restrict__ pw,
                     const float* __restrict__ rpb,
                     const float* __restrict__ n1b, const float* __restrict__ qb) {
    for (int i = blockIdx.x * blockDim.x + threadIdx.x; i < 56944; i += gridDim.x * blockDim.x) {
        if (i < 12288) { int c = i / 192, o = i % 192; g_qwT[i] = qw[o * 64 + c]; }
        else if (i < 28672) { int j = i - 12288; int c = j / 256, u = j % 256; g_w1T[j] = w1[u * 64 + c]; }
        else if (i < 45056) { int j = i - 28672; int u = j / 64, c = j % 64; g_w2T[j] = w2[c * 256 + u]; }
        else if (i < 49152) { int j = i - 45056; int c = j / 64, o = j % 64; g_projT[j] = pw[o * 64 + c]; }
        else if (i < 54152) {
            int j = i - 49152; int h = j / 625, r = j % 625; int qi = r / 25, kj = r % 25;
            int idx = (qi / 5 - kj / 5 + 4) * 9 + (qi % 5 - kj % 5 + 4);
            g_ebias[j] = __expf(rpb[idx * 8 + h]);
        } else if (i < 56552) {
            int j = i - 54152; int h = j / 300, rem = j % 300; int r = rem / 12, c = rem % 12;
            int idx = (r / 5 - c / 5 + 4) * 9 + (r % 5 - c % 5 + 4);
            g_eb12[j] = __expf(rpb[idx * 8 + h]);
        } else if (i < 56752) {
            int j = i - 56552; int h = j / 25, r = j % 25;
            float s = 0.f;
            for (int c = 12; c < 25; c++) {
                int idx = (r / 5 - c / 5 + 4) * 9 + (r % 5 - c % 5 + 4);
                s += __expf(rpb[idx * 8 + h]);
            }
            g_cb[j] = s;
        } else {
            int o = i - 56752;   // const qkv row: LN(0) = n1b
            float a = qb[o];
            for (int c = 0; c < 64; c++) a += n1b[c] * qw[o * 64 + c];
            if (o < 64) a *= QSCALE;
            g_const[o] = a;
        }
    }
}

// ---- k1: LN1 + QKV, register-tiled: block=64 pixels, warp=8 pixels ----
__global__ __launch_bounds__(256) void k1(const float* __restrict__ x,
                                          const float* __restrict__ n1w,
                                          const float* __restrict__ n1b,
                                          const float* __restrict__ qb) {
    __shared__ float sLn[64][65];
    int tid = threadIdx.x, lane = tid & 31, w = tid >> 5;
    int p0 = blockIdx.x * 64;
    float nw0 = n1w[lane], nw1 = n1w[lane + 32];
    float nb0 = n1b[lane], nb1 = n1b[lane + 32];
#pragma unroll
    for (int t = 0; t < 8; t++) {
        int wid = p0 + w * 8 + t;
        int b = wid >> 12, hw = wid & 4095;
        const float* xb = x + (size_t)b * 262144 + hw;
        float x0 = __ldg(xb + (size_t)lane * 4096);
        float x1 = __ldg(xb + (size_t)(lane + 32) * 4096);
        float m  = wsum(x0 + x1) * (1.f / 64.f);
        float vv = wsum(x0 * x0 + x1 * x1) * (1.f / 64.f) - m * m;
        float rs = rsqrtf(vv + 1e-5f);
        sLn[w * 8 + t][lane]      = (x0 - m) * rs * nw0 + nb0;
        sLn[w * 8 + t][lane + 32] = (x1 - m) * rs * nw1 + nb1;
        float* yp = g_y + (size_t)wid * 256;
        yp[192 + lane] = x0; yp[224 + lane] = x1;
    }
    __syncwarp();
    float acc[6][8];
#pragma unroll
    for (int k = 0; k < 6; k++)
#pragma unroll
        for (int j = 0; j < 8; j++) acc[k][j] = 0.f;
    for (int c = 0; c < 64; c++) {
        float wv[6];
        const float* wr = g_qwT + c * 192 + lane;
#pragma unroll
        for (int k = 0; k < 6; k++) wv[k] = wr[32 * k];
#pragma unroll
        for (int j = 0; j < 8; j++) {
            float l = sLn[w * 8 + j][c];
#pragma unroll
            for (int k = 0; k < 6; k++) acc[k][j] += wv[k] * l;
        }
    }
#pragma unroll
    for (int k = 0; k < 6; k++) {
        int o = lane + 32 * k;
        float bias = qb[o];
        float sc = (o < 64) ? QSCALE : 1.f;
#pragma unroll
        for (int j = 0; j < 8; j++)
            g_y[(size_t)(p0 + w * 8 + j) * 256 + o] = (acc[k][j] + bias) * sc;
    }
}

// ---- k2: merged window attention. blocks [0,NBI): interior 4-pixel strips;
//      blocks [NBI, NBI+NBB): boundary single pixels (generic masked path). ----
__global__ __launch_bounds__(256, 4) void k2() {
    __shared__ float sQ[22 * SLOT_STRIDE];
    __shared__ float sED[4 * 1352];     // boundary overlays its CB scratch at +1360
    __shared__ float sInv[4 * 200];
    __shared__ float sW[4 * 104];
    __shared__ int   sSlot[4][13];
    __shared__ int   sMap[25];
    __shared__ int   sOff[13];

    int tid = threadIdx.x;

    if (blockIdx.x < NBI) {
        // ================= interior path =================
        int idx = blockIdx.x;
        int b = idx / 900, rem = idx - b * 900;
        int h0 = 2 + rem / 15, w0 = 2 + (rem % 15) * 4;
        int base = (b << 12) + (h0 << 6) + w0;

        if (tid < 52) {
            int j = tid / 13, ls = tid - j * 13;
            int g = (ls < 5) ? ls + j : (ls < 10) ? 8 + (ls - 5) + j : (ls < 12) ? 16 + (ls - 10) + j : 21;
            sSlot[j][ls] = g;
        }
        for (int i = tid; i < 22 * 64; i += 256) {
            int slot = i >> 6, jj = i & 63;
            float4 v;
            if (slot < 21) {
                int row, col;
                if (slot < 16) { row = slot >> 3; col = slot & 7; }
                else { row = 2; col = slot - 16; }
                int pp = base + (row - 2) * 64 + (col - 2);
                v = *(const float4*)(g_y + (size_t)pp * 256 + jj * 4);
            } else {
                v = (jj < 48) ? *(const float4*)(g_const + jj * 4) : make_float4(0.f, 0.f, 0.f, 0.f);
            }
            *(float4*)(sQ + slot * SLOT_STRIDE + jj * 4) = v;
        }
        __syncthreads();

        // dots: broadcast-k scheme, half-warp group per (pix,h) pair
        {
            int w = tid >> 5, lane = tid & 31;
            int grp = lane >> 4, qi = lane & 15;
            bool act = qi < 13;
#pragma unroll
            for (int it = 0; it < 2; it++) {
                int pairidx = w * 4 + it * 2 + grp;
                int pix = pairidx >> 3, h = pairidx & 7;
                const int* sm = sSlot[pix];
                float4 qa = make_float4(0.f, 0.f, 0.f, 0.f), qd = qa;
                if (act) {
                    int gq = sm[qi];
                    qa = *(const float4*)(sQ + gq * SLOT_STRIDE + h * 8);
                    qd = *(const float4*)(sQ + gq * SLOT_STRIDE + h * 8 + 4);
                }
                float* ed = sED + pix * 1352 + h * 169 + qi * 13;
#pragma unroll
                for (int ki = 0; ki < 13; ki++) {
                    const float* kb = sQ + sm[ki] * SLOT_STRIDE + 64 + h * 8;
                    float4 ka = *(const float4*)kb;
                    float4 kd = *(const float4*)(kb + 4);
                    float dot = qa.x * ka.x + qa.y * ka.y + qa.z * ka.z + qa.w * ka.w
                              + qd.x * kd.x + qd.y * kd.y + qd.z * kd.z + qd.w * kd.w;
                    if (act) ed[ki] = __expf(dot);
                }
            }
        }
        __syncthreads();

        // pass1
        for (int i = tid; i < 800; i += 256) {
            int pix = i / 200, t = i - pix * 200;
            int h = t / 25, r = t - h * 25;
            int qi = (r < 12) ? r : 12;
            const float* ed = sED + pix * 1352 + h * 169 + qi * 13;
            const float* eb = g_eb12 + h * 300 + r * 12;
            float4 e0 = __ldg((const float4*)eb);
            float4 e1 = __ldg((const float4*)(eb + 4));
            float4 e2 = __ldg((const float4*)(eb + 8));
            float den = __ldg(g_cb + h * 25 + r) * ed[12];
            den += e0.x * ed[0] + e0.y * ed[1] + e0.z * ed[2] + e0.w * ed[3];
            den += e1.x * ed[4] + e1.y * ed[5] + e1.z * ed[6] + e1.w * ed[7];
            den += e2.x * ed[8] + e2.y * ed[9] + e2.z * ed[10] + e2.w * ed[11];
            sInv[pix * 200 + t] = 1.f / den;
        }
        __syncthreads();

        // pass2
        for (int i = tid; i < 416; i += 256) {
            int pix = i / 104, t = i - pix * 104;
            int h = t / 13, c = t - h * 13;
            const float* ed = sED + pix * 1352 + h * 169;
            const float* iv = sInv + pix * 200 + h * 25;
            float w = 0.f, tt = 0.f;
            if (c < 12) {
                const float* eb = g_eb12 + h * 300 + c;
#pragma unroll
                for (int r = 0; r < 12; r++) w += iv[r] * ed[r * 13 + c] * __ldg(eb + r * 12);
#pragma unroll
                for (int r = 12; r < 25; r++) tt += iv[r] * __ldg(eb + r * 12);
                w += ed[156 + c] * tt;
            } else {
                const float* cb = g_cb + h * 25;
#pragma unroll
                for (int r = 0; r < 12; r++) w += iv[r] * ed[r * 13 + 12] * __ldg(cb + r);
#pragma unroll
                for (int r = 12; r < 25; r++) tt += iv[r] * __ldg(cb + r);
                w += ed[168] * tt;
            }
            sW[pix * 104 + t] = w;
        }
        __syncthreads();

        // pass3
        {
            int pix = tid >> 6, ch = tid & 63, h = ch >> 3;
            const float* w = sW + pix * 104 + h * 13;
            const int* sm = sSlot[pix];
            float acc = 0.f;
#pragma unroll
            for (int c = 0; c < 13; c++) acc += w[c] * sQ[sm[c] * SLOT_STRIDE + 128 + ch];
#pragma unroll
            for (int s = 0; s < 12; s++) acc += sQ[sm[s] * SLOT_STRIDE + 192 + ch];
            g_osum[(size_t)(base + pix) * 64 + ch] = acc;
        }
    } else {
        // ================= boundary path =================
        float* sCB = sED + 1360;   // overlay (ED uses [0,1352))
        int t = blockIdx.x - NBI;
        int b = t / 496, u = t - b * 496;
        int h0, w0;
        if (u < 128)      { h0 = u >> 6; w0 = u & 63; }
        else if (u < 256) { int v = u - 128; h0 = 62 + (v >> 6); w0 = v & 63; }
        else              { int v = u - 256; h0 = 2 + v / 4; int c = v & 3; w0 = (c < 2) ? c : (60 + c); }
        int p = (b << 12) + (h0 << 6) + w0;

        if (tid < 25) {
            int ri = tid / 5 - 2, ci = tid % 5 - 2;
            int nh = h0 + ri, nw = w0 + ci;
            int ok = (tid < 12) && nh >= 0 && nh < 64 && nw >= 0 && nw < 64;
            sMap[tid] = ok ? tid : 12;
            if (tid < 13) sOff[tid] = -1;
            if (ok) sOff[tid] = ((b << 12) + (nh << 6) + nw) * 256;
        }
        __syncthreads();

        for (int i = tid; i < 13 * 64; i += 256) {
            int slot = i >> 6, j = i & 63;
            int off = sOff[slot];
            float4 v;
            if (off >= 0)    v = *(const float4*)(g_y + off + j * 4);
            else if (j < 48) v = *(const float4*)(g_const + j * 4);
            else             v = make_float4(0.f, 0.f, 0.f, 0.f);
            *(float4*)(sQ + slot * SLOT_STRIDE + j * 4) = v;
        }
        __syncthreads();

        if (tid < 104) {
            int h = tid / 13, qi = tid % 13;
            float4 qa = *(const float4*)(sQ + qi * SLOT_STRIDE + h * 8);
            float4 qd = *(const float4*)(sQ + qi * SLOT_STRIDE + h * 8 + 4);
            float* ed = sED + h * 169 + qi * 13;
#pragma unroll
            for (int ki = 0; ki < 13; ki++) {
                const float* kb = sQ + ki * SLOT_STRIDE + 64 + h * 8;
                float4 ka = *(const float4*)kb;
                float4 kd = *(const float4*)(kb + 4);
                float dot = qa.x * ka.x + qa.y * ka.y + qa.z * ka.z + qa.w * ka.w
                          + qd.x * kd.x + qd.y * kd.y + qd.z * kd.z + qd.w * kd.w;
                ed[ki] = __expf(dot);
            }
        }
        __syncthreads();

        if (tid < 200) {
            int h = tid / 25, r = tid % 25;
            int qi = sMap[r];
            const float* eb = g_ebias + h * 625 + r * 25;
            const float* ed = sED + h * 169 + qi * 13;
            float den = 0.f, cb = 0.f;
#pragma unroll
            for (int col = 0; col < 25; col++) {
                int ki = sMap[col];
                float e = __ldg(eb + col);
                den += e * ed[ki];
                if (ki == 12) cb += e;
            }
            sInv[tid] = 1.f / den;
            sCB[tid] = cb;
        }
        __syncthreads();

        if (tid < 104) {
            int h = tid / 13, c = tid % 13;
            const float* ed = sED + h * 169;
            const float* iv = sInv + h * 25;
            float w = 0.f;
            if (c == 12) {
                const float* cb = sCB + h * 25;
#pragma unroll
                for (int r = 0; r < 25; r++) w += iv[r] * ed[sMap[r] * 13 + 12] * cb[r];
            } else if (sMap[c] == c) {
                const float* eb = g_ebias + h * 625 + c;
#pragma unroll
                for (int r = 0; r < 25; r++) w += iv[r] * ed[sMap[r] * 13 + c] * __ldg(eb + r * 25);
            }
            sW[tid] = w;
        }
        __syncthreads();

        if (tid < 64) {
            int h = tid >> 3;
            const float* w = sW + h * 13;
            float acc = 0.f;
#pragma unroll
            for (int c = 0; c < 13; c++) acc += w[c] * sQ[c * SLOT_STRIDE + 128 + tid];
#pragma unroll
            for (int s = 0; s < 12; s++) acc += sQ[s * SLOT_STRIDE + 192 + tid];
            g_osum[(size_t)p * 64 + tid] = acc;
        }
    }
}

// ---- k3: fused LN2+MLP+proj, chunked smem weight staging (32KB chunks).
//      block = 32 pixels, 256 thr; lane = pixel, warp = output slice. ----
__global__ __launch_bounds__(256) void k3(const float* __restrict__ n2w, const float* __restrict__ n2b,
                                          const float* __restrict__ b1, const float* __restrict__ b2,
                                          const float* __restrict__ pb, float* __restrict__ out) {
    extern __shared__ float smem[];
    float* sWt = smem;                  // 8192 floats: weight staging chunk (32KB)
    float* sA  = smem + 8192;           // 32 x 65: LN values, later y
    float* sH  = sA + 32 * 65;          // 32 x 257: gelu activations
    int tid = threadIdx.x, lane = tid & 31, w = tid >> 5;
    int p0 = blockIdx.x * 32;

    // LN: warp w handles pixels w*4 .. w*4+3
#pragma unroll
    for (int t = 0; t < 4; t++) {
        int pix = w * 4 + t;
        const float* os = g_osum + (size_t)(p0 + pix) * 64;
        float x0 = os[lane], x1 = os[lane + 32];
        float m  = wsum(x0 + x1) * (1.f / 64.f);
        float vv = wsum(x0 * x0 + x1 * x1) * (1.f / 64.f) - m * m;
        float rs = rsqrtf(vv + 1e-5f);
        sA[pix * 65 + lane]      = (x0 - m) * rs * n2w[lane] + n2b[lane];
        sA[pix * 65 + lane + 32] = (x1 - m) * rs * n2w[lane + 32] + n2b[lane + 32];
    }

    // fc1: lane = pixel, warp owns outputs [32w, 32w+32); w1T staged in 2 halves
    float acc[32];
#pragma unroll
    for (int j = 0; j < 32; j++) acc[j] = 0.f;
#pragma unroll
    for (int half = 0; half < 2; half++) {
        __syncthreads();   // prior consumers (and LN writes on first iter) done
        {
            const float4* src = (const float4*)(g_w1T + half * 32 * 256);
            float4* dst = (float4*)sWt;
            for (int i = tid; i < 2048; i += 256) dst[i] = src[i];
        }
        __syncthreads();
        const float* aRow = sA + lane * 65 + half * 32;
        const float* wBase = sWt + w * 32;
        for (int k = 0; k < 32; k++) {
            float a = aRow[k];
            const float4* wr = (const float4*)(wBase + k * 256);
#pragma unroll
            for (int j4 = 0; j4 < 8; j4++) {
                float4 wv = wr[j4];
                acc[4 * j4 + 0] += wv.x * a;
                acc[4 * j4 + 1] += wv.y * a;
                acc[4 * j4 + 2] += wv.z * a;
                acc[4 * j4 + 3] += wv.w * a;
            }
        }
    }
    // bias + gelu -> sH
    {
        float* hRow = sH + lane * 257 + w * 32;
#pragma unroll
        for (int j4 = 0; j4 < 8; j4++) {
            float4 bv = __ldg((const float4*)(b1 + w * 32 + 4 * j4));
            float v0 = acc[4 * j4 + 0] + bv.x;
            float v1 = acc[4 * j4 + 1] + bv.y;
            float v2 = acc[4 * j4 + 2] + bv.z;
            float v3 = acc[4 * j4 + 3] + bv.w;
            hRow[4 * j4 + 0] = 0.5f * v0 * (1.f + erff(v0 * 0.70710678118f));
            hRow[4 * j4 + 1] = 0.5f * v1 * (1.f + erff(v1 * 0.70710678118f));
            hRow[4 * j4 + 2] = 0.5f * v2 * (1.f + erff(v2 * 0.70710678118f));
            hRow[4 * j4 + 3] = 0.5f * v3 * (1.f + erff(v3 * 0.70710678118f));
        }
    }

    // fc2: lane = pixel, warp owns outputs [8w, 8w+8); w2T staged in 2 halves
    float a2[8];
#pragma unroll
    for (int j = 0; j < 8; j++) a2[j] = 0.f;
#pragma unroll
    for (int half = 0; half < 2; half++) {
        __syncthreads();   // sH writes / prior consumers done
        {
            const float4* src = (const float4*)(g_w2T + half * 128 * 64);
            float4* dst = (float4*)sWt;
            for (int i = tid; i < 2048; i += 256) dst[i] = src[i];
        }
        __syncthreads();
        const float* hRow = sH + lane * 257 + half * 128;
        const float* wBase = sWt + w * 8;
        for (int k = 0; k < 128; k++) {
            float hv = hRow[k];
            float4 w0 = *(const float4*)(wBase + k * 64);
            float4 w1v = *(const float4*)(wBase + k * 64 + 4);
            a2[0] += w0.x * hv; a2[1] += w0.y * hv; a2[2] += w0.z * hv; a2[3] += w0.w * hv;
            a2[4] += w1v.x * hv; a2[5] += w1v.y * hv; a2[6] += w1v.z * hv; a2[7] += w1v.w * hv;
        }
    }
    // + b2 + residual -> y in sA (sA's LN values no longer needed)
    __syncthreads();
    {
        float4 bva = __ldg((const float4*)(b2 + w * 8));
        float4 bvb = __ldg((const float4*)(b2 + w * 8 + 4));
        const float* os = g_osum + (size_t)(p0 + lane) * 64 + w * 8;
        float4 ra = __ldg((const float4*)os);
        float4 rb = __ldg((const float4*)(os + 4));
        float* yRow = sA + lane * 65 + w * 8;
        yRow[0] = a2[0] + bva.x + ra.x;
        yRow[1] = a2[1] + bva.y + ra.y;
        yRow[2] = a2[2] + bva.z + ra.z;
        yRow[3] = a2[3] + bva.w + ra.w;
        yRow[4] = a2[4] + bvb.x + rb.x;
        yRow[5] = a2[5] + bvb.y + rb.y;
        yRow[6] = a2[6] + bvb.z + rb.z;
        yRow[7] = a2[7] + bvb.w + rb.w;
    }
    __syncthreads();

    // stage projT (16KB, single chunk)
    {
        const float4* src = (const float4*)g_projT;
        float4* dst = (float4*)sWt;
        for (int i = tid; i < 1024; i += 256) dst[i] = src[i];
    }
    __syncthreads();

    // proj: lane = pixel, warp owns outputs [8w, 8w+8)
    float a3[8];
#pragma unroll
    for (int j = 0; j < 8; j++) a3[j] = 0.f;
    {
        const float* yRow = sA + lane * 65;
        const float* wBase = sWt + w * 8;
        for (int k = 0; k < 64; k++) {
            float yv = yRow[k];
            float4 w0 = *(const float4*)(wBase + k * 64);
            float4 w1v = *(const float4*)(wBase + k * 64 + 4);
            a3[0] += w0.x * yv; a3[1] += w0.y * yv; a3[2] += w0.z * yv; a3[3] += w0.w * yv;
            a3[4] += w1v.x * yv; a3[5] += w1v.y * yv; a3[6] += w1v.z * yv; a3[7] += w1v.w * yv;
        }
    }
    {
        float4 pa = __ldg((const float4*)(pb + w * 8));
        float4 pbv = __ldg((const float4*)(pb + w * 8 + 4));
        int wid = p0 + lane;
        int b = wid >> 12, hw = wid & 4095;
        float* ob = out + (size_t)b * 262144 + hw;
        ob[(size_t)(w * 8 + 0) * 4096] = a3[0] + pa.x;
        ob[(size_t)(w * 8 + 1) * 4096] = a3[1] + pa.y;
        ob[(size_t)(w * 8 + 2) * 4096] = a3[2] + pa.z;
        ob[(size_t)(w * 8 + 3) * 4096] = a3[3] + pa.w;
        ob[(size_t)(w * 8 + 4) * 4096] = a3[4] + pbv.x;
        ob[(size_t)(w * 8 + 5) * 4096] = a3[5] + pbv.y;
        ob[(size_t)(w * 8 + 6) * 4096] = a3[6] + pbv.z;
        ob[(size_t)(w * 8 + 7) * 4096] = a3[7] + pbv.w;
    }
}

extern "C" void kernel_launch(void* const* d_in, const int* in_sizes, int n_in,
                              void* d_out, int out_size) {
    const float* x    = (const float*)d_in[0];
    const float* n1w  = (const float*)d_in[1];
    const float* n1b  = (const float*)d_in[2];
    const float* qw   = (const float*)d_in[3];
    const float* qb   = (const float*)d_in[4];
    const float* rpb  = (const float*)d_in[5];
    const float* n2w  = (const float*)d_in[6];
    const float* n2b  = (const float*)d_in[7];
    const float* w1   = (const float*)d_in[8];
    const float* b1   = (const float*)d_in[9];
    const float* w2   = (const float*)d_in[10];
    const float* b2   = (const float*)d_in[11];
    const float* pw   = (const float*)d_in[12];
    const float* pb   = (const float*)d_in[13];
    float* out = (float*)d_out;

    cudaFuncSetAttribute(k3, cudaFuncAttributeMaxDynamicSharedMemorySize, K3_SMEM);

    prep<<<64, 256>>>(qw, w1, w2, pw, rpb, n1b, qb);
    k1<<<256, 256>>>(x, n1w, n1b, qb);
    k2<<<NBI + NBB, 256>>>();
    k3<<<512, 256, K3_SMEM>>>(n2w, n2b, b1, b2, pb, out);
}

// round 13
// speedup vs baseline: 2.7542x; 1.0017x over previous
#include <cuda_runtime.h>
#include <math.h>

#define NPIX 16384
#define QSCALE 0.35355339059327373f
#define SLOT_STRIDE 260
#define NBI 3600   // interior blocks
#define NBB 1984   // boundary blocks
#define K3_SMEM ((8192 + 32 * 65 + 32 * 257) * 4)

__device__ __align__(16) float g_y[NPIX * 256];   // per pixel: q*s | k | v | raw x
__device__ __align__(16) float g_osum[NPIX * 64];
__device__ __align__(16) float g_const[192];      // qkv row for masked/OOB slots
__device__ float g_qwT[64 * 192];                 // [c][o]
__device__ __align__(16) float g_w1T[64 * 256];   // [c][u]
__device__ __align__(16) float g_w2T[256 * 64];   // [u][o]
__device__ __align__(16) float g_projT[64 * 64];  // [c][o]
__device__ __align__(16) float g_ebias[8 * 25 * 25];   // exp(bias) full (boundary)
__device__ __align__(16) float g_eb12[8 * 25 * 12];    // exp(bias)[h][r][c<12] (interior)
__device__ float g_cb[8 * 25];                    // sum_{c>=12} exp(bias)

__device__ __forceinline__ float wsum(float v) {
#pragma unroll
    for (int o = 16; o; o >>= 1) v += __shfl_xor_sync(0xffffffffu, v, o);
    return v;
}

// ---- packed fp32x2 helpers (FFMA2 path, sm_103a) ----
__device__ __forceinline__ unsigned long long pack2(float lo, float hi) {
    unsigned long long r;
    asm("mov.b64 %0, {%1, %2};" : "=l"(r) : "f"(lo), "f"(hi));
    return r;
}
__device__ __forceinline__ void fma2(unsigned long long& d, unsigned long long a, unsigned long long b) {
    asm("fma.rn.f32x2 %0, %1, %2, %0;" : "+l"(d) : "l"(a), "l"(b));
}
__device__ __forceinline__ float2 unpack2(unsigned long long v) {
    float lo, hi;
    asm("mov.b64 {%0, %1}, %2;" : "=f"(lo), "=f"(hi) : "l"(v));
    return make_float2(lo, hi);
}

// ---- prep: transposed weights + exp(bias) tables + const qkv row ----
__global__ void prep(const float* __restrict__ qw, const float* __restrict__ w1,
                     const float* __restrict__ w2, const float* __restrict__ pw,
                     const float* __restrict__ rpb,
                     const float* __restrict__ n1b, const float* __restrict__ qb) {
    for (int i = blockIdx.x * blockDim.x + threadIdx.x; i < 56944; i += gridDim.x * blockDim.x) {
        if (i < 12288) { int c = i / 192, o = i % 192; g_qwT[i] = qw[o * 64 + c]; }
        else if (i < 28672) { int j = i - 12288; int c = j / 256, u = j % 256; g_w1T[j] = w1[u * 64 + c]; }
        else if (i < 45056) { int j = i - 28672; int u = j / 64, c = j % 64; g_w2T[j] = w2[c * 256 + u]; }
        else if (i < 49152) { int j = i - 45056; int c = j / 64, o = j % 64; g_projT[j] = pw[o * 64 + c]; }
        else if (i < 54152) {
            int j = i - 49152; int h = j / 625, r = j % 625; int qi = r / 25, kj = r % 25;
            int idx = (qi / 5 - kj / 5 + 4) * 9 + (qi % 5 - kj % 5 + 4);
            g_ebias[j] = __expf(rpb[idx * 8 + h]);
        } else if (i < 56552) {
            int j = i - 54152; int h = j / 300, rem = j % 300; int r = rem / 12, c = rem % 12;
            int idx = (r / 5 - c / 5 + 4) * 9 + (r % 5 - c % 5 + 4);
            g_eb12[j] = __expf(rpb[idx * 8 + h]);
        } else if (i < 56752) {
            int j = i - 56552; int h = j / 25, r = j % 25;
            float s = 0.f;
            for (int c = 12; c < 25; c++) {
                int idx = (r / 5 - c / 5 + 4) * 9 + (r % 5 - c % 5 + 4);
                s += __expf(rpb[idx * 8 + h]);
            }
            g_cb[j] = s;
        } else {
            int o = i - 56752;   // const qkv row: LN(0) = n1b
            float a = qb[o];
            for (int c = 0; c < 64; c++) a += n1b[c] * qw[o * 64 + c];
            if (o < 64) a *= QSCALE;
            g_const[o] = a;
        }
    }
}

// ---- k1: LN1 + QKV, register-tiled: block=64 pixels, warp=8 pixels ----
__global__ __launch_bounds__(256) void k1(const float* __restrict__ x,
                                          const float* __restrict__ n1w,
                                          const float* __restrict__ n1b,
                                          const float* __restrict__ qb) {
    __shared__ float sLn[64][65];
    int tid = threadIdx.x, lane = tid & 31, w = tid >> 5;
    int p0 = blockIdx.x * 64;
    float nw0 = n1w[lane], nw1 = n1w[lane + 32];
    float nb0 = n1b[lane], nb1 = n1b[lane + 32];
#pragma unroll
    for (int t = 0; t < 8; t++) {
        int wid = p0 + w * 8 + t;
        int b = wid >> 12, hw = wid & 4095;
        const float* xb = x + (size_t)b * 262144 + hw;
        float x0 = __ldg(xb + (size_t)lane * 4096);
        float x1 = __ldg(xb + (size_t)(lane + 32) * 4096);
        float m  = wsum(x0 + x1) * (1.f / 64.f);
        float vv = wsum(x0 * x0 + x1 * x1) * (1.f / 64.f) - m * m;
        float rs = rsqrtf(vv + 1e-5f);
        sLn[w * 8 + t][lane]      = (x0 - m) * rs * nw0 + nb0;
        sLn[w * 8 + t][lane + 32] = (x1 - m) * rs * nw1 + nb1;
        float* yp = g_y + (size_t)wid * 256;
        yp[192 + lane] = x0; yp[224 + lane] = x1;
    }
    __syncwarp();
    float acc[6][8];
#pragma unroll
    for (int k = 0; k < 6; k++)
#pragma unroll
        for (int j = 0; j < 8; j++) acc[k][j] = 0.f;
    for (int c = 0; c < 64; c++) {
        float wv[6];
        const float* wr = g_qwT + c * 192 + lane;
#pragma unroll
        for (int k = 0; k < 6; k++) wv[k] = wr[32 * k];
#pragma unroll
        for (int j = 0; j < 8; j++) {
            float l = sLn[w * 8 + j][c];
#pragma unroll
            for (int k = 0; k < 6; k++) acc[k][j] += wv[k] * l;
        }
    }
#pragma unroll
    for (int k = 0; k < 6; k++) {
        int o = lane + 32 * k;
        float bias = qb[o];
        float sc = (o < 64) ? QSCALE : 1.f;
#pragma unroll
        for (int j = 0; j < 8; j++)
            g_y[(size_t)(p0 + w * 8 + j) * 256 + o] = (acc[k][j] + bias) * sc;
    }
}

// ---- k2: merged window attention. blocks [0,NBI): interior 4-pixel strips;
//      blocks [NBI, NBI+NBB): boundary single pixels (generic masked path). ----
__global__ __launch_bounds__(256, 4) void k2() {
    __shared__ float sQ[22 * SLOT_STRIDE];
    __shared__ float sED[4 * 1352];     // boundary overlays its CB scratch at +1360
    __shared__ float sInv[4 * 200];
    __shared__ float sW[4 * 104];
    __shared__ int   sSlot[4][13];
    __shared__ int   sMap[25];
    __shared__ int   sOff[13];

    int tid = threadIdx.x;

    if (blockIdx.x < NBI) {
        // ================= interior path =================
        int idx = blockIdx.x;
        int b = idx / 900, rem = idx - b * 900;
        int h0 = 2 + rem / 15, w0 = 2 + (rem % 15) * 4;
        int base = (b << 12) + (h0 << 6) + w0;

        if (tid < 52) {
            int j = tid / 13, ls = tid - j * 13;
            int g = (ls < 5) ? ls + j : (ls < 10) ? 8 + (ls - 5) + j : (ls < 12) ? 16 + (ls - 10) + j : 21;
            sSlot[j][ls] = g;
        }
        for (int i = tid; i < 22 * 64; i += 256) {
            int slot = i >> 6, jj = i & 63;
            float4 v;
            if (slot < 21) {
                int row, col;
                if (slot < 16) { row = slot >> 3; col = slot & 7; }
                else { row = 2; col = slot - 16; }
                int pp = base + (row - 2) * 64 + (col - 2);
                v = *(const float4*)(g_y + (size_t)pp * 256 + jj * 4);
            } else {
                v = (jj < 48) ? *(const float4*)(g_const + jj * 4) : make_float4(0.f, 0.f, 0.f, 0.f);
            }
            *(float4*)(sQ + slot * SLOT_STRIDE + jj * 4) = v;
        }
        __syncthreads();

        // dots: broadcast-k scheme, half-warp group per (pix,h) pair
        {
            int w = tid >> 5, lane = tid & 31;
            int grp = lane >> 4, qi = lane & 15;
            bool act = qi < 13;
#pragma unroll
            for (int it = 0; it < 2; it++) {
                int pairidx = w * 4 + it * 2 + grp;
                int pix = pairidx >> 3, h = pairidx & 7;
                const int* sm = sSlot[pix];
                float4 qa = make_float4(0.f, 0.f, 0.f, 0.f), qd = qa;
                if (act) {
                    int gq = sm[qi];
                    qa = *(const float4*)(sQ + gq * SLOT_STRIDE + h * 8);
                    qd = *(const float4*)(sQ + gq * SLOT_STRIDE + h * 8 + 4);
                }
                float* ed = sED + pix * 1352 + h * 169 + qi * 13;
#pragma unroll
                for (int ki = 0; ki < 13; ki++) {
                    const float* kb = sQ + sm[ki] * SLOT_STRIDE + 64 + h * 8;
                    float4 ka = *(const float4*)kb;
                    float4 kd = *(const float4*)(kb + 4);
                    float dot = qa.x * ka.x + qa.y * ka.y + qa.z * ka.z + qa.w * ka.w
                              + qd.x * kd.x + qd.y * kd.y + qd.z * kd.z + qd.w * kd.w;
                    if (act) ed[ki] = __expf(dot);
                }
            }
        }
        __syncthreads();

        // pass1
        for (int i = tid; i < 800; i += 256) {
            int pix = i / 200, t = i - pix * 200;
            int h = t / 25, r = t - h * 25;
            int qi = (r < 12) ? r : 12;
            const float* ed = sED + pix * 1352 + h * 169 + qi * 13;
            const float* eb = g_eb12 + h * 300 + r * 12;
            float4 e0 = __ldg((const float4*)eb);
            float4 e1 = __ldg((const float4*)(eb + 4));
            float4 e2 = __ldg((const float4*)(eb + 8));
            float den = __ldg(g_cb + h * 25 + r) * ed[12];
            den += e0.x * ed[0] + e0.y * ed[1] + e0.z * ed[2] + e0.w * ed[3];
            den += e1.x * ed[4] + e1.y * ed[5] + e1.z * ed[6] + e1.w * ed[7];
            den += e2.x * ed[8] + e2.y * ed[9] + e2.z * ed[10] + e2.w * ed[11];
            sInv[pix * 200 + t] = 1.f / den;
        }
        __syncthreads();

        // pass2
        for (int i = tid; i < 416; i += 256) {
            int pix = i / 104, t = i - pix * 104;
            int h = t / 13, c = t - h * 13;
            const float* ed = sED + pix * 1352 + h * 169;
            const float* iv = sInv + pix * 200 + h * 25;
            float w = 0.f, tt = 0.f;
            if (c < 12) {
                const float* eb = g_eb12 + h * 300 + c;
#pragma unroll
                for (int r = 0; r < 12; r++) w += iv[r] * ed[r * 13 + c] * __ldg(eb + r * 12);
#pragma unroll
                for (int r = 12; r < 25; r++) tt += iv[r] * __ldg(eb + r * 12);
                w += ed[156 + c] * tt;
            } else {
                const float* cb = g_cb + h * 25;
#pragma unroll
                for (int r = 0; r < 12; r++) w += iv[r] * ed[r * 13 + 12] * __ldg(cb + r);
#pragma unroll
                for (int r = 12; r < 25; r++) tt += iv[r] * __ldg(cb + r);
                w += ed[168] * tt;
            }
            sW[pix * 104 + t] = w;
        }
        __syncthreads();

        // pass3
        {
            int pix = tid >> 6, ch = tid & 63, h = ch >> 3;
            const float* w = sW + pix * 104 + h * 13;
            const int* sm = sSlot[pix];
            float acc = 0.f;
#pragma unroll
            for (int c = 0; c < 13; c++) acc += w[c] * sQ[sm[c] * SLOT_STRIDE + 128 + ch];
#pragma unroll
            for (int s = 0; s < 12; s++) acc += sQ[sm[s] * SLOT_STRIDE + 192 + ch];
            g_osum[(size_t)(base + pix) * 64 + ch] = acc;
        }
    } else {
        // ================= boundary path =================
        float* sCB = sED + 1360;   // overlay (ED uses [0,1352))
        int t = blockIdx.x - NBI;
        int b = t / 496, u = t - b * 496;
        int h0, w0;
        if (u < 128)      { h0 = u >> 6; w0 = u & 63; }
        else if (u < 256) { int v = u - 128; h0 = 62 + (v >> 6); w0 = v & 63; }
        else              { int v = u - 256; h0 = 2 + v / 4; int c = v & 3; w0 = (c < 2) ? c : (60 + c); }
        int p = (b << 12) + (h0 << 6) + w0;

        if (tid < 25) {
            int ri = tid / 5 - 2, ci = tid % 5 - 2;
            int nh = h0 + ri, nw = w0 + ci;
            int ok = (tid < 12) && nh >= 0 && nh < 64 && nw >= 0 && nw < 64;
            sMap[tid] = ok ? tid : 12;
            if (tid < 13) sOff[tid] = -1;
            if (ok) sOff[tid] = ((b << 12) + (nh << 6) + nw) * 256;
        }
        __syncthreads();

        for (int i = tid; i < 13 * 64; i += 256) {
            int slot = i >> 6, j = i & 63;
            int off = sOff[slot];
            float4 v;
            if (off >= 0)    v = *(const float4*)(g_y + off + j * 4);
            else if (j < 48) v = *(const float4*)(g_const + j * 4);
            else             v = make_float4(0.f, 0.f, 0.f, 0.f);
            *(float4*)(sQ + slot * SLOT_STRIDE + j * 4) = v;
        }
        __syncthreads();

        if (tid < 104) {
            int h = tid / 13, qi = tid % 13;
            float4 qa = *(const float4*)(sQ + qi * SLOT_STRIDE + h * 8);
            float4 qd = *(const float4*)(sQ + qi * SLOT_STRIDE + h * 8 + 4);
            float* ed = sED + h * 169 + qi * 13;
#pragma unroll
            for (int ki = 0; ki < 13; ki++) {
                const float* kb = sQ + ki * SLOT_STRIDE + 64 + h * 8;
                float4 ka = *(const float4*)kb;
                float4 kd = *(const float4*)(kb + 4);
                float dot = qa.x * ka.x + qa.y * ka.y + qa.z * ka.z + qa.w * ka.w
                          + qd.x * kd.x + qd.y * kd.y + qd.z * kd.z + qd.w * kd.w;
                ed[ki] = __expf(dot);
            }
        }
        __syncthreads();

        if (tid < 200) {
            int h = tid / 25, r = tid % 25;
            int qi = sMap[r];
            const float* eb = g_ebias + h * 625 + r * 25;
            const float* ed = sED + h * 169 + qi * 13;
            float den = 0.f, cb = 0.f;
#pragma unroll
            for (int col = 0; col < 25; col++) {
                int ki = sMap[col];
                float e = __ldg(eb + col);
                den += e * ed[ki];
                if (ki == 12) cb += e;
            }
            sInv[tid] = 1.f / den;
            sCB[tid] = cb;
        }
        __syncthreads();

        if (tid < 104) {
            int h = tid / 13, c = tid % 13;
            const float* ed = sED + h * 169;
            const float* iv = sInv + h * 25;
            float w = 0.f;
            if (c == 12) {
                const float* cb = sCB + h * 25;
#pragma unroll
                for (int r = 0; r < 25; r++) w += iv[r] * ed[sMap[r] * 13 + 12] * cb[r];
            } else if (sMap[c] == c) {
                const float* eb = g_ebias + h * 625 + c;
#pragma unroll
                for (int r = 0; r < 25; r++) w += iv[r] * ed[sMap[r] * 13 + c] * __ldg(eb + r * 25);
            }
            sW[tid] = w;
        }
        __syncthreads();

        if (tid < 64) {
            int h = tid >> 3;
            const float* w = sW + h * 13;
            float acc = 0.f;
#pragma unroll
            for (int c = 0; c < 13; c++) acc += w[c] * sQ[c * SLOT_STRIDE + 128 + tid];
#pragma unroll
            for (int s = 0; s < 12; s++) acc += sQ[s * SLOT_STRIDE + 192 + tid];
            g_osum[(size_t)p * 64 + tid] = acc;
        }
    }
}

// ---- k3: fused LN2+MLP+proj, chunked smem staging + packed f32x2 FMA.
//      block = 32 pixels, 256 thr; lane = pixel, warp = output slice. ----
__global__ __launch_bounds__(256) void k3(const float* __restrict__ n2w, const float* __restrict__ n2b,
                                          const float* __restrict__ b1, const float* __restrict__ b2,
                                          const float* __restrict__ pb, float* __restrict__ out) {
    extern __shared__ float smem[];
    float* sWt = smem;                  // 8192 floats: weight staging chunk (32KB)
    float* sA  = smem + 8192;           // 32 x 65: LN values, later y
    float* sH  = sA + 32 * 65;          // 32 x 257: gelu activations
    int tid = threadIdx.x, lane = tid & 31, w = tid >> 5;
    int p0 = blockIdx.x * 32;

    // LN: warp w handles pixels w*4 .. w*4+3
#pragma unroll
    for (int t = 0; t < 4; t++) {
        int pix = w * 4 + t;
        const float* os = g_osum + (size_t)(p0 + pix) * 64;
        float x0 = os[lane], x1 = os[lane + 32];
        float m  = wsum(x0 + x1) * (1.f / 64.f);
        float vv = wsum(x0 * x0 + x1 * x1) * (1.f / 64.f) - m * m;
        float rs = rsqrtf(vv + 1e-5f);
        sA[pix * 65 + lane]      = (x0 - m) * rs * n2w[lane] + n2b[lane];
        sA[pix * 65 + lane + 32] = (x1 - m) * rs * n2w[lane + 32] + n2b[lane + 32];
    }

    // fc1: lane = pixel, warp owns outputs [32w, 32w+32); 16 packed accumulators
    unsigned long long acc2[16];
#pragma unroll
    for (int j = 0; j < 16; j++) acc2[j] = 0ull;
#pragma unroll
    for (int half = 0; half < 2; half++) {
        __syncthreads();
        {
            const float4* src = (const float4*)(g_w1T + half * 32 * 256);
            float4* dst = (float4*)sWt;
            for (int i = tid; i < 2048; i += 256) dst[i] = src[i];
        }
        __syncthreads();
        const float* aRow = sA + lane * 65 + half * 32;
        const float* wBase = sWt + w * 32;
        for (int k = 0; k < 32; k++) {
            float a = aRow[k];
            unsigned long long aa = pack2(a, a);
            const ulonglong2* wr = (const ulonglong2*)(wBase + k * 256);
#pragma unroll
            for (int j4 = 0; j4 < 8; j4++) {
                ulonglong2 wv = wr[j4];
                fma2(acc2[2 * j4],     wv.x, aa);
                fma2(acc2[2 * j4 + 1], wv.y, aa);
            }
        }
    }
    // bias + gelu -> sH
    {
        float* hRow = sH + lane * 257 + w * 32;
#pragma unroll
        for (int j2 = 0; j2 < 16; j2++) {
            float2 bv = __ldg((const float2*)(b1 + w * 32 + 2 * j2));
            float2 p = unpack2(acc2[j2]);
            float v0 = p.x + bv.x;
            float v1 = p.y + bv.y;
            hRow[2 * j2 + 0] = 0.5f * v0 * (1.f + erff(v0 * 0.70710678118f));
            hRow[2 * j2 + 1] = 0.5f * v1 * (1.f + erff(v1 * 0.70710678118f));
        }
    }

    // fc2: lane = pixel, warp owns outputs [8w, 8w+8); 4 packed accumulators
    unsigned long long a2p[4];
#pragma unroll
    for (int j = 0; j < 4; j++) a2p[j] = 0ull;
#pragma unroll
    for (int half = 0; half < 2; half++) {
        __syncthreads();
        {
            const float4* src = (const float4*)(g_w2T + half * 128 * 64);
            float4* dst = (float4*)sWt;
            for (int i = tid; i < 2048; i += 256) dst[i] = src[i];
        }
        __syncthreads();
        const float* hRow = sH + lane * 257 + half * 128;
        const float* wBase = sWt + w * 8;
        for (int k = 0; k < 128; k++) {
            float hv = hRow[k];
            unsigned long long hh = pack2(hv, hv);
            ulonglong2 w0 = *(const ulonglong2*)(wBase + k * 64);
            ulonglong2 w1v = *(const ulonglong2*)(wBase + k * 64 + 4);
            fma2(a2p[0], w0.x, hh);
            fma2(a2p[1], w0.y, hh);
            fma2(a2p[2], w1v.x, hh);
            fma2(a2p[3], w1v.y, hh);
        }
    }
    // + b2 + residual -> y in sA
    __syncthreads();
    {
        const float* os = g_osum + (size_t)(p0 + lane) * 64 + w * 8;
        float* yRow = sA + lane * 65 + w * 8;
#pragma unroll
        for (int j2 = 0; j2 < 4; j2++) {
            float2 bv = __ldg((const float2*)(b2 + w * 8 + 2 * j2));
            float2 rv = __ldg((const float2*)(os + 2 * j2));
            float2 p = unpack2(a2p[j2]);
            yRow[2 * j2 + 0] = p.x + bv.x + rv.x;
            yRow[2 * j2 + 1] = p.y + bv.y + rv.y;
        }
    }
    __syncthreads();

    // stage projT (16KB, single chunk)
    {
        const float4* src = (const float4*)g_projT;
        float4* dst = (float4*)sWt;
        for (int i = tid; i < 1024; i += 256) dst[i] = src[i];
    }
    __syncthreads();

    // proj: lane = pixel, warp owns outputs [8w, 8w+8); 4 packed accumulators
    unsigned long long a3p[4];
#pragma unroll
    for (int j = 0; j < 4; j++) a3p[j] = 0ull;
    {
        const float* yRow = sA + lane * 65;
        const float* wBase = sWt + w * 8;
        for (int k = 0; k < 64; k++) {
            float yv = yRow[k];
            unsigned long long yy = pack2(yv, yv);
            ulonglong2 w0 = *(const ulonglong2*)(wBase + k * 64);
            ulonglong2 w1v = *(const ulonglong2*)(wBase + k * 64 + 4);
            fma2(a3p[0], w0.x, yy);
            fma2(a3p[1], w0.y, yy);
            fma2(a3p[2], w1v.x, yy);
            fma2(a3p[3], w1v.y, yy);
        }
    }
    {
        int wid = p0 + lane;
        int b = wid >> 12, hw = wid & 4095;
        float* ob = out + (size_t)b * 262144 + hw;
#pragma unroll
        for (int j2 = 0; j2 < 4; j2++) {
            float2 pv = __ldg((const float2*)(pb + w * 8 + 2 * j2));
            float2 p = unpack2(a3p[j2]);
            ob[(size_t)(w * 8 + 2 * j2 + 0) * 4096] = p.x + pv.x;
            ob[(size_t)(w * 8 + 2 * j2 + 1) * 4096] = p.y + pv.y;
        }
    }
}

extern "C" void kernel_launch(void* const* d_in, const int* in_sizes, int n_in,
                              void* d_out, int out_size) {
    const float* x    = (const float*)d_in[0];
    const float* n1w  = (const float*)d_in[1];
    const float* n1b  = (const float*)d_in[2];
    const float* qw   = (const float*)d_in[3];
    const float* qb   = (const float*)d_in[4];
    const float* rpb  = (const float*)d_in[5];
    const float* n2w  = (const float*)d_in[6];
    const float* n2b  = (const float*)d_in[7];
    const float* w1   = (const float*)d_in[8];
    const float* b1   = (const float*)d_in[9];
    const float* w2   = (const float*)d_in[10];
    const float* b2   = (const float*)d_in[11];
    const float* pw   = (const float*)d_in[12];
    const float* pb   = (const float*)d_in[13];
    float* out = (float*)d_out;

    cudaFuncSetAttribute(k3, cudaFuncAttributeMaxDynamicSharedMemorySize, K3_SMEM);

    prep<<<64, 256>>>(qw, w1, w2, pw, rpb, n1b, qb);
    k1<<<256, 256>>>(x, n1w, n1b, qb);
    k2<<<NBI + NBB, 256>>>();
    k3<<<512, 256, K3_SMEM>>>(n2w, n2b, b1, b2, pb, out);
}

// round 14
// speedup vs baseline: 3.0241x; 1.0980x over previous
#include <cuda_runtime.h>
#include <math.h>

#define NPIX 16384
#define QSCALE 0.35355339059327373f
#define SLOT_STRIDE 260
#define NBI 3600   // interior blocks
#define NBB 1984   // boundary blocks
#define K3_SMEM ((8192 + 64 * 65 + 64 * 257) * 4)

__device__ __align__(16) float g_y[NPIX * 256];   // per pixel: q*s | k | v | raw x
__device__ __align__(16) float g_osum[NPIX * 64];
__device__ __align__(16) float g_const[192];      // qkv row for masked/OOB slots
__device__ float g_qwT[64 * 192];                 // [c][o]
__device__ __align__(16) float g_w1T[64 * 256];   // [c][u]
__device__ __align__(16) float g_w2T[256 * 64];   // [u][o]
__device__ __align__(16) float g_projT[64 * 64];  // [c][o]
__device__ __align__(16) float g_ebias[8 * 25 * 25];   // exp(bias) full (boundary)
__device__ __align__(16) float g_eb12[8 * 25 * 12];    // exp(bias)[h][r][c<12] (interior)
__device__ float g_cb[8 * 25];                    // sum_{c>=12} exp(bias)

__device__ __forceinline__ float wsum(float v) {
#pragma unroll
    for (int o = 16; o; o >>= 1) v += __shfl_xor_sync(0xffffffffu, v, o);
    return v;
}

// ---- packed fp32x2 helpers (FFMA2 path, sm_103a) ----
__device__ __forceinline__ unsigned long long pack2(float lo, float hi) {
    unsigned long long r;
    asm("mov.b64 %0, {%1, %2};" : "=l"(r) : "f"(lo), "f"(hi));
    return r;
}
__device__ __forceinline__ void fma2(unsigned long long& d, unsigned long long a, unsigned long long b) {
    asm("fma.rn.f32x2 %0, %1, %2, %0;" : "+l"(d) : "l"(a), "l"(b));
}
__device__ __forceinline__ float2 unpack2(unsigned long long v) {
    float lo, hi;
    asm("mov.b64 {%0, %1}, %2;" : "=f"(lo), "=f"(hi) : "l"(v));
    return make_float2(lo, hi);
}

// ---- prep: transposed weights + exp(bias) tables + const qkv row ----
__global__ void prep(const float* __restrict__ qw, const float* __restrict__ w1,
                     const float* __restrict__ w2, const float* __restrict__ pw,
                     const float* __restrict__ rpb,
                     const float* __restrict__ n1b, const float* __restrict__ qb) {
    for (int i = blockIdx.x * blockDim.x + threadIdx.x; i < 56944; i += gridDim.x * blockDim.x) {
        if (i < 12288) { int c = i / 192, o = i % 192; g_qwT[i] = qw[o * 64 + c]; }
        else if (i < 28672) { int j = i - 12288; int c = j / 256, u = j % 256; g_w1T[j] = w1[u * 64 + c]; }
        else if (i < 45056) { int j = i - 28672; int u = j / 64, c = j % 64; g_w2T[j] = w2[c * 256 + u]; }
        else if (i < 49152) { int j = i - 45056; int c = j / 64, o = j % 64; g_projT[j] = pw[o * 64 + c]; }
        else if (i < 54152) {
            int j = i - 49152; int h = j / 625, r = j % 625; int qi = r / 25, kj = r % 25;
            int idx = (qi / 5 - kj / 5 + 4) * 9 + (qi % 5 - kj % 5 + 4);
            g_ebias[j] = __expf(rpb[idx * 8 + h]);
        } else if (i < 56552) {
            int j = i - 54152; int h = j / 300, rem = j % 300; int r = rem / 12, c = rem % 12;
            int idx = (r / 5 - c / 5 + 4) * 9 + (r % 5 - c % 5 + 4);
            g_eb12[j] = __expf(rpb[idx * 8 + h]);
        } else if (i < 56752) {
            int j = i - 56552; int h = j / 25, r = j % 25;
            float s = 0.f;
            for (int c = 12; c < 25; c++) {
                int idx = (r / 5 - c / 5 + 4) * 9 + (r % 5 - c % 5 + 4);
                s += __expf(rpb[idx * 8 + h]);
            }
            g_cb[j] = s;
        } else {
            int o = i - 56752;   // const qkv row: LN(0) = n1b
            float a = qb[o];
            for (int c = 0; c < 64; c++) a += n1b[c] * qw[o * 64 + c];
            if (o < 64) a *= QSCALE;
            g_const[o] = a;
        }
    }
}

// ---- k1: LN1 + QKV, register-tiled: block=64 pixels, warp=8 pixels ----
__global__ __launch_bounds__(256) void k1(const float* __restrict__ x,
                                          const float* __restrict__ n1w,
                                          const float* __restrict__ n1b,
                                          const float* __restrict__ qb) {
    __shared__ float sLn[64][65];
    int tid = threadIdx.x, lane = tid & 31, w = tid >> 5;
    int p0 = blockIdx.x * 64;
    float nw0 = n1w[lane], nw1 = n1w[lane + 32];
    float nb0 = n1b[lane], nb1 = n1b[lane + 32];
#pragma unroll
    for (int t = 0; t < 8; t++) {
        int wid = p0 + w * 8 + t;
        int b = wid >> 12, hw = wid & 4095;
        const float* xb = x + (size_t)b * 262144 + hw;
        float x0 = __ldg(xb + (size_t)lane * 4096);
        float x1 = __ldg(xb + (size_t)(lane + 32) * 4096);
        float m  = wsum(x0 + x1) * (1.f / 64.f);
        float vv = wsum(x0 * x0 + x1 * x1) * (1.f / 64.f) - m * m;
        float rs = rsqrtf(vv + 1e-5f);
        sLn[w * 8 + t][lane]      = (x0 - m) * rs * nw0 + nb0;
        sLn[w * 8 + t][lane + 32] = (x1 - m) * rs * nw1 + nb1;
        float* yp = g_y + (size_t)wid * 256;
        yp[192 + lane] = x0; yp[224 + lane] = x1;
    }
    __syncwarp();
    float acc[6][8];
#pragma unroll
    for (int k = 0; k < 6; k++)
#pragma unroll
        for (int j = 0; j < 8; j++) acc[k][j] = 0.f;
    for (int c = 0; c < 64; c++) {
        float wv[6];
        const float* wr = g_qwT + c * 192 + lane;
#pragma unroll
        for (int k = 0; k < 6; k++) wv[k] = wr[32 * k];
#pragma unroll
        for (int j = 0; j < 8; j++) {
            float l = sLn[w * 8 + j][c];
#pragma unroll
            for (int k = 0; k < 6; k++) acc[k][j] += wv[k] * l;
        }
    }
#pragma unroll
    for (int k = 0; k < 6; k++) {
        int o = lane + 32 * k;
        float bias = qb[o];
        float sc = (o < 64) ? QSCALE : 1.f;
#pragma unroll
        for (int j = 0; j < 8; j++)
            g_y[(size_t)(p0 + w * 8 + j) * 256 + o] = (acc[k][j] + bias) * sc;
    }
}

// ---- k2: merged window attention. blocks [0,NBI): interior 4-pixel strips;
//      blocks [NBI, NBI+NBB): boundary single pixels (generic masked path). ----
__global__ __launch_bounds__(256, 4) void k2() {
    __shared__ float sQ[22 * SLOT_STRIDE];
    __shared__ float sED[4 * 1352];     // boundary overlays its CB scratch at +1360
    __shared__ float sInv[4 * 200];
    __shared__ float sW[4 * 104];
    __shared__ int   sSlot[4][13];
    __shared__ int   sMap[25];
    __shared__ int   sOff[13];

    int tid = threadIdx.x;

    if (blockIdx.x < NBI) {
        // ================= interior path =================
        int idx = blockIdx.x;
        int b = idx / 900, rem = idx - b * 900;
        int h0 = 2 + rem / 15, w0 = 2 + (rem % 15) * 4;
        int base = (b << 12) + (h0 << 6) + w0;

        if (tid < 52) {
            int j = tid / 13, ls = tid - j * 13;
            int g = (ls < 5) ? ls + j : (ls < 10) ? 8 + (ls - 5) + j : (ls < 12) ? 16 + (ls - 10) + j : 21;
            sSlot[j][ls] = g;
        }
        for (int i = tid; i < 22 * 64; i += 256) {
            int slot = i >> 6, jj = i & 63;
            float4 v;
            if (slot < 21) {
                int row, col;
                if (slot < 16) { row = slot >> 3; col = slot & 7; }
                else { row = 2; col = slot - 16; }
                int pp = base + (row - 2) * 64 + (col - 2);
                v = *(const float4*)(g_y + (size_t)pp * 256 + jj * 4);
            } else {
                v = (jj < 48) ? *(const float4*)(g_const + jj * 4) : make_float4(0.f, 0.f, 0.f, 0.f);
            }
            *(float4*)(sQ + slot * SLOT_STRIDE + jj * 4) = v;
        }
        __syncthreads();

        // dots: broadcast-k scheme, half-warp group per (pix,h) pair
        {
            int w = tid >> 5, lane = tid & 31;
            int grp = lane >> 4, qi = lane & 15;
            bool act = qi < 13;
#pragma unroll
            for (int it = 0; it < 2; it++) {
                int pairidx = w * 4 + it * 2 + grp;
                int pix = pairidx >> 3, h = pairidx & 7;
                const int* sm = sSlot[pix];
                float4 qa = make_float4(0.f, 0.f, 0.f, 0.f), qd = qa;
                if (act) {
                    int gq = sm[qi];
                    qa = *(const float4*)(sQ + gq * SLOT_STRIDE + h * 8);
                    qd = *(const float4*)(sQ + gq * SLOT_STRIDE + h * 8 + 4);
                }
                float* ed = sED + pix * 1352 + h * 169 + qi * 13;
#pragma unroll
                for (int ki = 0; ki < 13; ki++) {
                    const float* kb = sQ + sm[ki] * SLOT_STRIDE + 64 + h * 8;
                    float4 ka = *(const float4*)kb;
                    float4 kd = *(const float4*)(kb + 4);
                    float dot = qa.x * ka.x + qa.y * ka.y + qa.z * ka.z + qa.w * ka.w
                              + qd.x * kd.x + qd.y * kd.y + qd.z * kd.z + qd.w * kd.w;
                    if (act) ed[ki] = __expf(dot);
                }
            }
        }
        __syncthreads();

        // pass1
        for (int i = tid; i < 800; i += 256) {
            int pix = i / 200, t = i - pix * 200;
            int h = t / 25, r = t - h * 25;
            int qi = (r < 12) ? r : 12;
            const float* ed = sED + pix * 1352 + h * 169 + qi * 13;
            const float* eb = g_eb12 + h * 300 + r * 12;
            float4 e0 = __ldg((const float4*)eb);
            float4 e1 = __ldg((const float4*)(eb + 4));
            float4 e2 = __ldg((const float4*)(eb + 8));
            float den = __ldg(g_cb + h * 25 + r) * ed[12];
            den += e0.x * ed[0] + e0.y * ed[1] + e0.z * ed[2] + e0.w * ed[3];
            den += e1.x * ed[4] + e1.y * ed[5] + e1.z * ed[6] + e1.w * ed[7];
            den += e2.x * ed[8] + e2.y * ed[9] + e2.z * ed[10] + e2.w * ed[11];
            sInv[pix * 200 + t] = 1.f / den;
        }
        __syncthreads();

        // pass2
        for (int i = tid; i < 416; i += 256) {
            int pix = i / 104, t = i - pix * 104;
            int h = t / 13, c = t - h * 13;
            const float* ed = sED + pix * 1352 + h * 169;
            const float* iv = sInv + pix * 200 + h * 25;
            float w = 0.f, tt = 0.f;
            if (c < 12) {
                const float* eb = g_eb12 + h * 300 + c;
#pragma unroll
                for (int r = 0; r < 12; r++) w += iv[r] * ed[r * 13 + c] * __ldg(eb + r * 12);
#pragma unroll
                for (int r = 12; r < 25; r++) tt += iv[r] * __ldg(eb + r * 12);
                w += ed[156 + c] * tt;
            } else {
                const float* cb = g_cb + h * 25;
#pragma unroll
                for (int r = 0; r < 12; r++) w += iv[r] * ed[r * 13 + 12] * __ldg(cb + r);
#pragma unroll
                for (int r = 12; r < 25; r++) tt += iv[r] * __ldg(cb + r);
                w += ed[168] * tt;
            }
            sW[pix * 104 + t] = w;
        }
        __syncthreads();

        // pass3
        {
            int pix = tid >> 6, ch = tid & 63, h = ch >> 3;
            const float* w = sW + pix * 104 + h * 13;
            const int* sm = sSlot[pix];
            float acc = 0.f;
#pragma unroll
            for (int c = 0; c < 13; c++) acc += w[c] * sQ[sm[c] * SLOT_STRIDE + 128 + ch];
#pragma unroll
            for (int s = 0; s < 12; s++) acc += sQ[sm[s] * SLOT_STRIDE + 192 + ch];
            g_osum[(size_t)(base + pix) * 64 + ch] = acc;
        }
    } else {
        // ================= boundary path =================
        float* sCB = sED + 1360;   // overlay (ED uses [0,1352))
        int t = blockIdx.x - NBI;
        int b = t / 496, u = t - b * 496;
        int h0, w0;
        if (u < 128)      { h0 = u >> 6; w0 = u & 63; }
        else if (u < 256) { int v = u - 128; h0 = 62 + (v >> 6); w0 = v & 63; }
        else              { int v = u - 256; h0 = 2 + v / 4; int c = v & 3; w0 = (c < 2) ? c : (60 + c); }
        int p = (b << 12) + (h0 << 6) + w0;

        if (tid < 25) {
            int ri = tid / 5 - 2, ci = tid % 5 - 2;
            int nh = h0 + ri, nw = w0 + ci;
            int ok = (tid < 12) && nh >= 0 && nh < 64 && nw >= 0 && nw < 64;
            sMap[tid] = ok ? tid : 12;
            if (tid < 13) sOff[tid] = -1;
            if (ok) sOff[tid] = ((b << 12) + (nh << 6) + nw) * 256;
        }
        __syncthreads();

        for (int i = tid; i < 13 * 64; i += 256) {
            int slot = i >> 6, j = i & 63;
            int off = sOff[slot];
            float4 v;
            if (off >= 0)    v = *(const float4*)(g_y + off + j * 4);
            else if (j < 48) v = *(const float4*)(g_const + j * 4);
            else             v = make_float4(0.f, 0.f, 0.f, 0.f);
            *(float4*)(sQ + slot * SLOT_STRIDE + j * 4) = v;
        }
        __syncthreads();

        if (tid < 104) {
            int h = tid / 13, qi = tid % 13;
            float4 qa = *(const float4*)(sQ + qi * SLOT_STRIDE + h * 8);
            float4 qd = *(const float4*)(sQ + qi * SLOT_STRIDE + h * 8 + 4);
            float* ed = sED + h * 169 + qi * 13;
#pragma unroll
            for (int ki = 0; ki < 13; ki++) {
                const float* kb = sQ + ki * SLOT_STRIDE + 64 + h * 8;
                float4 ka = *(const float4*)kb;
                float4 kd = *(const float4*)(kb + 4);
                float dot = qa.x * ka.x + qa.y * ka.y + qa.z * ka.z + qa.w * ka.w
                          + qd.x * kd.x + qd.y * kd.y + qd.z * kd.z + qd.w * kd.w;
                ed[ki] = __expf(dot);
            }
        }
        __syncthreads();

        if (tid < 200) {
            int h = tid / 25, r = tid % 25;
            int qi = sMap[r];
            const float* eb = g_ebias + h * 625 + r * 25;
            const float* ed = sED + h * 169 + qi * 13;
            float den = 0.f, cb = 0.f;
#pragma unroll
            for (int col = 0; col < 25; col++) {
                int ki = sMap[col];
                float e = __ldg(eb + col);
                den += e * ed[ki];
                if (ki == 12) cb += e;
            }
            sInv[tid] = 1.f / den;
            sCB[tid] = cb;
        }
        __syncthreads();

        if (tid < 104) {
            int h = tid / 13, c = tid % 13;
            const float* ed = sED + h * 169;
            const float* iv = sInv + h * 25;
            float w = 0.f;
            if (c == 12) {
                const float* cb = sCB + h * 25;
#pragma unroll
                for (int r = 0; r < 25; r++) w += iv[r] * ed[sMap[r] * 13 + 12] * cb[r];
            } else if (sMap[c] == c) {
                const float* eb = g_ebias + h * 625 + c;
#pragma unroll
                for (int r = 0; r < 25; r++) w += iv[r] * ed[sMap[r] * 13 + c] * __ldg(eb + r * 25);
            }
            sW[tid] = w;
        }
        __syncthreads();

        if (tid < 64) {
            int h = tid >> 3;
            const float* w = sW + h * 13;
            float acc = 0.f;
#pragma unroll
            for (int c = 0; c < 13; c++) acc += w[c] * sQ[c * SLOT_STRIDE + 128 + tid];
#pragma unroll
            for (int s = 0; s < 12; s++) acc += sQ[s * SLOT_STRIDE + 192 + tid];
            g_osum[(size_t)p * 64 + tid] = acc;
        }
    }
}

// ---- k3: fused LN2+MLP+proj, 64 pixels/block, pixel-pair packed FFMA2.
//      lane owns pixels (lane, lane+32); warp owns an output slice. ----
__global__ __launch_bounds__(256) void k3(const float* __restrict__ n2w, const float* __restrict__ n2b,
                                          const float* __restrict__ b1, const float* __restrict__ b2,
                                          const float* __restrict__ pb, float* __restrict__ out) {
    extern __shared__ float smem[];
    float* sWt = smem;                  // 8192 floats: weight staging chunk (32KB)
    float* sA  = smem + 8192;           // 64 x 65: LN values, later y
    float* sH  = sA + 64 * 65;          // 64 x 257: gelu activations
    int tid = threadIdx.x, lane = tid & 31, w = tid >> 5;
    int p0 = blockIdx.x * 64;

    // LN: warp w handles pixels w*8 .. w*8+7
#pragma unroll
    for (int t = 0; t < 8; t++) {
        int pix = w * 8 + t;
        const float* os = g_osum + (size_t)(p0 + pix) * 64;
        float x0 = os[lane], x1 = os[lane + 32];
        float m  = wsum(x0 + x1) * (1.f / 64.f);
        float vv = wsum(x0 * x0 + x1 * x1) * (1.f / 64.f) - m * m;
        float rs = rsqrtf(vv + 1e-5f);
        sA[pix * 65 + lane]      = (x0 - m) * rs * n2w[lane] + n2b[lane];
        sA[pix * 65 + lane + 32] = (x1 - m) * rs * n2w[lane + 32] + n2b[lane + 32];
    }

    // fc1: two output-half passes; warp owns outputs [oh*128 + 16w, +16)
#pragma unroll
    for (int oh = 0; oh < 2; oh++) {
        __syncthreads();
        {
            const float4* src = (const float4*)g_w1T;
            float4* dst = (float4*)sWt;
            for (int i = tid; i < 2048; i += 256) {
                int row = i >> 5, c4 = i & 31;
                dst[i] = src[row * 64 + oh * 32 + c4];
            }
        }
        __syncthreads();
        unsigned long long acc2[16];
#pragma unroll
        for (int j = 0; j < 16; j++) acc2[j] = 0ull;
        const float* a0 = sA + lane * 65;
        const float* a1 = sA + (lane + 32) * 65;
        const float* wBase = sWt + w * 16;
        for (int k = 0; k < 64; k++) {
            unsigned long long aa = pack2(a0[k], a1[k]);
            const float4* wr = (const float4*)(wBase + k * 128);
#pragma unroll
            for (int j4 = 0; j4 < 4; j4++) {
                float4 wv = wr[j4];
                fma2(acc2[4 * j4 + 0], pack2(wv.x, wv.x), aa);
                fma2(acc2[4 * j4 + 1], pack2(wv.y, wv.y), aa);
                fma2(acc2[4 * j4 + 2], pack2(wv.z, wv.z), aa);
                fma2(acc2[4 * j4 + 3], pack2(wv.w, wv.w), aa);
            }
        }
        // bias + gelu -> sH
        float* h0 = sH + lane * 257 + oh * 128 + w * 16;
        float* h1 = sH + (lane + 32) * 257 + oh * 128 + w * 16;
#pragma unroll
        for (int j = 0; j < 16; j++) {
            float bv = __ldg(b1 + oh * 128 + w * 16 + j);
            float2 p = unpack2(acc2[j]);
            float v0 = p.x + bv, v1 = p.y + bv;
            h0[j] = 0.5f * v0 * (1.f + erff(v0 * 0.70710678118f));
            h1[j] = 0.5f * v1 * (1.f + erff(v1 * 0.70710678118f));
        }
    }

    // fc2: warp owns outputs [8w, 8w+8); w2T staged in 2 k-halves
    unsigned long long a2p[8];
#pragma unroll
    for (int j = 0; j < 8; j++) a2p[j] = 0ull;
#pragma unroll
    for (int kh = 0; kh < 2; kh++) {
        __syncthreads();
        {
            const float4* src = (const float4*)(g_w2T + kh * 128 * 64);
            float4* dst = (float4*)sWt;
            for (int i = tid; i < 2048; i += 256) dst[i] = src[i];
        }
        __syncthreads();
        const float* h0 = sH + lane * 257 + kh * 128;
        const float* h1 = sH + (lane + 32) * 257 + kh * 128;
        const float* wBase = sWt + w * 8;
        for (int k = 0; k < 128; k++) {
            unsigned long long hh = pack2(h0[k], h1[k]);
            const float4* wr = (const float4*)(wBase + k * 64);
            float4 w0 = wr[0], w1v = wr[1];
            fma2(a2p[0], pack2(w0.x, w0.x), hh);
            fma2(a2p[1], pack2(w0.y, w0.y), hh);
            fma2(a2p[2], pack2(w0.z, w0.z), hh);
            fma2(a2p[3], pack2(w0.w, w0.w), hh);
            fma2(a2p[4], pack2(w1v.x, w1v.x), hh);
            fma2(a2p[5], pack2(w1v.y, w1v.y), hh);
            fma2(a2p[6], pack2(w1v.z, w1v.z), hh);
            fma2(a2p[7], pack2(w1v.w, w1v.w), hh);
        }
    }
    // + b2 + residual -> y in sA
    __syncthreads();
    {
        const float* os0 = g_osum + (size_t)(p0 + lane) * 64 + w * 8;
        const float* os1 = g_osum + (size_t)(p0 + lane + 32) * 64 + w * 8;
        float* y0 = sA + lane * 65 + w * 8;
        float* y1 = sA + (lane + 32) * 65 + w * 8;
#pragma unroll
        for (int j = 0; j < 8; j++) {
            float bv = __ldg(b2 + w * 8 + j);
            float2 p = unpack2(a2p[j]);
            y0[j] = p.x + bv + __ldg(os0 + j);
            y1[j] = p.y + bv + __ldg(os1 + j);
        }
    }
    __syncthreads();

    // stage projT (16KB, single chunk)
    {
        const float4* src = (const float4*)g_projT;
        float4* dst = (float4*)sWt;
        for (int i = tid; i < 1024; i += 256) dst[i] = src[i];
    }
    __syncthreads();

    // proj: warp owns outputs [8w, 8w+8)
    unsigned long long a3p[8];
#pragma unroll
    for (int j = 0; j < 8; j++) a3p[j] = 0ull;
    {
        const float* y0 = sA + lane * 65;
        const float* y1 = sA + (lane + 32) * 65;
        const float* wBase = sWt + w * 8;
        for (int k = 0; k < 64; k++) {
            unsigned long long yy = pack2(y0[k], y1[k]);
            const float4* wr = (const float4*)(wBase + k * 64);
            float4 w0 = wr[0], w1v = wr[1];
            fma2(a3p[0], pack2(w0.x, w0.x), yy);
            fma2(a3p[1], pack2(w0.y, w0.y), yy);
            fma2(a3p[2], pack2(w0.z, w0.z), yy);
            fma2(a3p[3], pack2(w0.w, w0.w), yy);
            fma2(a3p[4], pack2(w1v.x, w1v.x), yy);
            fma2(a3p[5], pack2(w1v.y, w1v.y), yy);
            fma2(a3p[6], pack2(w1v.z, w1v.z), yy);
            fma2(a3p[7], pack2(w1v.w, w1v.w), yy);
        }
    }
    {
        int wid0 = p0 + lane, wid1 = p0 + lane + 32;
        float* ob0 = out + (size_t)(wid0 >> 12) * 262144 + (wid0 & 4095);
        float* ob1 = out + (size_t)(wid1 >> 12) * 262144 + (wid1 & 4095);
#pragma unroll
        for (int j = 0; j < 8; j++) {
            float pv = __ldg(pb + w * 8 + j);
            float2 p = unpack2(a3p[j]);
            ob0[(size_t)(w * 8 + j) * 4096] = p.x + pv;
            ob1[(size_t)(w * 8 + j) * 4096] = p.y + pv;
        }
    }
}

extern "C" void kernel_launch(void* const* d_in, const int* in_sizes, int n_in,
                              void* d_out, int out_size) {
    const float* x    = (const float*)d_in[0];
    const float* n1w  = (const float*)d_in[1];
    const float* n1b  = (const float*)d_in[2];
    const float* qw   = (const float*)d_in[3];
    const float* qb   = (const float*)d_in[4];
    const float* rpb  = (const float*)d_in[5];
    const float* n2w  = (const float*)d_in[6];
    const float* n2b  = (const float*)d_in[7];
    const float* w1   = (const float*)d_in[8];
    const float* b1   = (const float*)d_in[9];
    const float* w2   = (const float*)d_in[10];
    const float* b2   = (const float*)d_in[11];
    const float* pw   = (const float*)d_in[12];
    const float* pb   = (const float*)d_in[13];
    float* out = (float*)d_out;

    cudaFuncSetAttribute(k3, cudaFuncAttributeMaxDynamicSharedMemorySize, K3_SMEM);

    prep<<<64, 256>>>(qw, w1, w2, pw, rpb, n1b, qb);
    k1<<<256, 256>>>(x, n1w, n1b, qb);
    k2<<<NBI + NBB, 256>>>();
    k3<<<256, 256, K3_SMEM>>>(n2w, n2b, b1, b2, pb, out);
}

// round 15
// speedup vs baseline: 3.1258x; 1.0336x over previous
#include <cuda_runtime.h>
#include <math.h>

#define NPIX 16384
#define QSCALE 0.35355339059327373f
#define SLOT_STRIDE 260
#define NBI 3600   // interior blocks
#define NBB 1984   // boundary blocks
#define K3_SMEM ((8192 + 64 * 65 + 64 * 257) * 4)

__device__ __align__(16) float g_y[NPIX * 256];   // per pixel: q*s | k | v | raw x
__device__ __align__(16) float g_osum[NPIX * 64];
__device__ __align__(16) float g_const[192];      // qkv row for masked/OOB slots
__device__ __align__(16) float g_qwT[64 * 192];   // [c][o]
__device__ __align__(16) float g_w1T[64 * 256];   // [c][u]
__device__ __align__(16) float g_w2T[256 * 64];   // [u][o]
__device__ __align__(16) float g_projT[64 * 64];  // [c][o]
__device__ __align__(16) float g_ebias[8 * 25 * 25];   // exp(bias) full (boundary)
__device__ __align__(16) float g_eb12[8 * 25 * 12];    // exp(bias)[h][r][c<12] (interior)
__device__ float g_cb[8 * 25];                    // sum_{c>=12} exp(bias)

__device__ __forceinline__ float wsum(float v) {
#pragma unroll
    for (int o = 16; o; o >>= 1) v += __shfl_xor_sync(0xffffffffu, v, o);
    return v;
}

// ---- packed fp32x2 helpers (FFMA2 path, sm_103a) ----
__device__ __forceinline__ unsigned long long pack2(float lo, float hi) {
    unsigned long long r;
    asm("mov.b64 %0, {%1, %2};" : "=l"(r) : "f"(lo), "f"(hi));
    return r;
}
__device__ __forceinline__ void fma2(unsigned long long& d, unsigned long long a, unsigned long long b) {
    asm("fma.rn.f32x2 %0, %1, %2, %0;" : "+l"(d) : "l"(a), "l"(b));
}
__device__ __forceinline__ float2 unpack2(unsigned long long v) {
    float lo, hi;
    asm("mov.b64 {%0, %1}, %2;" : "=f"(lo), "=f"(hi) : "l"(v));
    return make_float2(lo, hi);
}

// ---- prep: transposed weights + exp(bias) tables + const qkv row ----
__global__ void prep(const float* __restrict__ qw, const float* __restrict__ w1,
                     const float* __restrict__ w2, const float* __restrict__ pw,
                     const float* __restrict__ rpb,
                     const float* __restrict__ n1b, const float* __restrict__ qb) {
    for (int i = blockIdx.x * blockDim.x + threadIdx.x; i < 56944; i += gridDim.x * blockDim.x) {
        if (i < 12288) { int c = i / 192, o = i % 192; g_qwT[i] = qw[o * 64 + c]; }
        else if (i < 28672) { int j = i - 12288; int c = j / 256, u = j % 256; g_w1T[j] = w1[u * 64 + c]; }
        else if (i < 45056) { int j = i - 28672; int u = j / 64, c = j % 64; g_w2T[j] = w2[c * 256 + u]; }
        else if (i < 49152) { int j = i - 45056; int c = j / 64, o = j % 64; g_projT[j] = pw[o * 64 + c]; }
        else if (i < 54152) {
            int j = i - 49152; int h = j / 625, r = j % 625; int qi = r / 25, kj = r % 25;
            int idx = (qi / 5 - kj / 5 + 4) * 9 + (qi % 5 - kj % 5 + 4);
            g_ebias[j] = __expf(rpb[idx * 8 + h]);
        } else if (i < 56552) {
            int j = i - 54152; int h = j / 300, rem = j % 300; int r = rem / 12, c = rem % 12;
            int idx = (r / 5 - c / 5 + 4) * 9 + (r % 5 - c % 5 + 4);
            g_eb12[j] = __expf(rpb[idx * 8 + h]);
        } else if (i < 56752) {
            int j = i - 56552; int h = j / 25, r = j % 25;
            float s = 0.f;
            for (int c = 12; c < 25; c++) {
                int idx = (r / 5 - c / 5 + 4) * 9 + (r % 5 - c % 5 + 4);
                s += __expf(rpb[idx * 8 + h]);
            }
            g_cb[j] = s;
        } else {
            int o = i - 56752;   // const qkv row: LN(0) = n1b
            float a = qb[o];
            for (int c = 0; c < 64; c++) a += n1b[c] * qw[o * 64 + c];
            if (o < 64) a *= QSCALE;
            g_const[o] = a;
        }
    }
}

// ---- k1: LN1 + QKV, smem-staged weights + pixel-pair FFMA2.
//      block = 64 pixels; lane owns pixels (lane, lane+32); warp owns 12 outputs. ----
__global__ __launch_bounds__(256) void k1(const float* __restrict__ x,
                                          const float* __restrict__ n1w,
                                          const float* __restrict__ n1b,
                                          const float* __restrict__ qb) {
    __shared__ float sWt[64 * 96];    // qwT chunk: [k][96 outputs]
    __shared__ float sA[64 * 65];     // LN values per pixel
    int tid = threadIdx.x, lane = tid & 31, w = tid >> 5;
    int p0 = blockIdx.x * 64;

    float nw0 = n1w[lane], nw1 = n1w[lane + 32];
    float nb0 = n1b[lane], nb1 = n1b[lane + 32];
    // LN: warp w handles pixels w*8 .. w*8+7; also write residual x into g_y
#pragma unroll
    for (int t = 0; t < 8; t++) {
        int pix = w * 8 + t;
        int wid = p0 + pix;
        int b = wid >> 12, hw = wid & 4095;
        const float* xb = x + (size_t)b * 262144 + hw;
        float x0 = __ldg(xb + (size_t)lane * 4096);
        float x1 = __ldg(xb + (size_t)(lane + 32) * 4096);
        float m  = wsum(x0 + x1) * (1.f / 64.f);
        float vv = wsum(x0 * x0 + x1 * x1) * (1.f / 64.f) - m * m;
        float rs = rsqrtf(vv + 1e-5f);
        sA[pix * 65 + lane]      = (x0 - m) * rs * nw0 + nb0;
        sA[pix * 65 + lane + 32] = (x1 - m) * rs * nw1 + nb1;
        float* yp = g_y + (size_t)wid * 256;
        yp[192 + lane] = x0; yp[224 + lane] = x1;
    }

    // GEMM: two output-half passes; warp owns outputs [oh*96 + 12w, +12)
#pragma unroll
    for (int oh = 0; oh < 2; oh++) {
        __syncthreads();
        {
            const float4* src = (const float4*)g_qwT;
            float4* dst = (float4*)sWt;
            for (int i = tid; i < 1536; i += 256) {
                int row = i / 24, c4 = i % 24;
                dst[i] = src[row * 48 + oh * 24 + c4];
            }
        }
        __syncthreads();
        // accA/accB: packed output pairs (2j, 2j+1) for pixel lane / lane+32
        unsigned long long accA[6], accB[6];
#pragma unroll
        for (int j = 0; j < 6; j++) { accA[j] = 0ull; accB[j] = 0ull; }
        const float* a0 = sA + lane * 65;
        const float* a1 = sA + (lane + 32) * 65;
        const float* wBase = sWt + w * 12;
        for (int k = 0; k < 64; k++) {
            unsigned long long aa0 = pack2(a0[k], a0[k]);
            unsigned long long aa1 = pack2(a1[k], a1[k]);
            const ulonglong2* wr = (const ulonglong2*)(wBase + k * 96);
            ulonglong2 w01 = wr[0];
            fma2(accA[0], w01.x, aa0); fma2(accB[0], w01.x, aa1);
            fma2(accA[1], w01.y, aa0); fma2(accB[1], w01.y, aa1);
            ulonglong2 w23 = wr[1];
            fma2(accA[2], w23.x, aa0); fma2(accB[2], w23.x, aa1);
            fma2(accA[3], w23.y, aa0); fma2(accB[3], w23.y, aa1);
            ulonglong2 w45 = wr[2];
            fma2(accA[4], w45.x, aa0); fma2(accB[4], w45.x, aa1);
            fma2(accA[5], w45.y, aa0); fma2(accB[5], w45.y, aa1);
        }
        // bias + scale, direct scattered STG.128 (12 consecutive floats per pixel)
        float ov0[12], ov1[12];
#pragma unroll
        for (int j = 0; j < 6; j++) {
            int o = oh * 96 + w * 12 + 2 * j;
            float b0 = __ldg(qb + o), b1v = __ldg(qb + o + 1);
            float s0 = (o < 64) ? QSCALE : 1.f;
            float s1 = (o + 1 < 64) ? QSCALE : 1.f;
            float2 pA = unpack2(accA[j]);
            float2 pB = unpack2(accB[j]);
            ov0[2 * j]     = (pA.x + b0) * s0;
            ov0[2 * j + 1] = (pA.y + b1v) * s1;
            ov1[2 * j]     = (pB.x + b0) * s0;
            ov1[2 * j + 1] = (pB.y + b1v) * s1;
        }
        float* y0 = g_y + (size_t)(p0 + lane) * 256 + oh * 96 + w * 12;
        float* y1 = g_y + (size_t)(p0 + lane + 32) * 256 + oh * 96 + w * 12;
#pragma unroll
        for (int j4 = 0; j4 < 3; j4++) {
            *(float4*)(y0 + 4 * j4) = make_float4(ov0[4 * j4], ov0[4 * j4 + 1], ov0[4 * j4 + 2], ov0[4 * j4 + 3]);
            *(float4*)(y1 + 4 * j4) = make_float4(ov1[4 * j4], ov1[4 * j4 + 1], ov1[4 * j4 + 2], ov1[4 * j4 + 3]);
        }
    }
}

// ---- k2: merged window attention. blocks [0,NBI): interior 4-pixel strips;
//      blocks [NBI, NBI+NBB): boundary single pixels (generic masked path). ----
__global__ __launch_bounds__(256, 4) void k2() {
    __shared__ float sQ[22 * SLOT_STRIDE];
    __shared__ float sED[4 * 1352];     // boundary overlays its CB scratch at +1360
    __shared__ float sInv[4 * 200];
    __shared__ float sW[4 * 104];
    __shared__ int   sSlot[4][13];
    __shared__ int   sMap[25];
    __shared__ int   sOff[13];

    int tid = threadIdx.x;

    if (blockIdx.x < NBI) {
        // ================= interior path =================
        int idx = blockIdx.x;
        int b = idx / 900, rem = idx - b * 900;
        int h0 = 2 + rem / 15, w0 = 2 + (rem % 15) * 4;
        int base = (b << 12) + (h0 << 6) + w0;

        if (tid < 52) {
            int j = tid / 13, ls = tid - j * 13;
            int g = (ls < 5) ? ls + j : (ls < 10) ? 8 + (ls - 5) + j : (ls < 12) ? 16 + (ls - 10) + j : 21;
            sSlot[j][ls] = g;
        }
        for (int i = tid; i < 22 * 64; i += 256) {
            int slot = i >> 6, jj = i & 63;
            float4 v;
            if (slot < 21) {
                int row, col;
                if (slot < 16) { row = slot >> 3; col = slot & 7; }
                else { row = 2; col = slot - 16; }
                int pp = base + (row - 2) * 64 + (col - 2);
                v = *(const float4*)(g_y + (size_t)pp * 256 + jj * 4);
            } else {
                v = (jj < 48) ? *(const float4*)(g_const + jj * 4) : make_float4(0.f, 0.f, 0.f, 0.f);
            }
            *(float4*)(sQ + slot * SLOT_STRIDE + jj * 4) = v;
        }
        __syncthreads();

        // dots: broadcast-k scheme, half-warp group per (pix,h) pair
        {
            int w = tid >> 5, lane = tid & 31;
            int grp = lane >> 4, qi = lane & 15;
            bool act = qi < 13;
#pragma unroll
            for (int it = 0; it < 2; it++) {
                int pairidx = w * 4 + it * 2 + grp;
                int pix = pairidx >> 3, h = pairidx & 7;
                const int* sm = sSlot[pix];
                float4 qa = make_float4(0.f, 0.f, 0.f, 0.f), qd = qa;
                if (act) {
                    int gq = sm[qi];
                    qa = *(const float4*)(sQ + gq * SLOT_STRIDE + h * 8);
                    qd = *(const float4*)(sQ + gq * SLOT_STRIDE + h * 8 + 4);
                }
                float* ed = sED + pix * 1352 + h * 169 + qi * 13;
#pragma unroll
                for (int ki = 0; ki < 13; ki++) {
                    const float* kb = sQ + sm[ki] * SLOT_STRIDE + 64 + h * 8;
                    float4 ka = *(const float4*)kb;
                    float4 kd = *(const float4*)(kb + 4);
                    float dot = qa.x * ka.x + qa.y * ka.y + qa.z * ka.z + qa.w * ka.w
                              + qd.x * kd.x + qd.y * kd.y + qd.z * kd.z + qd.w * kd.w;
                    if (act) ed[ki] = __expf(dot);
                }
            }
        }
        __syncthreads();

        // pass1
        for (int i = tid; i < 800; i += 256) {
            int pix = i / 200, t = i - pix * 200;
            int h = t / 25, r = t - h * 25;
            int qi = (r < 12) ? r : 12;
            const float* ed = sED + pix * 1352 + h * 169 + qi * 13;
            const float* eb = g_eb12 + h * 300 + r * 12;
            float4 e0 = __ldg((const float4*)eb);
            float4 e1 = __ldg((const float4*)(eb + 4));
            float4 e2 = __ldg((const float4*)(eb + 8));
            float den = __ldg(g_cb + h * 25 + r) * ed[12];
            den += e0.x * ed[0] + e0.y * ed[1] + e0.z * ed[2] + e0.w * ed[3];
            den += e1.x * ed[4] + e1.y * ed[5] + e1.z * ed[6] + e1.w * ed[7];
            den += e2.x * ed[8] + e2.y * ed[9] + e2.z * ed[10] + e2.w * ed[11];
            sInv[pix * 200 + t] = 1.f / den;
        }
        __syncthreads();

        // pass2
        for (int i = tid; i < 416; i += 256) {
            int pix = i / 104, t = i - pix * 104;
            int h = t / 13, c = t - h * 13;
            const float* ed = sED + pix * 1352 + h * 169;
            const float* iv = sInv + pix * 200 + h * 25;
            float w = 0.f, tt = 0.f;
            if (c < 12) {
                const float* eb = g_eb12 + h * 300 + c;
#pragma unroll
                for (int r = 0; r < 12; r++) w += iv[r] * ed[r * 13 + c] * __ldg(eb + r * 12);
#pragma unroll
                for (int r = 12; r < 25; r++) tt += iv[r] * __ldg(eb + r * 12);
                w += ed[156 + c] * tt;
            } else {
                const float* cb = g_cb + h * 25;
#pragma unroll
                for (int r = 0; r < 12; r++) w += iv[r] * ed[r * 13 + 12] * __ldg(cb + r);
#pragma unroll
                for (int r = 12; r < 25; r++) tt += iv[r] * __ldg(cb + r);
                w += ed[168] * tt;
            }
            sW[pix * 104 + t] = w;
        }
        __syncthreads();

        // pass3
        {
            int pix = tid >> 6, ch = tid & 63, h = ch >> 3;
            const float* w = sW + pix * 104 + h * 13;
            const int* sm = sSlot[pix];
            float acc = 0.f;
#pragma unroll
            for (int c = 0; c < 13; c++) acc += w[c] * sQ[sm[c] * SLOT_STRIDE + 128 + ch];
#pragma unroll
            for (int s = 0; s < 12; s++) acc += sQ[sm[s] * SLOT_STRIDE + 192 + ch];
            g_osum[(size_t)(base + pix) * 64 + ch] = acc;
        }
    } else {
        // ================= boundary path =================
        float* sCB = sED + 1360;   // overlay (ED uses [0,1352))
        int t = blockIdx.x - NBI;
        int b = t / 496, u = t - b * 496;
        int h0, w0;
        if (u < 128)      { h0 = u >> 6; w0 = u & 63; }
        else if (u < 256) { int v = u - 128; h0 = 62 + (v >> 6); w0 = v & 63; }
        else              { int v = u - 256; h0 = 2 + v / 4; int c = v & 3; w0 = (c < 2) ? c : (60 + c); }
        int p = (b << 12) + (h0 << 6) + w0;

        if (tid < 25) {
            int ri = tid / 5 - 2, ci = tid % 5 - 2;
            int nh = h0 + ri, nw = w0 + ci;
            int ok = (tid < 12) && nh >= 0 && nh < 64 && nw >= 0 && nw < 64;
            sMap[tid] = ok ? tid : 12;
            if (tid < 13) sOff[tid] = -1;
            if (ok) sOff[tid] = ((b << 12) + (nh << 6) + nw) * 256;
        }
        __syncthreads();

        for (int i = tid; i < 13 * 64; i += 256) {
            int slot = i >> 6, j = i & 63;
            int off = sOff[slot];
            float4 v;
            if (off >= 0)    v = *(const float4*)(g_y + off + j * 4);
            else if (j < 48) v = *(const float4*)(g_const + j * 4);
            else             v = make_float4(0.f, 0.f, 0.f, 0.f);
            *(float4*)(sQ + slot * SLOT_STRIDE + j * 4) = v;
        }
        __syncthreads();

        if (tid < 104) {
            int h = tid / 13, qi = tid % 13;
            float4 qa = *(const float4*)(sQ + qi * SLOT_STRIDE + h * 8);
            float4 qd = *(const float4*)(sQ + qi * SLOT_STRIDE + h * 8 + 4);
            float* ed = sED + h * 169 + qi * 13;
#pragma unroll
            for (int ki = 0; ki < 13; ki++) {
                const float* kb = sQ + ki * SLOT_STRIDE + 64 + h * 8;
                float4 ka = *(const float4*)kb;
                float4 kd = *(const float4*)(kb + 4);
                float dot = qa.x * ka.x + qa.y * ka.y + qa.z * ka.z + qa.w * ka.w
                          + qd.x * kd.x + qd.y * kd.y + qd.z * kd.z + qd.w * kd.w;
                ed[ki] = __expf(dot);
            }
        }
        __syncthreads();

        if (tid < 200) {
            int h = tid / 25, r = tid % 25;
            int qi = sMap[r];
            const float* eb = g_ebias + h * 625 + r * 25;
            const float* ed = sED + h * 169 + qi * 13;
            float den = 0.f, cb = 0.f;
#pragma unroll
            for (int col = 0; col < 25; col++) {
                int ki = sMap[col];
                float e = __ldg(eb + col);
                den += e * ed[ki];
                if (ki == 12) cb += e;
            }
            sInv[tid] = 1.f / den;
            sCB[tid] = cb;
        }
        __syncthreads();

        if (tid < 104) {
            int h = tid / 13, c = tid % 13;
            const float* ed = sED + h * 169;
            const float* iv = sInv + h * 25;
            float w = 0.f;
            if (c == 12) {
                const float* cb = sCB + h * 25;
#pragma unroll
                for (int r = 0; r < 25; r++) w += iv[r] * ed[sMap[r] * 13 + 12] * cb[r];
            } else if (sMap[c] == c) {
                const float* eb = g_ebias + h * 625 + c;
#pragma unroll
                for (int r = 0; r < 25; r++) w += iv[r] * ed[sMap[r] * 13 + c] * __ldg(eb + r * 25);
            }
            sW[tid] = w;
        }
        __syncthreads();

        if (tid < 64) {
            int h = tid >> 3;
            const float* w = sW + h * 13;
            float acc = 0.f;
#pragma unroll
            for (int c = 0; c < 13; c++) acc += w[c] * sQ[c * SLOT_STRIDE + 128 + tid];
#pragma unroll
            for (int s = 0; s < 12; s++) acc += sQ[s * SLOT_STRIDE + 192 + tid];
            g_osum[(size_t)p * 64 + tid] = acc;
        }
    }
}

// ---- k3: fused LN2+MLP+proj, 64 pixels/block, pixel-pair packed FFMA2.
//      lane owns pixels (lane, lane+32); warp owns an output slice. ----
__global__ __launch_bounds__(256) void k3(const float* __restrict__ n2w, const float* __restrict__ n2b,
                                          const float* __restrict__ b1, const float* __restrict__ b2,
                                          const float* __restrict__ pb, float* __restrict__ out) {
    extern __shared__ float smem[];
    float* sWt = smem;                  // 8192 floats: weight staging chunk (32KB)
    float* sA  = smem + 8192;           // 64 x 65: LN values, later y
    float* sH  = sA + 64 * 65;          // 64 x 257: gelu activations
    int tid = threadIdx.x, lane = tid & 31, w = tid >> 5;
    int p0 = blockIdx.x * 64;

    // LN: warp w handles pixels w*8 .. w*8+7
#pragma unroll
    for (int t = 0; t < 8; t++) {
        int pix = w * 8 + t;
        const float* os = g_osum + (size_t)(p0 + pix) * 64;
        float x0 = os[lane], x1 = os[lane + 32];
        float m  = wsum(x0 + x1) * (1.f / 64.f);
        float vv = wsum(x0 * x0 + x1 * x1) * (1.f / 64.f) - m * m;
        float rs = rsqrtf(vv + 1e-5f);
        sA[pix * 65 + lane]      = (x0 - m) * rs * n2w[lane] + n2b[lane];
        sA[pix * 65 + lane + 32] = (x1 - m) * rs * n2w[lane + 32] + n2b[lane + 32];
    }

    // fc1: two output-half passes; warp owns outputs [oh*128 + 16w, +16)
#pragma unroll
    for (int oh = 0; oh < 2; oh++) {
        __syncthreads();
        {
            const float4* src = (const float4*)g_w1T;
            float4* dst = (float4*)sWt;
            for (int i = tid; i < 2048; i += 256) {
                int row = i >> 5, c4 = i & 31;
                dst[i] = src[row * 64 + oh * 32 + c4];
            }
        }
        __syncthreads();
        unsigned long long acc2[16];
#pragma unroll
        for (int j = 0; j < 16; j++) acc2[j] = 0ull;
        const float* a0 = sA + lane * 65;
        const float* a1 = sA + (lane + 32) * 65;
        const float* wBase = sWt + w * 16;
        for (int k = 0; k < 64; k++) {
            unsigned long long aa = pack2(a0[k], a1[k]);
            const float4* wr = (const float4*)(wBase + k * 128);
#pragma unroll
            for (int j4 = 0; j4 < 4; j4++) {
                float4 wv = wr[j4];
                fma2(acc2[4 * j4 + 0], pack2(wv.x, wv.x), aa);
                fma2(acc2[4 * j4 + 1], pack2(wv.y, wv.y), aa);
                fma2(acc2[4 * j4 + 2], pack2(wv.z, wv.z), aa);
                fma2(acc2[4 * j4 + 3], pack2(wv.w, wv.w), aa);
            }
        }
        // bias + gelu -> sH
        float* h0 = sH + lane * 257 + oh * 128 + w * 16;
        float* h1 = sH + (lane + 32) * 257 + oh * 128 + w * 16;
#pragma unroll
        for (int j = 0; j < 16; j++) {
            float bv = __ldg(b1 + oh * 128 + w * 16 + j);
            float2 p = unpack2(acc2[j]);
            float v0 = p.x + bv, v1 = p.y + bv;
            h0[j] = 0.5f * v0 * (1.f + erff(v0 * 0.70710678118f));
            h1[j] = 0.5f * v1 * (1.f + erff(v1 * 0.70710678118f));
        }
    }

    // fc2: warp owns outputs [8w, 8w+8); w2T staged in 2 k-halves
    unsigned long long a2p[8];
#pragma unroll
    for (int j = 0; j < 8; j++) a2p[j] = 0ull;
#pragma unroll
    for (int kh = 0; kh < 2; kh++) {
        __syncthreads();
        {
            const float4* src = (const float4*)(g_w2T + kh * 128 * 64);
            float4* dst = (float4*)sWt;
            for (int i = tid; i < 2048; i += 256) dst[i] = src[i];
        }
        __syncthreads();
        const float* h0 = sH + lane * 257 + kh * 128;
        const float* h1 = sH + (lane + 32) * 257 + kh * 128;
        const float* wBase = sWt + w * 8;
        for (int k = 0; k < 128; k++) {
            unsigned long long hh = pack2(h0[k], h1[k]);
            const float4* wr = (const float4*)(wBase + k * 64);
            float4 w0 = wr[0], w1v = wr[1];
            fma2(a2p[0], pack2(w0.x, w0.x), hh);
            fma2(a2p[1], pack2(w0.y, w0.y), hh);
            fma2(a2p[2], pack2(w0.z, w0.z), hh);
            fma2(a2p[3], pack2(w0.w, w0.w), hh);
            fma2(a2p[4], pack2(w1v.x, w1v.x), hh);
            fma2(a2p[5], pack2(w1v.y, w1v.y), hh);
            fma2(a2p[6], pack2(w1v.z, w1v.z), hh);
            fma2(a2p[7], pack2(w1v.w, w1v.w), hh);
        }
    }
    // + b2 + residual -> y in sA
    __syncthreads();
    {
        const float* os0 = g_osum + (size_t)(p0 + lane) * 64 + w * 8;
        const float* os1 = g_osum + (size_t)(p0 + lane + 32) * 64 + w * 8;
        float* y0 = sA + lane * 65 + w * 8;
        float* y1 = sA + (lane + 32) * 65 + w * 8;
#pragma unroll
        for (int j = 0; j < 8; j++) {
            float bv = __ldg(b2 + w * 8 + j);
            float2 p = unpack2(a2p[j]);
            y0[j] = p.x + bv + __ldg(os0 + j);
            y1[j] = p.y + bv + __ldg(os1 + j);
        }
    }
    __syncthreads();

    // stage projT (16KB, single chunk)
    {
        const float4* src = (const float4*)g_projT;
        float4* dst = (float4*)sWt;
        for (int i = tid; i < 1024; i += 256) dst[i] = src[i];
    }
    __syncthreads();

    // proj: warp owns outputs [8w, 8w+8)
    unsigned long long a3p[8];
#pragma unroll
    for (int j = 0; j < 8; j++) a3p[j] = 0ull;
    {
        const float* y0 = sA + lane * 65;
        const float* y1 = sA + (lane + 32) * 65;
        const float* wBase = sWt + w * 8;
        for (int k = 0; k < 64; k++) {
            unsigned long long yy = pack2(y0[k], y1[k]);
            const float4* wr = (const float4*)(wBase + k * 64);
            float4 w0 = wr[0], w1v = wr[1];
            fma2(a3p[0], pack2(w0.x, w0.x), yy);
            fma2(a3p[1], pack2(w0.y, w0.y), yy);
            fma2(a3p[2], pack2(w0.z, w0.z), yy);
            fma2(a3p[3], pack2(w0.w, w0.w), yy);
            fma2(a3p[4], pack2(w1v.x, w1v.x), yy);
            fma2(a3p[5], pack2(w1v.y, w1v.y), yy);
            fma2(a3p[6], pack2(w1v.z, w1v.z), yy);
            fma2(a3p[7], pack2(w1v.w, w1v.w), yy);
        }
    }
    {
        int wid0 = p0 + lane, wid1 = p0 + lane + 32;
        float* ob0 = out + (size_t)(wid0 >> 12) * 262144 + (wid0 & 4095);
        float* ob1 = out + (size_t)(wid1 >> 12) * 262144 + (wid1 & 4095);
#pragma unroll
        for (int j = 0; j < 8; j++) {
            float pv = __ldg(pb + w * 8 + j);
            float2 p = unpack2(a3p[j]);
            ob0[(size_t)(w * 8 + j) * 4096] = p.x + pv;
            ob1[(size_t)(w * 8 + j) * 4096] = p.y + pv;
        }
    }
}

extern "C" void kernel_launch(void* const* d_in, const int* in_sizes, int n_in,
                              void* d_out, int out_size) {
    const float* x    = (const float*)d_in[0];
    const float* n1w  = (const float*)d_in[1];
    const float* n1b  = (const float*)d_in[2];
    const float* qw   = (const float*)d_in[3];
    const float* qb   = (const float*)d_in[4];
    const float* rpb  = (const float*)d_in[5];
    const float* n2w  = (const float*)d_in[6];
    const float* n2b  = (const float*)d_in[7];
    const float* w1   = (const float*)d_in[8];
    const float* b1   = (const float*)d_in[9];
    const float* w2   = (const float*)d_in[10];
    const float* b2   = (const float*)d_in[11];
    const float* pw   = (const float*)d_in[12];
    const float* pb   = (const float*)d_in[13];
    float* out = (float*)d_out;

    cudaFuncSetAttribute(k3, cudaFuncAttributeMaxDynamicSharedMemorySize, K3_SMEM);

    prep<<<64, 256>>>(qw, w1, w2, pw, rpb, n1b, qb);
    k1<<<256, 256>>>(x, n1w, n1b, qb);
    k2<<<NBI + NBB, 256>>>();
    k3<<<256, 256, K3_SMEM>>>(n2w, n2b, b1, b2, pb, out);
}

// round 16
// speedup vs baseline: 3.2956x; 1.0543x over previous
#include <cuda_runtime.h>
#include <math.h>

#define NPIX 16384
#define QSCALE 0.35355339059327373f
#define QKS 132    // q|k slot stride in k2 smem
#define NBI 3600   // interior blocks
#define NBB 1984   // boundary blocks
#define K3_SMEM ((8192 + 64 * 65 + 64 * 257) * 4)

__device__ __align__(16) float g_y[NPIX * 256];   // per pixel: q*s | k | v | raw x
__device__ __align__(16) float g_osum[NPIX * 64];
__device__ __align__(16) float g_const[192];      // qkv row for masked/OOB slots
__device__ __align__(16) float g_qwT[64 * 192];   // [c][o]
__device__ __align__(16) float g_w1T[64 * 256];   // [c][u]
__device__ __align__(16) float g_w2T[256 * 64];   // [u][o]
__device__ __align__(16) float g_projT[64 * 64];  // [c][o]
__device__ __align__(16) float g_ebias[8 * 25 * 25];   // exp(bias) full (boundary)
__device__ __align__(16) float g_eb12[8 * 25 * 12];    // exp(bias)[h][r][c<12] (interior)
__device__ float g_cb[8 * 25];                    // sum_{c>=12} exp(bias)

__device__ __forceinline__ float wsum(float v) {
#pragma unroll
    for (int o = 16; o; o >>= 1) v += __shfl_xor_sync(0xffffffffu, v, o);
    return v;
}

// ---- packed fp32x2 helpers (FFMA2 path, sm_103a) ----
__device__ __forceinline__ unsigned long long pack2(float lo, float hi) {
    unsigned long long r;
    asm("mov.b64 %0, {%1, %2};" : "=l"(r) : "f"(lo), "f"(hi));
    return r;
}
__device__ __forceinline__ void fma2(unsigned long long& d, unsigned long long a, unsigned long long b) {
    asm("fma.rn.f32x2 %0, %1, %2, %0;" : "+l"(d) : "l"(a), "l"(b));
}
__device__ __forceinline__ float2 unpack2(unsigned long long v) {
    float lo, hi;
    asm("mov.b64 {%0, %1}, %2;" : "=f"(lo), "=f"(hi) : "l"(v));
    return make_float2(lo, hi);
}

// ---- prep: transposed weights + exp(bias) tables + const qkv row ----
__global__ void prep(const float* __restrict__ qw, const float* __restrict__ w1,
                     const float* __restrict__ w2, const float* __restrict__ pw,
                     const float* __restrict__ rpb,
                     const float* __restrict__ n1b, const float* __restrict__ qb) {
    for (int i = blockIdx.x * blockDim.x + threadIdx.x; i < 56944; i += gridDim.x * blockDim.x) {
        if (i < 12288) { int c = i / 192, o = i % 192; g_qwT[i] = qw[o * 64 + c]; }
        else if (i < 28672) { int j = i - 12288; int c = j / 256, u = j % 256; g_w1T[j] = w1[u * 64 + c]; }
        else if (i < 45056) { int j = i - 28672; int u = j / 64, c = j % 64; g_w2T[j] = w2[c * 256 + u]; }
        else if (i < 49152) { int j = i - 45056; int c = j / 64, o = j % 64; g_projT[j] = pw[o * 64 + c]; }
        else if (i < 54152) {
            int j = i - 49152; int h = j / 625, r = j % 625; int qi = r / 25, kj = r % 25;
            int idx = (qi / 5 - kj / 5 + 4) * 9 + (qi % 5 - kj % 5 + 4);
            g_ebias[j] = __expf(rpb[idx * 8 + h]);
        } else if (i < 56552) {
            int j = i - 54152; int h = j / 300, rem = j % 300; int r = rem / 12, c = rem % 12;
            int idx = (r / 5 - c / 5 + 4) * 9 + (r % 5 - c % 5 + 4);
            g_eb12[j] = __expf(rpb[idx * 8 + h]);
        } else if (i < 56752) {
            int j = i - 56552; int h = j / 25, r = j % 25;
            float s = 0.f;
            for (int c = 12; c < 25; c++) {
                int idx = (r / 5 - c / 5 + 4) * 9 + (r % 5 - c % 5 + 4);
                s += __expf(rpb[idx * 8 + h]);
            }
            g_cb[j] = s;
        } else {
            int o = i - 56752;   // const qkv row: LN(0) = n1b
            float a = qb[o];
            for (int c = 0; c < 64; c++) a += n1b[c] * qw[o * 64 + c];
            if (o < 64) a *= QSCALE;
            g_const[o] = a;
        }
    }
}

// ---- k1: LN1 + QKV, smem-staged weights + pixel-pair FFMA2. ----
__global__ __launch_bounds__(256) void k1(const float* __restrict__ x,
                                          const float* __restrict__ n1w,
                                          const float* __restrict__ n1b,
                                          const float* __restrict__ qb) {
    __shared__ float sWt[64 * 96];
    __shared__ float sA[64 * 65];
    int tid = threadIdx.x, lane = tid & 31, w = tid >> 5;
    int p0 = blockIdx.x * 64;

    float nw0 = n1w[lane], nw1 = n1w[lane + 32];
    float nb0 = n1b[lane], nb1 = n1b[lane + 32];
#pragma unroll
    for (int t = 0; t < 8; t++) {
        int pix = w * 8 + t;
        int wid = p0 + pix;
        int b = wid >> 12, hw = wid & 4095;
        const float* xb = x + (size_t)b * 262144 + hw;
        float x0 = __ldg(xb + (size_t)lane * 4096);
        float x1 = __ldg(xb + (size_t)(lane + 32) * 4096);
        float m  = wsum(x0 + x1) * (1.f / 64.f);
        float vv = wsum(x0 * x0 + x1 * x1) * (1.f / 64.f) - m * m;
        float rs = rsqrtf(vv + 1e-5f);
        sA[pix * 65 + lane]      = (x0 - m) * rs * nw0 + nb0;
        sA[pix * 65 + lane + 32] = (x1 - m) * rs * nw1 + nb1;
        float* yp = g_y + (size_t)wid * 256;
        yp[192 + lane] = x0; yp[224 + lane] = x1;
    }

#pragma unroll
    for (int oh = 0; oh < 2; oh++) {
        __syncthreads();
        {
            const float4* src = (const float4*)g_qwT;
            float4* dst = (float4*)sWt;
            for (int i = tid; i < 1536; i += 256) {
                int row = i / 24, c4 = i % 24;
                dst[i] = src[row * 48 + oh * 24 + c4];
            }
        }
        __syncthreads();
        unsigned long long accA[6], accB[6];
#pragma unroll
        for (int j = 0; j < 6; j++) { accA[j] = 0ull; accB[j] = 0ull; }
        const float* a0 = sA + lane * 65;
        const float* a1 = sA + (lane + 32) * 65;
        const float* wBase = sWt + w * 12;
        for (int k = 0; k < 64; k++) {
            unsigned long long aa0 = pack2(a0[k], a0[k]);
            unsigned long long aa1 = pack2(a1[k], a1[k]);
            const ulonglong2* wr = (const ulonglong2*)(wBase + k * 96);
            ulonglong2 w01 = wr[0];
            fma2(accA[0], w01.x, aa0); fma2(accB[0], w01.x, aa1);
            fma2(accA[1], w01.y, aa0); fma2(accB[1], w01.y, aa1);
            ulonglong2 w23 = wr[1];
            fma2(accA[2], w23.x, aa0); fma2(accB[2], w23.x, aa1);
            fma2(accA[3], w23.y, aa0); fma2(accB[3], w23.y, aa1);
            ulonglong2 w45 = wr[2];
            fma2(accA[4], w45.x, aa0); fma2(accB[4], w45.x, aa1);
            fma2(accA[5], w45.y, aa0); fma2(accB[5], w45.y, aa1);
        }
        float ov0[12], ov1[12];
#pragma unroll
        for (int j = 0; j < 6; j++) {
            int o = oh * 96 + w * 12 + 2 * j;
            float b0 = __ldg(qb + o), b1v = __ldg(qb + o + 1);
            float s0 = (o < 64) ? QSCALE : 1.f;
            float s1 = (o + 1 < 64) ? QSCALE : 1.f;
            float2 pA = unpack2(accA[j]);
            float2 pB = unpack2(accB[j]);
            ov0[2 * j]     = (pA.x + b0) * s0;
            ov0[2 * j + 1] = (pA.y + b1v) * s1;
            ov1[2 * j]     = (pB.x + b0) * s0;
            ov1[2 * j + 1] = (pB.y + b1v) * s1;
        }
        float* y0 = g_y + (size_t)(p0 + lane) * 256 + oh * 96 + w * 12;
        float* y1 = g_y + (size_t)(p0 + lane + 32) * 256 + oh * 96 + w * 12;
#pragma unroll
        for (int j4 = 0; j4 < 3; j4++) {
            *(float4*)(y0 + 4 * j4) = make_float4(ov0[4 * j4], ov0[4 * j4 + 1], ov0[4 * j4 + 2], ov0[4 * j4 + 3]);
            *(float4*)(y1 + 4 * j4) = make_float4(ov1[4 * j4], ov1[4 * j4 + 1], ov1[4 * j4 + 2], ov1[4 * j4 + 3]);
        }
    }
}

// ---- k2: merged window attention; q|k staged in smem, v|x read direct from gmem ----
__global__ __launch_bounds__(256, 4) void k2() {
    __shared__ float sQ[22 * QKS];       // per slot: q [0,64) | k [64,128)
    __shared__ float sED[4 * 1352];      // boundary overlays CB scratch at +1360
    __shared__ float sInv[4 * 200];
    __shared__ float sW[4 * 104];
    __shared__ int   sSlot[4][13];
    __shared__ int   sOffI[4][12];       // interior: per-pixel slot gmem offsets
    __shared__ int   sMap[25];
    __shared__ int   sOff[13];

    int tid = threadIdx.x;

    if (blockIdx.x < NBI) {
        // ================= interior path =================
        int idx = blockIdx.x;
        int b = idx / 900, rem = idx - b * 900;
        int h0 = 2 + rem / 15, w0 = 2 + (rem % 15) * 4;
        int base = (b << 12) + (h0 << 6) + w0;

        if (tid < 52) {
            int j = tid / 13, ls = tid - j * 13;
            int g = (ls < 5) ? ls + j : (ls < 10) ? 8 + (ls - 5) + j : (ls < 12) ? 16 + (ls - 10) + j : 21;
            sSlot[j][ls] = g;
        }
        if (tid >= 64 && tid < 112) {
            int t = tid - 64; int j = t / 12, s = t - j * 12;
            sOffI[j][s] = (base + j + (s / 5 - 2) * 64 + (s % 5 - 2)) * 256;
        }
        // stage q|k only: 22 slots x 32 float4
        for (int i = tid; i < 22 * 32; i += 256) {
            int slot = i >> 5, jj = i & 31;
            float4 v;
            if (slot < 21) {
                int row, col;
                if (slot < 16) { row = slot >> 3; col = slot & 7; }
                else { row = 2; col = slot - 16; }
                int pp = base + (row - 2) * 64 + (col - 2);
                v = *(const float4*)(g_y + (size_t)pp * 256 + jj * 4);
            } else {
                v = *(const float4*)(g_const + jj * 4);
            }
            *(float4*)(sQ + slot * QKS + jj * 4) = v;
        }
        __syncthreads();

        // dots: broadcast-k scheme, half-warp group per (pix,h) pair
        {
            int w = tid >> 5, lane = tid & 31;
            int grp = lane >> 4, qi = lane & 15;
            bool act = qi < 13;
#pragma unroll
            for (int it = 0; it < 2; it++) {
                int pairidx = w * 4 + it * 2 + grp;
                int pix = pairidx >> 3, h = pairidx & 7;
                const int* sm = sSlot[pix];
                float4 qa = make_float4(0.f, 0.f, 0.f, 0.f), qd = qa;
                if (act) {
                    int gq = sm[qi];
                    qa = *(const float4*)(sQ + gq * QKS + h * 8);
                    qd = *(const float4*)(sQ + gq * QKS + h * 8 + 4);
                }
                float* ed = sED + pix * 1352 + h * 169 + qi * 13;
#pragma unroll
                for (int ki = 0; ki < 13; ki++) {
                    const float* kb = sQ + sm[ki] * QKS + 64 + h * 8;
                    float4 ka = *(const float4*)kb;
                    float4 kd = *(const float4*)(kb + 4);
                    float dot = qa.x * ka.x + qa.y * ka.y + qa.z * ka.z + qa.w * ka.w
                              + qd.x * kd.x + qd.y * kd.y + qd.z * kd.z + qd.w * kd.w;
                    if (act) ed[ki] = __expf(dot);
                }
            }
        }
        __syncthreads();

        // pass1
        for (int i = tid; i < 800; i += 256) {
            int pix = i / 200, t = i - pix * 200;
            int h = t / 25, r = t - h * 25;
            int qi = (r < 12) ? r : 12;
            const float* ed = sED + pix * 1352 + h * 169 + qi * 13;
            const float* eb = g_eb12 + h * 300 + r * 12;
            float4 e0 = __ldg((const float4*)eb);
            float4 e1 = __ldg((const float4*)(eb + 4));
            float4 e2 = __ldg((const float4*)(eb + 8));
            float den = __ldg(g_cb + h * 25 + r) * ed[12];
            den += e0.x * ed[0] + e0.y * ed[1] + e0.z * ed[2] + e0.w * ed[3];
            den += e1.x * ed[4] + e1.y * ed[5] + e1.z * ed[6] + e1.w * ed[7];
            den += e2.x * ed[8] + e2.y * ed[9] + e2.z * ed[10] + e2.w * ed[11];
            sInv[pix * 200 + t] = 1.f / den;
        }
        __syncthreads();

        // pass2
        for (int i = tid; i < 416; i += 256) {
            int pix = i / 104, t = i - pix * 104;
            int h = t / 13, c = t - h * 13;
            const float* ed = sED + pix * 1352 + h * 169;
            const float* iv = sInv + pix * 200 + h * 25;
            float w = 0.f, tt = 0.f;
            if (c < 12) {
                const float* eb = g_eb12 + h * 300 + c;
#pragma unroll
                for (int r = 0; r < 12; r++) w += iv[r] * ed[r * 13 + c] * __ldg(eb + r * 12);
#pragma unroll
                for (int r = 12; r < 25; r++) tt += iv[r] * __ldg(eb + r * 12);
                w += ed[156 + c] * tt;
            } else {
                const float* cb = g_cb + h * 25;
#pragma unroll
                for (int r = 0; r < 12; r++) w += iv[r] * ed[r * 13 + 12] * __ldg(cb + r);
#pragma unroll
                for (int r = 12; r < 25; r++) tt += iv[r] * __ldg(cb + r);
                w += ed[168] * tt;
            }
            sW[pix * 104 + t] = w;
        }
        __syncthreads();

        // pass3: v & x direct from gmem (each consumed once — no staging)
        {
            int pix = tid >> 6, ch = tid & 63, h = ch >> 3;
            const float* wv = sW + pix * 104 + h * 13;
            const int* off = sOffI[pix];
            float acc = wv[12] * g_const[128 + ch];
#pragma unroll
            for (int s = 0; s < 12; s++) {
                const float* yb = g_y + off[s];
                acc += wv[s] * __ldg(yb + 128 + ch) + __ldg(yb + 192 + ch);
            }
            g_osum[(size_t)(base + pix) * 64 + ch] = acc;
        }
    } else {
        // ================= boundary path =================
        float* sCB = sED + 1360;   // overlay (ED uses [0,1352))
        int t = blockIdx.x - NBI;
        int b = t / 496, u = t - b * 496;
        int h0, w0;
        if (u < 128)      { h0 = u >> 6; w0 = u & 63; }
        else if (u < 256) { int v = u - 128; h0 = 62 + (v >> 6); w0 = v & 63; }
        else              { int v = u - 256; h0 = 2 + v / 4; int c = v & 3; w0 = (c < 2) ? c : (60 + c); }
        int p = (b << 12) + (h0 << 6) + w0;

        if (tid < 25) {
            int ri = tid / 5 - 2, ci = tid % 5 - 2;
            int nh = h0 + ri, nw = w0 + ci;
            int ok = (tid < 12) && nh >= 0 && nh < 64 && nw >= 0 && nw < 64;
            sMap[tid] = ok ? tid : 12;
            if (tid < 13) sOff[tid] = -1;
            if (ok) sOff[tid] = ((b << 12) + (nh << 6) + nw) * 256;
        }
        __syncthreads();

        // stage q|k only: 13 slots x 32 float4
        for (int i = tid; i < 13 * 32; i += 256) {
            int slot = i >> 5, jj = i & 31;
            int off = sOff[slot];
            float4 v;
            if (off >= 0) v = *(const float4*)(g_y + off + jj * 4);
            else          v = *(const float4*)(g_const + jj * 4);
            *(float4*)(sQ + slot * QKS + jj * 4) = v;
        }
        __syncthreads();

        if (tid < 104) {
            int h = tid / 13, qi = tid % 13;
            float4 qa = *(const float4*)(sQ + qi * QKS + h * 8);
            float4 qd = *(const float4*)(sQ + qi * QKS + h * 8 + 4);
            float* ed = sED + h * 169 + qi * 13;
#pragma unroll
            for (int ki = 0; ki < 13; ki++) {
                const float* kb = sQ + ki * QKS + 64 + h * 8;
                float4 ka = *(const float4*)kb;
                float4 kd = *(const float4*)(kb + 4);
                float dot = qa.x * ka.x + qa.y * ka.y + qa.z * ka.z + qa.w * ka.w
                          + qd.x * kd.x + qd.y * kd.y + qd.z * kd.z + qd.w * kd.w;
                ed[ki] = __expf(dot);
            }
        }
        __syncthreads();

        if (tid < 200) {
            int h = tid / 25, r = tid % 25;
            int qi = sMap[r];
            const float* eb = g_ebias + h * 625 + r * 25;
            const float* ed = sED + h * 169 + qi * 13;
            float den = 0.f, cb = 0.f;
#pragma unroll
            for (int col = 0; col < 25; col++) {
                int ki = sMap[col];
                float e = __ldg(eb + col);
                den += e * ed[ki];
                if (ki == 12) cb += e;
            }
            sInv[tid] = 1.f / den;
            sCB[tid] = cb;
        }
        __syncthreads();

        if (tid < 104) {
            int h = tid / 13, c = tid % 13;
            const float* ed = sED + h * 169;
            const float* iv = sInv + h * 25;
            float w = 0.f;
            if (c == 12) {
                const float* cb = sCB + h * 25;
#pragma unroll
                for (int r = 0; r < 25; r++) w += iv[r] * ed[sMap[r] * 13 + 12] * cb[r];
            } else if (sMap[c] == c) {
                const float* eb = g_ebias + h * 625 + c;
#pragma unroll
                for (int r = 0; r < 25; r++) w += iv[r] * ed[sMap[r] * 13 + c] * __ldg(eb + r * 25);
            }
            sW[tid] = w;
        }
        __syncthreads();

        if (tid < 64) {
            int ch = tid, h = ch >> 3;
            const float* w = sW + h * 13;
            float acc = w[12] * g_const[128 + ch];
#pragma unroll
            for (int s = 0; s < 12; s++) {
                int o = sOff[s];
                if (o >= 0) {
                    const float* yb = g_y + o;
                    acc += w[s] * __ldg(yb + 128 + ch) + __ldg(yb + 192 + ch);
                }
            }
            g_osum[(size_t)p * 64 + ch] = acc;
        }
    }
}

// ---- k3: fused LN2+MLP+proj, 64 pixels/block, pixel-pair packed FFMA2. ----
__global__ __launch_bounds__(256) void k3(const float* __restrict__ n2w, const float* __restrict__ n2b,
                                          const float* __restrict__ b1, const float* __restrict__ b2,
                                          const float* __restrict__ pb, float* __restrict__ out) {
    extern __shared__ float smem[];
    float* sWt = smem;
    float* sA  = smem + 8192;
    float* sH  = sA + 64 * 65;
    int tid = threadIdx.x, lane = tid & 31, w = tid >> 5;
    int p0 = blockIdx.x * 64;

#pragma unroll
    for (int t = 0; t < 8; t++) {
        int pix = w * 8 + t;
        const float* os = g_osum + (size_t)(p0 + pix) * 64;
        float x0 = os[lane], x1 = os[lane + 32];
        float m  = wsum(x0 + x1) * (1.f / 64.f);
        float vv = wsum(x0 * x0 + x1 * x1) * (1.f / 64.f) - m * m;
        float rs = rsqrtf(vv + 1e-5f);
        sA[pix * 65 + lane]      = (x0 - m) * rs * n2w[lane] + n2b[lane];
        sA[pix * 65 + lane + 32] = (x1 - m) * rs * n2w[lane + 32] + n2b[lane + 32];
    }

#pragma unroll
    for (int oh = 0; oh < 2; oh++) {
        __syncthreads();
        {
            const float4* src = (const float4*)g_w1T;
            float4* dst = (float4*)sWt;
            for (int i = tid; i < 2048; i += 256) {
                int row = i >> 5, c4 = i & 31;
                dst[i] = src[row * 64 + oh * 32 + c4];
            }
        }
        __syncthreads();
        unsigned long long acc2[16];
#pragma unroll
        for (int j = 0; j < 16; j++) acc2[j] = 0ull;
        const float* a0 = sA + lane * 65;
        const float* a1 = sA + (lane + 32) * 65;
        const float* wBase = sWt + w * 16;
        for (int k = 0; k < 64; k++) {
            unsigned long long aa = pack2(a0[k], a1[k]);
            const float4* wr = (const float4*)(wBase + k * 128);
#pragma unroll
            for (int j4 = 0; j4 < 4; j4++) {
                float4 wv = wr[j4];
                fma2(acc2[4 * j4 + 0], pack2(wv.x, wv.x), aa);
                fma2(acc2[4 * j4 + 1], pack2(wv.y, wv.y), aa);
                fma2(acc2[4 * j4 + 2], pack2(wv.z, wv.z), aa);
                fma2(acc2[4 * j4 + 3], pack2(wv.w, wv.w), aa);
            }
        }
        float* h0 = sH + lane * 257 + oh * 128 + w * 16;
        float* h1 = sH + (lane + 32) * 257 + oh * 128 + w * 16;
#pragma unroll
        for (int j = 0; j < 16; j++) {
            float bv = __ldg(b1 + oh * 128 + w * 16 + j);
            float2 p = unpack2(acc2[j]);
            float v0 = p.x + bv, v1 = p.y + bv;
            h0[j] = 0.5f * v0 * (1.f + erff(v0 * 0.70710678118f));
            h1[j] = 0.5f * v1 * (1.f + erff(v1 * 0.70710678118f));
        }
    }

    unsigned long long a2p[8];
#pragma unroll
    for (int j = 0; j < 8; j++) a2p[j] = 0ull;
#pragma unroll
    for (int kh = 0; kh < 2; kh++) {
        __syncthreads();
        {
            const float4* src = (const float4*)(g_w2T + kh * 128 * 64);
            float4* dst = (float4*)sWt;
            for (int i = tid; i < 2048; i += 256) dst[i] = src[i];
        }
        __syncthreads();
        const float* h0 = sH + lane * 257 + kh * 128;
        const float* h1 = sH + (lane + 32) * 257 + kh * 128;
        const float* wBase = sWt + w * 8;
        for (int k = 0; k < 128; k++) {
            unsigned long long hh = pack2(h0[k], h1[k]);
            const float4* wr = (const float4*)(wBase + k * 64);
            float4 w0 = wr[0], w1v = wr[1];
            fma2(a2p[0], pack2(w0.x, w0.x), hh);
            fma2(a2p[1], pack2(w0.y, w0.y), hh);
            fma2(a2p[2], pack2(w0.z, w0.z), hh);
            fma2(a2p[3], pack2(w0.w, w0.w), hh);
            fma2(a2p[4], pack2(w1v.x, w1v.x), hh);
            fma2(a2p[5], pack2(w1v.y, w1v.y), hh);
            fma2(a2p[6], pack2(w1v.z, w1v.z), hh);
            fma2(a2p[7], pack2(w1v.w, w1v.w), hh);
        }
    }
    __syncthreads();
    {
        const float* os0 = g_osum + (size_t)(p0 + lane) * 64 + w * 8;
        const float* os1 = g_osum + (size_t)(p0 + lane + 32) * 64 + w * 8;
        float* y0 = sA + lane * 65 + w * 8;
        float* y1 = sA + (lane + 32) * 65 + w * 8;
#pragma unroll
        for (int j = 0; j < 8; j++) {
            float bv = __ldg(b2 + w * 8 + j);
            float2 p = unpack2(a2p[j]);
            y0[j] = p.x + bv + __ldg(os0 + j);
            y1[j] = p.y + bv + __ldg(os1 + j);
        }
    }
    __syncthreads();

    {
        const float4* src = (const float4*)g_projT;
        float4* dst = (float4*)sWt;
        for (int i = tid; i < 1024; i += 256) dst[i] = src[i];
    }
    __syncthreads();

    unsigned long long a3p[8];
#pragma unroll
    for (int j = 0; j < 8; j++) a3p[j] = 0ull;
    {
        const float* y0 = sA + lane * 65;
        const float* y1 = sA + (lane + 32) * 65;
        const float* wBase = sWt + w * 8;
        for (int k = 0; k < 64; k++) {
            unsigned long long yy = pack2(y0[k], y1[k]);
            const float4* wr = (const float4*)(wBase + k * 64);
            float4 w0 = wr[0], w1v = wr[1];
            fma2(a3p[0], pack2(w0.x, w0.x), yy);
            fma2(a3p[1], pack2(w0.y, w0.y), yy);
            fma2(a3p[2], pack2(w0.z, w0.z), yy);
            fma2(a3p[3], pack2(w0.w, w0.w), yy);
            fma2(a3p[4], pack2(w1v.x, w1v.x), yy);
            fma2(a3p[5], pack2(w1v.y, w1v.y), yy);
            fma2(a3p[6], pack2(w1v.z, w1v.z), yy);
            fma2(a3p[7], pack2(w1v.w, w1v.w), yy);
        }
    }
    {
        int wid0 = p0 + lane, wid1 = p0 + lane + 32;
        float* ob0 = out + (size_t)(wid0 >> 12) * 262144 + (wid0 & 4095);
        float* ob1 = out + (size_t)(wid1 >> 12) * 262144 + (wid1 & 4095);
#pragma unroll
        for (int j = 0; j < 8; j++) {
            float pv = __ldg(pb + w * 8 + j);
            float2 p = unpack2(a3p[j]);
            ob0[(size_t)(w * 8 + j) * 4096] = p.x + pv;
            ob1[(size_t)(w * 8 + j) * 4096] = p.y + pv;
        }
    }
}

extern "C" void kernel_launch(void* const* d_in, const int* in_sizes, int n_in,
                              void* d_out, int out_size) {
    const float* x    = (const float*)d_in[0];
    const float* n1w  = (const float*)d_in[1];
    const float* n1b  = (const float*)d_in[2];
    const float* qw   = (const float*)d_in[3];
    const float* qb   = (const float*)d_in[4];
    const float* rpb  = (const float*)d_in[5];
    const float* n2w  = (const float*)d_in[6];
    const float* n2b  = (const float*)d_in[7];
    const float* w1   = (const float*)d_in[8];
    const float* b1   = (const float*)d_in[9];
    const float* w2   = (const float*)d_in[10];
    const float* b2   = (const float*)d_in[11];
    const float* pw   = (const float*)d_in[12];
    const float* pb   = (const float*)d_in[13];
    float* out = (float*)d_out;

    cudaFuncSetAttribute(k3, cudaFuncAttributeMaxDynamicSharedMemorySize, K3_SMEM);

    prep<<<64, 256>>>(qw, w1, w2, pw, rpb, n1b, qb);
    k1<<<256, 256>>>(x, n1w, n1b, qb);
    k2<<<NBI + NBB, 256>>>();
    k3<<<256, 256, K3_SMEM>>>(n2w, n2b, b1, b2, pb, out);
}